// round 3
// baseline (speedup 1.0000x reference)
#include <cuda_runtime.h>
#include <cuda_bf16.h>
#include <math.h>

// Problem constants (fixed by reference)
#define NNODES 20000
#define NEDGES 320000
#define ETOT   340000   // NEDGES + NNODES self loops
#define INDIM  512
#define NHEAD  4
#define CDIM   64
#define HCDIM  256
#define EPS_BN 1e-5f

// ---------------- scratch (device globals; no allocation allowed) ----------
__device__ float g_xl[NNODES * HCDIM];
__device__ float g_xr[NNODES * HCDIM];
__device__ float g_agg[NNODES * HCDIM];
__device__ float g_h[NNODES * HCDIM];
__device__ float g_e[ETOT * NHEAD];
__device__ float g_emax[NNODES * NHEAD];
__device__ float g_denom[NNODES * NHEAD];

__device__ float g_xl2[NNODES * 2];
__device__ float g_xr2[NNODES * 2];
__device__ float g_e2[ETOT];
__device__ float g_emax2[NNODES];
__device__ float g_denom2[NNODES];
__device__ float g_agg2[NNODES * 2];

// ---------------- helpers --------------------------------------------------
__device__ __forceinline__ void atomicMaxFloat(float* addr, float value) {
    if (value >= 0.0f)
        atomicMax((int*)addr, __float_as_int(value));
    else
        atomicMin((unsigned int*)addr, __float_as_uint(value));
}

__device__ __forceinline__ void red_add_v2(float* ptr, float x, float y) {
    asm volatile("red.global.add.v2.f32 [%0], {%1, %2};"
                 :: "l"(ptr), "f"(x), "f"(y) : "memory");
}

__device__ __forceinline__ void edge_endpoints(const int* __restrict__ ei, int e,
                                               int& src, int& dst) {
    if (e < NEDGES) { src = ei[e]; dst = ei[NEDGES + e]; }
    else            { src = e - NEDGES; dst = src; }
}

// ---------------- fill -----------------------------------------------------
__global__ void fill_kernel(float* p, int n, float v) {
    int i = blockIdx.x * blockDim.x + threadIdx.x;
    if (i < n) p[i] = v;
}

// ---------------- SGEMM (fp32, 64x64 tile, 4x4 microtile) ------------------
__global__ void sgemm_kernel(const float* __restrict__ A, const float* __restrict__ B,
                             float* __restrict__ Cmat, int M, int Ncols, int K) {
    const int BM = 64, BN = 64, BK = 16;
    __shared__ float As[BK][BM];
    __shared__ float Bs[BK][BN];
    int tid = threadIdx.x;
    int by = blockIdx.y, bx = blockIdx.x;
    int trow = tid >> 4, tcol = tid & 15;
    float acc[4][4];
#pragma unroll
    for (int i = 0; i < 4; i++)
#pragma unroll
        for (int j = 0; j < 4; j++) acc[i][j] = 0.0f;

    int aRow = tid >> 2;
    int aCol = (tid & 3) << 2;
    int bRow = tid >> 4;
    int bCol = (tid & 15) << 2;
    int gARow = by * BM + aRow;
    const float* Aptr = A + (long)gARow * K;

    for (int k0 = 0; k0 < K; k0 += BK) {
        float4 av = make_float4(0.f, 0.f, 0.f, 0.f);
        if (gARow < M) av = *(const float4*)(Aptr + k0 + aCol);
        As[aCol + 0][aRow] = av.x;
        As[aCol + 1][aRow] = av.y;
        As[aCol + 2][aRow] = av.z;
        As[aCol + 3][aRow] = av.w;
        float4 bv = *(const float4*)(B + (long)(k0 + bRow) * Ncols + bx * BN + bCol);
        *(float4*)&Bs[bRow][bCol] = bv;
        __syncthreads();
#pragma unroll
        for (int k = 0; k < BK; k++) {
            float a[4], b[4];
#pragma unroll
            for (int i = 0; i < 4; i++) a[i] = As[k][trow * 4 + i];
#pragma unroll
            for (int j = 0; j < 4; j++) b[j] = Bs[k][tcol * 4 + j];
#pragma unroll
            for (int i = 0; i < 4; i++)
#pragma unroll
                for (int j = 0; j < 4; j++) acc[i][j] += a[i] * b[j];
        }
        __syncthreads();
    }
#pragma unroll
    for (int i = 0; i < 4; i++) {
        int r = by * BM + trow * 4 + i;
        if (r < M) {
            float4 o = make_float4(acc[i][0], acc[i][1], acc[i][2], acc[i][3]);
            *(float4*)(Cmat + (long)r * Ncols + bx * BN + tcol * 4) = o;
        }
    }
}

// ---------------- edge kernels (layers 0/1, H=4, C=64) ---------------------
// Warp per (edge, head): compute e = sum_c leakyrelu(xl[src]+xr[dst]) * att
__global__ void edge_e_kernel(const int* __restrict__ ei,
                              const float* __restrict__ xl,
                              const float* __restrict__ xr,
                              const float* __restrict__ att,
                              float* __restrict__ e_out,
                              float* __restrict__ emax) {
    int w = (blockIdx.x * blockDim.x + threadIdx.x) >> 5;
    int lane = threadIdx.x & 31;
    if (w >= ETOT * NHEAD) return;
    int edge = w >> 2;
    int head = w & 3;
    int src, dst;
    edge_endpoints(ei, edge, src, dst);
    const float2* pl = (const float2*)(xl + (long)src * HCDIM + head * CDIM);
    const float2* pr = (const float2*)(xr + (long)dst * HCDIM + head * CDIM);
    const float2* pa = (const float2*)(att + head * CDIM);
    float2 l = pl[lane], r = pr[lane], a = pa[lane];
    float mx = l.x + r.x, my = l.y + r.y;
    mx = mx > 0.f ? mx : 0.2f * mx;
    my = my > 0.f ? my : 0.2f * my;
    float s = mx * a.x + my * a.y;
#pragma unroll
    for (int off = 16; off; off >>= 1) s += __shfl_xor_sync(0xFFFFFFFFu, s, off);
    if (lane == 0) {
        e_out[w] = s;
        atomicMaxFloat(&emax[dst * NHEAD + head], s);
    }
}

// Thread per (edge, head): ex = exp(e - emax[dst]); denom += ex  (in-place on e)
__global__ void edge_exp_kernel(const int* __restrict__ ei,
                                float* __restrict__ e_inout,
                                const float* __restrict__ emax,
                                float* __restrict__ denom) {
    int t = blockIdx.x * blockDim.x + threadIdx.x;
    if (t >= ETOT * NHEAD) return;
    int edge = t >> 2;
    int head = t & 3;
    int dst = (edge < NEDGES) ? ei[NEDGES + edge] : edge - NEDGES;
    float ex = expf(e_inout[t] - emax[dst * NHEAD + head]);
    e_inout[t] = ex;
    atomicAdd(&denom[dst * NHEAD + head], ex);
}

// Warp per (edge, head): agg[dst] += alpha * xl[src]
__global__ void edge_agg_kernel(const int* __restrict__ ei,
                                const float* __restrict__ ex,
                                const float* __restrict__ denom,
                                const float* __restrict__ xl,
                                float* __restrict__ agg) {
    int w = (blockIdx.x * blockDim.x + threadIdx.x) >> 5;
    int lane = threadIdx.x & 31;
    if (w >= ETOT * NHEAD) return;
    int edge = w >> 2;
    int head = w & 3;
    int src, dst;
    edge_endpoints(ei, edge, src, dst);
    float alpha = ex[w] / (denom[dst * NHEAD + head] + 1e-16f);
    const float2* pl = (const float2*)(xl + (long)src * HCDIM + head * CDIM);
    float2 v = pl[lane];
    float* dstp = agg + (long)dst * HCDIM + head * CDIM + 2 * lane;
    red_add_v2(dstp, alpha * v.x, alpha * v.y);
}

// Per-element epilogue: +bias, BN(eval), ELU
__global__ void node_post_kernel(const float* __restrict__ agg,
                                 const float* __restrict__ b,
                                 const float* __restrict__ g,
                                 const float* __restrict__ be,
                                 const float* __restrict__ m,
                                 const float* __restrict__ v,
                                 float* __restrict__ out) {
    int i = blockIdx.x * blockDim.x + threadIdx.x;
    if (i >= NNODES * HCDIM) return;
    int col = i & (HCDIM - 1);
    float x = agg[i] + b[col];
    x = (x - m[col]) * (g[col] * rsqrtf(v[col] + EPS_BN)) + be[col];
    out[i] = x > 0.f ? x : (expf(x) - 1.0f);
}

// ---------------- layer 2 (HC=256 -> 2, single head) -----------------------
// Warp per node: xl2 = h @ Wl2, xr2 = h @ Wr2 (both 256->2)
__global__ void gemm2_kernel(const float* __restrict__ h,
                             const float* __restrict__ Wl,
                             const float* __restrict__ Wr,
                             float* __restrict__ xl2,
                             float* __restrict__ xr2) {
    int w = (blockIdx.x * blockDim.x + threadIdx.x) >> 5;
    int lane = threadIdx.x & 31;
    if (w >= NNODES) return;
    float al0 = 0.f, al1 = 0.f, ar0 = 0.f, ar1 = 0.f;
    const float* hp = h + (long)w * HCDIM;
#pragma unroll
    for (int k = lane; k < HCDIM; k += 32) {
        float hv = hp[k];
        float2 wl = *(const float2*)(Wl + k * 2);
        float2 wr = *(const float2*)(Wr + k * 2);
        al0 += hv * wl.x; al1 += hv * wl.y;
        ar0 += hv * wr.x; ar1 += hv * wr.y;
    }
#pragma unroll
    for (int off = 16; off; off >>= 1) {
        al0 += __shfl_xor_sync(0xFFFFFFFFu, al0, off);
        al1 += __shfl_xor_sync(0xFFFFFFFFu, al1, off);
        ar0 += __shfl_xor_sync(0xFFFFFFFFu, ar0, off);
        ar1 += __shfl_xor_sync(0xFFFFFFFFu, ar1, off);
    }
    if (lane == 0) {
        xl2[w * 2 + 0] = al0; xl2[w * 2 + 1] = al1;
        xr2[w * 2 + 0] = ar0; xr2[w * 2 + 1] = ar1;
    }
}

__global__ void edge_e2_kernel(const int* __restrict__ ei,
                               const float* __restrict__ xl2,
                               const float* __restrict__ xr2,
                               const float* __restrict__ att2,
                               float* __restrict__ e_out,
                               float* __restrict__ emax) {
    int t = blockIdx.x * blockDim.x + threadIdx.x;
    if (t >= ETOT) return;
    int src, dst;
    edge_endpoints(ei, t, src, dst);
    float2 l = *(const float2*)(xl2 + src * 2);
    float2 r = *(const float2*)(xr2 + dst * 2);
    float mx = l.x + r.x, my = l.y + r.y;
    mx = mx > 0.f ? mx : 0.2f * mx;
    my = my > 0.f ? my : 0.2f * my;
    float e = mx * att2[0] + my * att2[1];
    e_out[t] = e;
    atomicMaxFloat(&emax[dst], e);
}

__global__ void edge_exp2_kernel(const int* __restrict__ ei,
                                 float* __restrict__ e_inout,
                                 const float* __restrict__ emax,
                                 float* __restrict__ denom) {
    int t = blockIdx.x * blockDim.x + threadIdx.x;
    if (t >= ETOT) return;
    int dst = (t < NEDGES) ? ei[NEDGES + t] : t - NEDGES;
    float ex = expf(e_inout[t] - emax[dst]);
    e_inout[t] = ex;
    atomicAdd(&denom[dst], ex);
}

__global__ void edge_agg2_kernel(const int* __restrict__ ei,
                                 const float* __restrict__ ex,
                                 const float* __restrict__ denom,
                                 const float* __restrict__ xl2,
                                 float* __restrict__ agg2) {
    int t = blockIdx.x * blockDim.x + threadIdx.x;
    if (t >= ETOT) return;
    int src, dst;
    edge_endpoints(ei, t, src, dst);
    float alpha = ex[t] / (denom[dst] + 1e-16f);
    float2 v = *(const float2*)(xl2 + src * 2);
    red_add_v2(agg2 + dst * 2, alpha * v.x, alpha * v.y);
}

__global__ void final_kernel(const float* __restrict__ agg2,
                             const float* __restrict__ b2,
                             float* __restrict__ out) {
    int n = blockIdx.x * blockDim.x + threadIdx.x;
    if (n >= NNODES) return;
    float o0 = agg2[n * 2 + 0] + b2[0];
    float o1 = agg2[n * 2 + 1] + b2[1];
    float mx = fmaxf(o0, o1);
    float lse = mx + logf(expf(o0 - mx) + expf(o1 - mx));
    out[n * 2 + 0] = o0 - lse;
    out[n * 2 + 1] = o1 - lse;
}

// ---------------- launch ---------------------------------------------------
extern "C" void kernel_launch(void* const* d_in, const int* in_sizes, int n_in,
                              void* d_out, int out_size) {
    const float* x   = (const float*)d_in[0];
    const int*   ei  = (const int*)d_in[1];
    const float* Wl0 = (const float*)d_in[2];
    const float* Wr0 = (const float*)d_in[3];
    const float* att0= (const float*)d_in[4];
    const float* b0  = (const float*)d_in[5];
    const float* g0  = (const float*)d_in[6];
    const float* be0 = (const float*)d_in[7];
    const float* m0  = (const float*)d_in[8];
    const float* v0  = (const float*)d_in[9];
    const float* Wl1 = (const float*)d_in[10];
    const float* Wr1 = (const float*)d_in[11];
    const float* att1= (const float*)d_in[12];
    const float* b1  = (const float*)d_in[13];
    const float* g1  = (const float*)d_in[14];
    const float* be1 = (const float*)d_in[15];
    const float* m1  = (const float*)d_in[16];
    const float* v1  = (const float*)d_in[17];
    const float* Wl2 = (const float*)d_in[18];
    const float* Wr2 = (const float*)d_in[19];
    const float* att2= (const float*)d_in[20];
    const float* b2  = (const float*)d_in[21];
    float* out = (float*)d_out;

    float *p_xl, *p_xr, *p_agg, *p_h, *p_e, *p_emax, *p_denom;
    float *p_xl2, *p_xr2, *p_e2, *p_emax2, *p_denom2, *p_agg2;
    cudaGetSymbolAddress((void**)&p_xl, g_xl);
    cudaGetSymbolAddress((void**)&p_xr, g_xr);
    cudaGetSymbolAddress((void**)&p_agg, g_agg);
    cudaGetSymbolAddress((void**)&p_h, g_h);
    cudaGetSymbolAddress((void**)&p_e, g_e);
    cudaGetSymbolAddress((void**)&p_emax, g_emax);
    cudaGetSymbolAddress((void**)&p_denom, g_denom);
    cudaGetSymbolAddress((void**)&p_xl2, g_xl2);
    cudaGetSymbolAddress((void**)&p_xr2, g_xr2);
    cudaGetSymbolAddress((void**)&p_e2, g_e2);
    cudaGetSymbolAddress((void**)&p_emax2, g_emax2);
    cudaGetSymbolAddress((void**)&p_denom2, g_denom2);
    cudaGetSymbolAddress((void**)&p_agg2, g_agg2);

    const float NEG_INF = -INFINITY;
    dim3 gemmGrid(HCDIM / 64, (NNODES + 63) / 64);
    int edgeWarps = ETOT * NHEAD;
    int edgeWarpBlocks = (edgeWarps * 32 + 255) / 256;
    int edgeThreadBlocks = (edgeWarps + 255) / 256;
    int nodeElemBlocks = (NNODES * HCDIM + 255) / 256;
    int nhBlocks = (NNODES * NHEAD + 255) / 256;
    int eScalarBlocks = (ETOT + 255) / 256;
    int nodeBlocks = (NNODES + 255) / 256;
    int nodeWarpBlocks = (NNODES * 32 + 255) / 256;

    // ===== Layer 0 =====
    sgemm_kernel<<<gemmGrid, 256>>>(x, Wl0, p_xl, NNODES, HCDIM, INDIM);
    sgemm_kernel<<<gemmGrid, 256>>>(x, Wr0, p_xr, NNODES, HCDIM, INDIM);
    fill_kernel<<<nhBlocks, 256>>>(p_emax, NNODES * NHEAD, NEG_INF);
    fill_kernel<<<nhBlocks, 256>>>(p_denom, NNODES * NHEAD, 0.f);
    fill_kernel<<<nodeElemBlocks, 256>>>(p_agg, NNODES * HCDIM, 0.f);
    edge_e_kernel<<<edgeWarpBlocks, 256>>>(ei, p_xl, p_xr, att0, p_e, p_emax);
    edge_exp_kernel<<<edgeThreadBlocks, 256>>>(ei, p_e, p_emax, p_denom);
    edge_agg_kernel<<<edgeWarpBlocks, 256>>>(ei, p_e, p_denom, p_xl, p_agg);
    node_post_kernel<<<nodeElemBlocks, 256>>>(p_agg, b0, g0, be0, m0, v0, p_h);

    // ===== Layer 1 =====
    sgemm_kernel<<<gemmGrid, 256>>>(p_h, Wl1, p_xl, NNODES, HCDIM, HCDIM);
    sgemm_kernel<<<gemmGrid, 256>>>(p_h, Wr1, p_xr, NNODES, HCDIM, HCDIM);
    fill_kernel<<<nhBlocks, 256>>>(p_emax, NNODES * NHEAD, NEG_INF);
    fill_kernel<<<nhBlocks, 256>>>(p_denom, NNODES * NHEAD, 0.f);
    fill_kernel<<<nodeElemBlocks, 256>>>(p_agg, NNODES * HCDIM, 0.f);
    edge_e_kernel<<<edgeWarpBlocks, 256>>>(ei, p_xl, p_xr, att1, p_e, p_emax);
    edge_exp_kernel<<<edgeThreadBlocks, 256>>>(ei, p_e, p_emax, p_denom);
    edge_agg_kernel<<<edgeWarpBlocks, 256>>>(ei, p_e, p_denom, p_xl, p_agg);
    node_post_kernel<<<nodeElemBlocks, 256>>>(p_agg, b1, g1, be1, m1, v1, p_h);

    // ===== Layer 2 =====
    gemm2_kernel<<<nodeWarpBlocks, 256>>>(p_h, Wl2, Wr2, p_xl2, p_xr2);
    fill_kernel<<<nodeBlocks, 256>>>(p_emax2, NNODES, NEG_INF);
    fill_kernel<<<nodeBlocks, 256>>>(p_denom2, NNODES, 0.f);
    fill_kernel<<<(NNODES * 2 + 255) / 256, 256>>>(p_agg2, NNODES * 2, 0.f);
    edge_e2_kernel<<<eScalarBlocks, 256>>>(ei, p_xl2, p_xr2, att2, p_e2, p_emax2);
    edge_exp2_kernel<<<eScalarBlocks, 256>>>(ei, p_e2, p_emax2, p_denom2);
    edge_agg2_kernel<<<eScalarBlocks, 256>>>(ei, p_e2, p_denom2, p_xl2, p_agg2);
    final_kernel<<<nodeBlocks, 256>>>(p_agg2, b2, out);
}

// round 5
// speedup vs baseline: 1.3111x; 1.3111x over previous
#include <cuda_runtime.h>
#include <cuda_bf16.h>
#include <math.h>
#include <stdint.h>

// Problem constants (fixed by reference)
#define NNODES 20000
#define NEDGES 320000
#define ETOT   340000   // NEDGES + NNODES self loops
#define INDIM  512
#define NHEAD  4
#define CDIM   64
#define HCDIM  256
#define NOUT   512      // dual-GEMM output width (xl | xr)
#define EPS_BN 1e-5f

// ---------------- scratch (device globals; no allocation allowed) ----------
__device__ float g_xlr[NNODES * NOUT];   // cols 0-255: xl, 256-511: xr
__device__ float g_agg[NNODES * HCDIM];
__device__ float g_h[NNODES * HCDIM];
__device__ float g_e[ETOT * NHEAD];
__device__ float g_denom[NNODES * NHEAD];

__device__ float g_xl2[NNODES * 2];
__device__ float g_xr2[NNODES * 2];
__device__ float g_e2[ETOT];
__device__ float g_denom2[NNODES];
__device__ float g_agg2[NNODES * 2];

// bf16 hi/lo split buffers for tensor-core GEMMs
__device__ __nv_bfloat16 g_xhi[NNODES * INDIM];
__device__ __nv_bfloat16 g_xlo[NNODES * INDIM];
__device__ __nv_bfloat16 g_hhi[NNODES * HCDIM];
__device__ __nv_bfloat16 g_hlo[NNODES * HCDIM];
// concatenated, transposed (N-major, K-contiguous) weight splits: [512, K]
__device__ __nv_bfloat16 g_w0h[NOUT * INDIM];
__device__ __nv_bfloat16 g_w0l[NOUT * INDIM];
__device__ __nv_bfloat16 g_w1h[NOUT * HCDIM];
__device__ __nv_bfloat16 g_w1l[NOUT * HCDIM];

// ---------------- PTX helpers ----------------------------------------------
__device__ __forceinline__ uint32_t smem_to_u32(const void* smem_ptr) {
    uint32_t addr;
    asm("{ .reg .u64 tmp; cvta.to.shared.u64 tmp, %1; cvt.u32.u64 %0, tmp; }"
        : "=r"(addr) : "l"(smem_ptr));
    return addr;
}

__device__ __forceinline__ void cp_async16(uint32_t dst, const void* src) {
    asm volatile("cp.async.cg.shared.global [%0], [%1], 16;" :: "r"(dst), "l"(src));
}
#define CP_COMMIT() asm volatile("cp.async.commit_group;" ::: "memory")
#define CP_WAIT(n)  asm volatile("cp.async.wait_group %0;" :: "n"(n) : "memory")

__device__ __forceinline__ void ldsm_x4(uint32_t (&r)[4], uint32_t addr) {
    asm volatile("ldmatrix.sync.aligned.m8n8.x4.shared.b16 {%0,%1,%2,%3}, [%4];"
                 : "=r"(r[0]), "=r"(r[1]), "=r"(r[2]), "=r"(r[3]) : "r"(addr));
}
__device__ __forceinline__ void ldsm_x2(uint32_t (&r)[2], uint32_t addr) {
    asm volatile("ldmatrix.sync.aligned.m8n8.x2.shared.b16 {%0,%1}, [%2];"
                 : "=r"(r[0]), "=r"(r[1]) : "r"(addr));
}
__device__ __forceinline__ void mma_bf16(float (&d)[4], const uint32_t (&a)[4],
                                         const uint32_t (&b)[2]) {
    asm volatile("mma.sync.aligned.m16n8k16.row.col.f32.bf16.bf16.f32 "
                 "{%0,%1,%2,%3}, {%4,%5,%6,%7}, {%8,%9}, {%0,%1,%2,%3};"
                 : "+f"(d[0]), "+f"(d[1]), "+f"(d[2]), "+f"(d[3])
                 : "r"(a[0]), "r"(a[1]), "r"(a[2]), "r"(a[3]),
                   "r"(b[0]), "r"(b[1]));
}

// ---------------- misc helpers ---------------------------------------------
__device__ __forceinline__ void red_add_v2(float* ptr, float x, float y) {
    asm volatile("red.global.add.v2.f32 [%0], {%1, %2};"
                 :: "l"(ptr), "f"(x), "f"(y) : "memory");
}

__device__ __forceinline__ void edge_endpoints(const int* __restrict__ ei, int e,
                                               int& src, int& dst) {
    if (e < NEDGES) { src = ei[e]; dst = ei[NEDGES + e]; }
    else            { src = e - NEDGES; dst = src; }
}

// ---------------- fill -----------------------------------------------------
__global__ void fill_kernel(float* p, int n, float v) {
    int i = blockIdx.x * blockDim.x + threadIdx.x;
    if (i < n) p[i] = v;
}

// ---------------- bf16 split kernels ---------------------------------------
__global__ void xsplit_kernel(const float* __restrict__ X, int n,
                              __nv_bfloat16* __restrict__ Xh,
                              __nv_bfloat16* __restrict__ Xl) {
    int i = blockIdx.x * blockDim.x + threadIdx.x;
    if (i >= n) return;
    float v = X[i];
    __nv_bfloat16 h = __float2bfloat16(v);
    Xh[i] = h;
    Xl[i] = __float2bfloat16(v - __bfloat162float(h));
}

// Transpose [K, 256] fp32 weight into [256, K] bf16 hi/lo (K contiguous)
__global__ void wsplit_kernel(const float* __restrict__ W, int K,
                              __nv_bfloat16* __restrict__ Wh,
                              __nv_bfloat16* __restrict__ Wl) {
    int i = blockIdx.x * blockDim.x + threadIdx.x;
    if (i >= HCDIM * K) return;
    int n = i / K, k = i - n * K;
    float v = W[(size_t)k * HCDIM + n];
    __nv_bfloat16 h = __float2bfloat16(v);
    Wh[i] = h;
    Wl[i] = __float2bfloat16(v - __bfloat162float(h));
}

// ---------------- HMMA dual GEMM -------------------------------------------
// C[M, 512] = A[M, K] * B[512, K]^T with bf16 hi/lo compensation:
//   D = Ah*Bh + Ah*Bl + Al*Bh   (fp32 accumulate)
// Block tile 128x128, 8 warps (2m x 4n), warp tile 64x32, K chunk 32,
// double-buffered cp.async, XOR-swizzled 64B smem rows, ldmatrix frags.
#define GSTAGE 32768    // bytes per stage: Ah 8K | Al 8K | Bh 8K | Bl 8K
#define GSMEM  (2 * GSTAGE)

__global__ void __launch_bounds__(256, 1)
hmma_dual_gemm(const __nv_bfloat16* __restrict__ Ah,
               const __nv_bfloat16* __restrict__ Al,
               const __nv_bfloat16* __restrict__ Bh,
               const __nv_bfloat16* __restrict__ Bl,
               float* __restrict__ C, int M, int K) {
    extern __shared__ char smem[];
    uint32_t sb = smem_to_u32(smem);
    int tid = threadIdx.x;
    int lane = tid & 31, wid = tid >> 5;
    int wm = wid >> 2, wn = wid & 3;
    int mBase = blockIdx.y * 128;
    int nBase = blockIdx.x * 128;
    int nq = K >> 5;

    float acc[4][4][4];
#pragma unroll
    for (int a = 0; a < 4; a++)
#pragma unroll
        for (int b = 0; b < 4; b++)
#pragma unroll
            for (int c = 0; c < 4; c++) acc[a][b][c] = 0.f;

    // stage loader: 32 rows of K per chunk; 64B rows, 4x 16B chunks, XOR swizzle
    auto load_stage = [&](int q, int s) {
        int k0 = q << 5;
        uint32_t base = sb + s * GSTAGE;
        char* sm = smem + s * GSTAGE;
#pragma unroll
        for (int it = 0; it < 2; it++) {
            int idx = tid + it * 256;               // 512 chunks for A
            int r = idx >> 2, c = idx & 3;
            uint32_t dsw = r * 64 + ((c ^ (r & 3)) << 4);
            int R = mBase + r;
            if (R < M) {
                const char* sh = (const char*)(Ah + (size_t)R * K + k0) + c * 16;
                const char* sl = (const char*)(Al + (size_t)R * K + k0) + c * 16;
                cp_async16(base + dsw, sh);
                cp_async16(base + 8192 + dsw, sl);
            } else {
                uint4 z = make_uint4(0, 0, 0, 0);
                *(uint4*)(sm + dsw) = z;
                *(uint4*)(sm + 8192 + dsw) = z;
            }
        }
#pragma unroll
        for (int it = 0; it < 2; it++) {
            int idx = tid + it * 256;               // 512 chunks for B
            int r = idx >> 2, c = idx & 3;
            uint32_t dsw = r * 64 + ((c ^ (r & 3)) << 4);
            int NR = nBase + r;                     // always < 512
            const char* sh = (const char*)(Bh + (size_t)NR * K + k0) + c * 16;
            const char* sl = (const char*)(Bl + (size_t)NR * K + k0) + c * 16;
            cp_async16(base + 16384 + dsw, sh);
            cp_async16(base + 24576 + dsw, sl);
        }
    };

    load_stage(0, 0); CP_COMMIT();

    for (int q = 0; q < nq; q++) {
        if (q + 1 < nq) {
            load_stage(q + 1, (q + 1) & 1); CP_COMMIT();
            CP_WAIT(1);
        } else {
            CP_WAIT(0);
        }
        __syncthreads();
        uint32_t base = sb + (q & 1) * GSTAGE;

#pragma unroll
        for (int step = 0; step < 2; step++) {
            uint32_t ahf[4][4], alf[4][4], bhf[4][2], blf[4][2];
            int arow = wm * 64 + (lane & 15);
            int ac = 2 * step + (lane >> 4);
#pragma unroll
            for (int mi = 0; mi < 4; mi++) {
                int r = arow + mi * 16;
                uint32_t ad = base + r * 64 + ((ac ^ (r & 3)) << 4);
                ldsm_x4(ahf[mi], ad);
                ldsm_x4(alf[mi], ad + 8192);
            }
#pragma unroll
            for (int nj = 0; nj < 4; nj++) {
                int r = wn * 32 + nj * 8 + (lane & 7);
                int bc = 2 * step + ((lane >> 3) & 1);
                uint32_t bd = base + 16384 + r * 64 + ((bc ^ (r & 3)) << 4);
                ldsm_x2(bhf[nj], bd);
                ldsm_x2(blf[nj], bd + 8192);
            }
#pragma unroll
            for (int mi = 0; mi < 4; mi++)
#pragma unroll
                for (int nj = 0; nj < 4; nj++) {
                    mma_bf16(acc[mi][nj], ahf[mi], bhf[nj]);
                    mma_bf16(acc[mi][nj], ahf[mi], blf[nj]);
                    mma_bf16(acc[mi][nj], alf[mi], bhf[nj]);
                }
        }
        __syncthreads();
    }

    // epilogue: direct float2 stores
    int rBase = mBase + wm * 64;
    int cBase = nBase + wn * 32;
#pragma unroll
    for (int mi = 0; mi < 4; mi++) {
        int r0 = rBase + mi * 16 + (lane >> 2);
#pragma unroll
        for (int nj = 0; nj < 4; nj++) {
            int cc = cBase + nj * 8 + 2 * (lane & 3);
            if (r0 < M)
                *(float2*)(C + (size_t)r0 * NOUT + cc) =
                    make_float2(acc[mi][nj][0], acc[mi][nj][1]);
            if (r0 + 8 < M)
                *(float2*)(C + (size_t)(r0 + 8) * NOUT + cc) =
                    make_float2(acc[mi][nj][2], acc[mi][nj][3]);
        }
    }
}

// ---------------- edge kernels (layers 0/1, H=4, C=64) ---------------------
// xlr layout: row stride 512, xl = cols 0-255, xr = cols 256-511
__global__ void edge_es_kernel(const int* __restrict__ ei,
                               const float* __restrict__ xlr,
                               const float* __restrict__ att,
                               float* __restrict__ ex_out,
                               float* __restrict__ denom) {
    int w = (blockIdx.x * blockDim.x + threadIdx.x) >> 5;
    int lane = threadIdx.x & 31;
    if (w >= ETOT * NHEAD) return;
    int edge = w >> 2;
    int head = w & 3;
    int src, dst;
    edge_endpoints(ei, edge, src, dst);
    const float2* pl = (const float2*)(xlr + (long)src * NOUT + head * CDIM);
    const float2* pr = (const float2*)(xlr + (long)dst * NOUT + 256 + head * CDIM);
    const float2* pa = (const float2*)(att + head * CDIM);
    float2 l = pl[lane], r = pr[lane], a = pa[lane];
    float mx = l.x + r.x, my = l.y + r.y;
    mx = mx > 0.f ? mx : 0.2f * mx;
    my = my > 0.f ? my : 0.2f * my;
    float s = mx * a.x + my * a.y;
#pragma unroll
    for (int off = 16; off; off >>= 1) s += __shfl_xor_sync(0xFFFFFFFFu, s, off);
    if (lane == 0) {
        float exv = expf(s);
        ex_out[w] = exv;
        atomicAdd(&denom[dst * NHEAD + head], exv);
    }
}

__global__ void edge_agg_kernel(const int* __restrict__ ei,
                                const float* __restrict__ ex,
                                const float* __restrict__ denom,
                                const float* __restrict__ xlr,
                                float* __restrict__ agg) {
    int w = (blockIdx.x * blockDim.x + threadIdx.x) >> 5;
    int lane = threadIdx.x & 31;
    if (w >= ETOT * NHEAD) return;
    int edge = w >> 2;
    int head = w & 3;
    int src, dst;
    edge_endpoints(ei, edge, src, dst);
    float alpha = ex[w] / (denom[dst * NHEAD + head] + 1e-16f);
    const float2* pl = (const float2*)(xlr + (long)src * NOUT + head * CDIM);
    float2 v = pl[lane];
    float* dstp = agg + (long)dst * HCDIM + head * CDIM + 2 * lane;
    red_add_v2(dstp, alpha * v.x, alpha * v.y);
}

// Epilogue: +bias, BN(eval), ELU; also emit bf16 hi/lo split of result
__global__ void node_post_kernel(const float* __restrict__ agg,
                                 const float* __restrict__ b,
                                 const float* __restrict__ g,
                                 const float* __restrict__ be,
                                 const float* __restrict__ m,
                                 const float* __restrict__ v,
                                 float* __restrict__ out,
                                 __nv_bfloat16* __restrict__ outh,
                                 __nv_bfloat16* __restrict__ outl) {
    int i = blockIdx.x * blockDim.x + threadIdx.x;
    if (i >= NNODES * HCDIM) return;
    int col = i & (HCDIM - 1);
    float x = agg[i] + b[col];
    x = (x - m[col]) * (g[col] * rsqrtf(v[col] + EPS_BN)) + be[col];
    x = x > 0.f ? x : (expf(x) - 1.0f);
    out[i] = x;
    __nv_bfloat16 h = __float2bfloat16(x);
    outh[i] = h;
    outl[i] = __float2bfloat16(x - __bfloat162float(h));
}

// ---------------- layer 2 (HC=256 -> 2, single head) -----------------------
__global__ void gemm2_kernel(const float* __restrict__ h,
                             const float* __restrict__ Wl,
                             const float* __restrict__ Wr,
                             float* __restrict__ xl2,
                             float* __restrict__ xr2) {
    int w = (blockIdx.x * blockDim.x + threadIdx.x) >> 5;
    int lane = threadIdx.x & 31;
    if (w >= NNODES) return;
    float al0 = 0.f, al1 = 0.f, ar0 = 0.f, ar1 = 0.f;
    const float* hp = h + (long)w * HCDIM;
#pragma unroll
    for (int k = lane; k < HCDIM; k += 32) {
        float hv = hp[k];
        float2 wl = *(const float2*)(Wl + k * 2);
        float2 wr = *(const float2*)(Wr + k * 2);
        al0 += hv * wl.x; al1 += hv * wl.y;
        ar0 += hv * wr.x; ar1 += hv * wr.y;
    }
#pragma unroll
    for (int off = 16; off; off >>= 1) {
        al0 += __shfl_xor_sync(0xFFFFFFFFu, al0, off);
        al1 += __shfl_xor_sync(0xFFFFFFFFu, al1, off);
        ar0 += __shfl_xor_sync(0xFFFFFFFFu, ar0, off);
        ar1 += __shfl_xor_sync(0xFFFFFFFFu, ar1, off);
    }
    if (lane == 0) {
        xl2[w * 2 + 0] = al0; xl2[w * 2 + 1] = al1;
        xr2[w * 2 + 0] = ar0; xr2[w * 2 + 1] = ar1;
    }
}

__global__ void edge_e2_kernel(const int* __restrict__ ei,
                               const float* __restrict__ xl2,
                               const float* __restrict__ xr2,
                               const float* __restrict__ att2,
                               float* __restrict__ ex_out,
                               float* __restrict__ denom) {
    int t = blockIdx.x * blockDim.x + threadIdx.x;
    if (t >= ETOT) return;
    int src, dst;
    edge_endpoints(ei, t, src, dst);
    float2 l = *(const float2*)(xl2 + src * 2);
    float2 r = *(const float2*)(xr2 + dst * 2);
    float mx = l.x + r.x, my = l.y + r.y;
    mx = mx > 0.f ? mx : 0.2f * mx;
    my = my > 0.f ? my : 0.2f * my;
    float e = mx * att2[0] + my * att2[1];
    float exv = expf(e);
    ex_out[t] = exv;
    atomicAdd(&denom[dst], exv);
}

__global__ void edge_agg2_kernel(const int* __restrict__ ei,
                                 const float* __restrict__ ex,
                                 const float* __restrict__ denom,
                                 const float* __restrict__ xl2,
                                 float* __restrict__ agg2) {
    int t = blockIdx.x * blockDim.x + threadIdx.x;
    if (t >= ETOT) return;
    int src, dst;
    edge_endpoints(ei, t, src, dst);
    float alpha = ex[t] / (denom[dst] + 1e-16f);
    float2 v = *(const float2*)(xl2 + src * 2);
    red_add_v2(agg2 + dst * 2, alpha * v.x, alpha * v.y);
}

__global__ void final_kernel(const float* __restrict__ agg2,
                             const float* __restrict__ b2,
                             float* __restrict__ out) {
    int n = blockIdx.x * blockDim.x + threadIdx.x;
    if (n >= NNODES) return;
    float o0 = agg2[n * 2 + 0] + b2[0];
    float o1 = agg2[n * 2 + 1] + b2[1];
    float mx = fmaxf(o0, o1);
    float lse = mx + logf(expf(o0 - mx) + expf(o1 - mx));
    out[n * 2 + 0] = o0 - lse;
    out[n * 2 + 1] = o1 - lse;
}

// ---------------- launch ---------------------------------------------------
extern "C" void kernel_launch(void* const* d_in, const int* in_sizes, int n_in,
                              void* d_out, int out_size) {
    const float* x   = (const float*)d_in[0];
    const int*   ei  = (const int*)d_in[1];
    const float* Wl0 = (const float*)d_in[2];
    const float* Wr0 = (const float*)d_in[3];
    const float* att0= (const float*)d_in[4];
    const float* b0  = (const float*)d_in[5];
    const float* g0  = (const float*)d_in[6];
    const float* be0 = (const float*)d_in[7];
    const float* m0  = (const float*)d_in[8];
    const float* v0  = (const float*)d_in[9];
    const float* Wl1 = (const float*)d_in[10];
    const float* Wr1 = (const float*)d_in[11];
    const float* att1= (const float*)d_in[12];
    const float* b1  = (const float*)d_in[13];
    const float* g1  = (const float*)d_in[14];
    const float* be1 = (const float*)d_in[15];
    const float* m1  = (const float*)d_in[16];
    const float* v1  = (const float*)d_in[17];
    const float* Wl2 = (const float*)d_in[18];
    const float* Wr2 = (const float*)d_in[19];
    const float* att2= (const float*)d_in[20];
    const float* b2  = (const float*)d_in[21];
    float* out = (float*)d_out;

    float *p_xlr, *p_agg, *p_h, *p_e, *p_denom;
    float *p_xl2, *p_xr2, *p_e2, *p_denom2, *p_agg2;
    __nv_bfloat16 *p_xhi, *p_xlo, *p_hhi, *p_hlo;
    __nv_bfloat16 *p_w0h, *p_w0l, *p_w1h, *p_w1l;
    cudaGetSymbolAddress((void**)&p_xlr, g_xlr);
    cudaGetSymbolAddress((void**)&p_agg, g_agg);
    cudaGetSymbolAddress((void**)&p_h, g_h);
    cudaGetSymbolAddress((void**)&p_e, g_e);
    cudaGetSymbolAddress((void**)&p_denom, g_denom);
    cudaGetSymbolAddress((void**)&p_xl2, g_xl2);
    cudaGetSymbolAddress((void**)&p_xr2, g_xr2);
    cudaGetSymbolAddress((void**)&p_e2, g_e2);
    cudaGetSymbolAddress((void**)&p_denom2, g_denom2);
    cudaGetSymbolAddress((void**)&p_agg2, g_agg2);
    cudaGetSymbolAddress((void**)&p_xhi, g_xhi);
    cudaGetSymbolAddress((void**)&p_xlo, g_xlo);
    cudaGetSymbolAddress((void**)&p_hhi, g_hhi);
    cudaGetSymbolAddress((void**)&p_hlo, g_hlo);
    cudaGetSymbolAddress((void**)&p_w0h, g_w0h);
    cudaGetSymbolAddress((void**)&p_w0l, g_w0l);
    cudaGetSymbolAddress((void**)&p_w1h, g_w1h);
    cudaGetSymbolAddress((void**)&p_w1l, g_w1l);

    cudaFuncSetAttribute(hmma_dual_gemm,
                         cudaFuncAttributeMaxDynamicSharedMemorySize, GSMEM);

    int edgeWarps = ETOT * NHEAD;
    int edgeWarpBlocks = (edgeWarps * 32 + 255) / 256;
    int nodeElemBlocks = (NNODES * HCDIM + 255) / 256;
    int nhBlocks = (NNODES * NHEAD + 255) / 256;
    int eScalarBlocks = (ETOT + 255) / 256;
    int nodeBlocks = (NNODES + 255) / 256;
    int nodeWarpBlocks = (NNODES * 32 + 255) / 256;
    dim3 gemmGrid(NOUT / 128, (NNODES + 127) / 128);

    // ===== prep: bf16 splits (concatenated weights: rows 0-255 Wl, 256-511 Wr)
    xsplit_kernel<<<(NNODES * INDIM + 255) / 256, 256>>>(x, NNODES * INDIM, p_xhi, p_xlo);
    wsplit_kernel<<<(HCDIM * INDIM + 255) / 256, 256>>>(Wl0, INDIM, p_w0h, p_w0l);
    wsplit_kernel<<<(HCDIM * INDIM + 255) / 256, 256>>>(Wr0, INDIM,
                                                        p_w0h + 256 * INDIM, p_w0l + 256 * INDIM);
    wsplit_kernel<<<(HCDIM * HCDIM + 255) / 256, 256>>>(Wl1, HCDIM, p_w1h, p_w1l);
    wsplit_kernel<<<(HCDIM * HCDIM + 255) / 256, 256>>>(Wr1, HCDIM,
                                                        p_w1h + 256 * HCDIM, p_w1l + 256 * HCDIM);

    // ===== Layer 0 =====
    hmma_dual_gemm<<<gemmGrid, 256, GSMEM>>>(p_xhi, p_xlo, p_w0h, p_w0l,
                                             p_xlr, NNODES, INDIM);
    fill_kernel<<<nhBlocks, 256>>>(p_denom, NNODES * NHEAD, 0.f);
    fill_kernel<<<nodeElemBlocks, 256>>>(p_agg, NNODES * HCDIM, 0.f);
    edge_es_kernel<<<edgeWarpBlocks, 256>>>(ei, p_xlr, att0, p_e, p_denom);
    edge_agg_kernel<<<edgeWarpBlocks, 256>>>(ei, p_e, p_denom, p_xlr, p_agg);
    node_post_kernel<<<nodeElemBlocks, 256>>>(p_agg, b0, g0, be0, m0, v0,
                                              p_h, p_hhi, p_hlo);

    // ===== Layer 1 =====
    hmma_dual_gemm<<<gemmGrid, 256, GSMEM>>>(p_hhi, p_hlo, p_w1h, p_w1l,
                                             p_xlr, NNODES, HCDIM);
    fill_kernel<<<nhBlocks, 256>>>(p_denom, NNODES * NHEAD, 0.f);
    fill_kernel<<<nodeElemBlocks, 256>>>(p_agg, NNODES * HCDIM, 0.f);
    edge_es_kernel<<<edgeWarpBlocks, 256>>>(ei, p_xlr, att1, p_e, p_denom);
    edge_agg_kernel<<<edgeWarpBlocks, 256>>>(ei, p_e, p_denom, p_xlr, p_agg);
    node_post_kernel<<<nodeElemBlocks, 256>>>(p_agg, b1, g1, be1, m1, v1,
                                              p_h, p_hhi, p_hlo);

    // ===== Layer 2 =====
    gemm2_kernel<<<nodeWarpBlocks, 256>>>(p_h, Wl2, Wr2, p_xl2, p_xr2);
    fill_kernel<<<nodeBlocks, 256>>>(p_denom2, NNODES, 0.f);
    fill_kernel<<<(NNODES * 2 + 255) / 256, 256>>>(p_agg2, NNODES * 2, 0.f);
    edge_e2_kernel<<<eScalarBlocks, 256>>>(ei, p_xl2, p_xr2, att2, p_e2, p_denom2);
    edge_agg2_kernel<<<eScalarBlocks, 256>>>(ei, p_e2, p_denom2, p_xl2, p_agg2);
    final_kernel<<<nodeBlocks, 256>>>(p_agg2, b2, out);
}

// round 6
// speedup vs baseline: 2.3138x; 1.7648x over previous
#include <cuda_runtime.h>
#include <cuda_bf16.h>
#include <math.h>
#include <stdint.h>

// Problem constants (fixed by reference)
#define NNODES 20000
#define NEDGES 320000
#define ETOT   340000   // NEDGES + NNODES self loops
#define INDIM  512
#define NHEAD  4
#define CDIM   64
#define HCDIM  256
#define NOUT   512      // dual-GEMM output width (xl | xr)
#define EPS_BN 1e-5f

// ---------------- scratch (device globals; no allocation allowed) ----------
__device__ float g_xlr[NNODES * NOUT];   // cols 0-255: xl, 256-511: xr
__device__ float g_h[NNODES * HCDIM];
__device__ float g_e[(size_t)ETOT * NHEAD];   // exp(score) per edge x head
__device__ float g_xl2[NNODES * 2];
__device__ float g_xr2[NNODES * 2];

// CSR by destination
__device__ int  g_deg[NNODES];
__device__ int  g_cursor[NNODES];
__device__ int  g_rowptr[NNODES + 1];
__device__ int2 g_csr[ETOT];             // (src, edge_id)

// bf16 hi/lo split buffers for tensor-core GEMMs
__device__ __nv_bfloat16 g_xhi[NNODES * INDIM];
__device__ __nv_bfloat16 g_xlo[NNODES * INDIM];
__device__ __nv_bfloat16 g_hhi[NNODES * HCDIM];
__device__ __nv_bfloat16 g_hlo[NNODES * HCDIM];
// concatenated, transposed (N-major, K-contiguous) weight splits: [512, K]
__device__ __nv_bfloat16 g_w0h[NOUT * INDIM];
__device__ __nv_bfloat16 g_w0l[NOUT * INDIM];
__device__ __nv_bfloat16 g_w1h[NOUT * HCDIM];
__device__ __nv_bfloat16 g_w1l[NOUT * HCDIM];

// ---------------- PTX helpers ----------------------------------------------
__device__ __forceinline__ uint32_t smem_to_u32(const void* smem_ptr) {
    uint32_t addr;
    asm("{ .reg .u64 tmp; cvta.to.shared.u64 tmp, %1; cvt.u32.u64 %0, tmp; }"
        : "=r"(addr) : "l"(smem_ptr));
    return addr;
}

__device__ __forceinline__ void cp_async16(uint32_t dst, const void* src) {
    asm volatile("cp.async.cg.shared.global [%0], [%1], 16;" :: "r"(dst), "l"(src));
}
#define CP_COMMIT() asm volatile("cp.async.commit_group;" ::: "memory")
#define CP_WAIT(n)  asm volatile("cp.async.wait_group %0;" :: "n"(n) : "memory")

__device__ __forceinline__ void ldsm_x4(uint32_t (&r)[4], uint32_t addr) {
    asm volatile("ldmatrix.sync.aligned.m8n8.x4.shared.b16 {%0,%1,%2,%3}, [%4];"
                 : "=r"(r[0]), "=r"(r[1]), "=r"(r[2]), "=r"(r[3]) : "r"(addr));
}
__device__ __forceinline__ void ldsm_x2(uint32_t (&r)[2], uint32_t addr) {
    asm volatile("ldmatrix.sync.aligned.m8n8.x2.shared.b16 {%0,%1}, [%2];"
                 : "=r"(r[0]), "=r"(r[1]) : "r"(addr));
}
__device__ __forceinline__ void mma_bf16(float (&d)[4], const uint32_t (&a)[4],
                                         const uint32_t (&b)[2]) {
    asm volatile("mma.sync.aligned.m16n8k16.row.col.f32.bf16.bf16.f32 "
                 "{%0,%1,%2,%3}, {%4,%5,%6,%7}, {%8,%9}, {%0,%1,%2,%3};"
                 : "+f"(d[0]), "+f"(d[1]), "+f"(d[2]), "+f"(d[3])
                 : "r"(a[0]), "r"(a[1]), "r"(a[2]), "r"(a[3]),
                   "r"(b[0]), "r"(b[1]));
}

__device__ __forceinline__ void edge_endpoints(const int* __restrict__ ei, int e,
                                               int& src, int& dst) {
    if (e < NEDGES) { src = ei[e]; dst = ei[NEDGES + e]; }
    else            { src = e - NEDGES; dst = src; }
}

// ---------------- CSR build -------------------------------------------------
__global__ void zero_int_kernel(int* p, int n) {
    int i = blockIdx.x * blockDim.x + threadIdx.x;
    if (i < n) p[i] = 0;
}

__global__ void deg_kernel(const int* __restrict__ ei, int* __restrict__ deg) {
    int t = blockIdx.x * blockDim.x + threadIdx.x;
    if (t >= ETOT) return;
    int dst = (t < NEDGES) ? ei[NEDGES + t] : t - NEDGES;
    atomicAdd(&deg[dst], 1);
}

// single-block exclusive scan over NNODES elements
__global__ void scan_kernel(const int* __restrict__ deg,
                            int* __restrict__ rowptr,
                            int* __restrict__ cursor) {
    __shared__ int sdata[1024];
    __shared__ int soff;
    int tid = threadIdx.x;
    if (tid == 0) soff = 0;
    __syncthreads();
    for (int base = 0; base < NNODES; base += 1024) {
        int i = base + tid;
        int v = (i < NNODES) ? deg[i] : 0;
        sdata[tid] = v;
        __syncthreads();
        for (int d = 1; d < 1024; d <<= 1) {
            int t = (tid >= d) ? sdata[tid - d] : 0;
            __syncthreads();
            sdata[tid] += t;
            __syncthreads();
        }
        int excl = soff + sdata[tid] - v;
        if (i < NNODES) { rowptr[i] = excl; cursor[i] = excl; }
        __syncthreads();
        if (tid == 0) soff += sdata[1023];
        __syncthreads();
    }
    if (tid == 0) rowptr[NNODES] = soff;
}

__global__ void scatter_kernel(const int* __restrict__ ei,
                               int* __restrict__ cursor,
                               int2* __restrict__ csr) {
    int t = blockIdx.x * blockDim.x + threadIdx.x;
    if (t >= ETOT) return;
    int src, dst;
    edge_endpoints(ei, t, src, dst);
    int pos = atomicAdd(&cursor[dst], 1);
    csr[pos] = make_int2(src, t);
}

// ---------------- bf16 split kernels ---------------------------------------
__global__ void xsplit_kernel(const float* __restrict__ X, int n,
                              __nv_bfloat16* __restrict__ Xh,
                              __nv_bfloat16* __restrict__ Xl) {
    int i = blockIdx.x * blockDim.x + threadIdx.x;
    if (i >= n) return;
    float v = X[i];
    __nv_bfloat16 h = __float2bfloat16(v);
    Xh[i] = h;
    Xl[i] = __float2bfloat16(v - __bfloat162float(h));
}

// Transpose [K, 256] fp32 weight into [256, K] bf16 hi/lo (K contiguous)
__global__ void wsplit_kernel(const float* __restrict__ W, int K,
                              __nv_bfloat16* __restrict__ Wh,
                              __nv_bfloat16* __restrict__ Wl) {
    int i = blockIdx.x * blockDim.x + threadIdx.x;
    if (i >= HCDIM * K) return;
    int n = i / K, k = i - n * K;
    float v = W[(size_t)k * HCDIM + n];
    __nv_bfloat16 h = __float2bfloat16(v);
    Wh[i] = h;
    Wl[i] = __float2bfloat16(v - __bfloat162float(h));
}

// ---------------- HMMA dual GEMM (unchanged from R5) ------------------------
#define GSTAGE 32768
#define GSMEM  (2 * GSTAGE)

__global__ void __launch_bounds__(256, 1)
hmma_dual_gemm(const __nv_bfloat16* __restrict__ Ah,
               const __nv_bfloat16* __restrict__ Al,
               const __nv_bfloat16* __restrict__ Bh,
               const __nv_bfloat16* __restrict__ Bl,
               float* __restrict__ C, int M, int K) {
    extern __shared__ char smem[];
    uint32_t sb = smem_to_u32(smem);
    int tid = threadIdx.x;
    int lane = tid & 31, wid = tid >> 5;
    int wm = wid >> 2, wn = wid & 3;
    int mBase = blockIdx.y * 128;
    int nBase = blockIdx.x * 128;
    int nq = K >> 5;

    float acc[4][4][4];
#pragma unroll
    for (int a = 0; a < 4; a++)
#pragma unroll
        for (int b = 0; b < 4; b++)
#pragma unroll
            for (int c = 0; c < 4; c++) acc[a][b][c] = 0.f;

    auto load_stage = [&](int q, int s) {
        int k0 = q << 5;
        uint32_t base = sb + s * GSTAGE;
        char* sm = smem + s * GSTAGE;
#pragma unroll
        for (int it = 0; it < 2; it++) {
            int idx = tid + it * 256;
            int r = idx >> 2, c = idx & 3;
            uint32_t dsw = r * 64 + ((c ^ (r & 3)) << 4);
            int R = mBase + r;
            if (R < M) {
                const char* sh = (const char*)(Ah + (size_t)R * K + k0) + c * 16;
                const char* sl = (const char*)(Al + (size_t)R * K + k0) + c * 16;
                cp_async16(base + dsw, sh);
                cp_async16(base + 8192 + dsw, sl);
            } else {
                uint4 z = make_uint4(0, 0, 0, 0);
                *(uint4*)(sm + dsw) = z;
                *(uint4*)(sm + 8192 + dsw) = z;
            }
        }
#pragma unroll
        for (int it = 0; it < 2; it++) {
            int idx = tid + it * 256;
            int r = idx >> 2, c = idx & 3;
            uint32_t dsw = r * 64 + ((c ^ (r & 3)) << 4);
            int NR = nBase + r;
            const char* sh = (const char*)(Bh + (size_t)NR * K + k0) + c * 16;
            const char* sl = (const char*)(Bl + (size_t)NR * K + k0) + c * 16;
            cp_async16(base + 16384 + dsw, sh);
            cp_async16(base + 24576 + dsw, sl);
        }
    };

    load_stage(0, 0); CP_COMMIT();

    for (int q = 0; q < nq; q++) {
        if (q + 1 < nq) {
            load_stage(q + 1, (q + 1) & 1); CP_COMMIT();
            CP_WAIT(1);
        } else {
            CP_WAIT(0);
        }
        __syncthreads();
        uint32_t base = sb + (q & 1) * GSTAGE;

#pragma unroll
        for (int step = 0; step < 2; step++) {
            uint32_t ahf[4][4], alf[4][4], bhf[4][2], blf[4][2];
            int arow = wm * 64 + (lane & 15);
            int ac = 2 * step + (lane >> 4);
#pragma unroll
            for (int mi = 0; mi < 4; mi++) {
                int r = arow + mi * 16;
                uint32_t ad = base + r * 64 + ((ac ^ (r & 3)) << 4);
                ldsm_x4(ahf[mi], ad);
                ldsm_x4(alf[mi], ad + 8192);
            }
#pragma unroll
            for (int nj = 0; nj < 4; nj++) {
                int r = wn * 32 + nj * 8 + (lane & 7);
                int bc = 2 * step + ((lane >> 3) & 1);
                uint32_t bd = base + 16384 + r * 64 + ((bc ^ (r & 3)) << 4);
                ldsm_x2(bhf[nj], bd);
                ldsm_x2(blf[nj], bd + 8192);
            }
#pragma unroll
            for (int mi = 0; mi < 4; mi++)
#pragma unroll
                for (int nj = 0; nj < 4; nj++) {
                    mma_bf16(acc[mi][nj], ahf[mi], bhf[nj]);
                    mma_bf16(acc[mi][nj], ahf[mi], blf[nj]);
                    mma_bf16(acc[mi][nj], alf[mi], bhf[nj]);
                }
        }
        __syncthreads();
    }

    int rBase = mBase + wm * 64;
    int cBase = nBase + wn * 32;
#pragma unroll
    for (int mi = 0; mi < 4; mi++) {
        int r0 = rBase + mi * 16 + (lane >> 2);
#pragma unroll
        for (int nj = 0; nj < 4; nj++) {
            int cc = cBase + nj * 8 + 2 * (lane & 3);
            if (r0 < M)
                *(float2*)(C + (size_t)r0 * NOUT + cc) =
                    make_float2(acc[mi][nj][0], acc[mi][nj][1]);
            if (r0 + 8 < M)
                *(float2*)(C + (size_t)(r0 + 8) * NOUT + cc) =
                    make_float2(acc[mi][nj][2], acc[mi][nj][3]);
        }
    }
}

// ---------------- edge scores (layers 0/1): warp per edge, all 4 heads -----
__global__ void edge_es_kernel(const int* __restrict__ ei,
                               const float* __restrict__ xlr,
                               const float* __restrict__ att,
                               float* __restrict__ ebuf) {
    int w = (blockIdx.x * blockDim.x + threadIdx.x) >> 5;
    int lane = threadIdx.x & 31;
    if (w >= ETOT) return;
    int src, dst;
    edge_endpoints(ei, w, src, dst);
    const float4* pl = (const float4*)(xlr + (size_t)src * NOUT);
    const float4* pr = (const float4*)(xlr + (size_t)dst * NOUT + 256);
    const float4* pa = (const float4*)att;
    float s = 0.f;
#pragma unroll
    for (int i = 0; i < 2; i++) {
        float4 l = pl[lane * 2 + i], r = pr[lane * 2 + i], a = pa[lane * 2 + i];
        float mv;
        mv = l.x + r.x; mv = mv > 0.f ? mv : 0.2f * mv; s += mv * a.x;
        mv = l.y + r.y; mv = mv > 0.f ? mv : 0.2f * mv; s += mv * a.y;
        mv = l.z + r.z; mv = mv > 0.f ? mv : 0.2f * mv; s += mv * a.z;
        mv = l.w + r.w; mv = mv > 0.f ? mv : 0.2f * mv; s += mv * a.w;
    }
    // reduce within 8-lane group (one head per group)
    s += __shfl_xor_sync(0xFFFFFFFFu, s, 1);
    s += __shfl_xor_sync(0xFFFFFFFFu, s, 2);
    s += __shfl_xor_sync(0xFFFFFFFFu, s, 4);
    float exv = expf(s);
    float e0 = __shfl_sync(0xFFFFFFFFu, exv, 0);
    float e1 = __shfl_sync(0xFFFFFFFFu, exv, 8);
    float e2 = __shfl_sync(0xFFFFFFFFu, exv, 16);
    float e3 = __shfl_sync(0xFFFFFFFFu, exv, 24);
    if (lane == 0)
        *(float4*)(ebuf + (size_t)w * 4) = make_float4(e0, e1, e2, e3);
}

// ---------------- CSR aggregation + epilogue (layers 0/1) -------------------
// Warp per node; lane owns 8 channels (head = lane/8).
// out = (sum_e exv*xl[src]) / (sum_e exv + 1e-16); then +b, BN, ELU, split.
__global__ void node_agg_kernel(const int* __restrict__ rowptr,
                                const int2* __restrict__ csr,
                                const float* __restrict__ ebuf,
                                const float* __restrict__ xlr,
                                const float* __restrict__ b,
                                const float* __restrict__ g,
                                const float* __restrict__ be,
                                const float* __restrict__ m,
                                const float* __restrict__ v,
                                float* __restrict__ hout,
                                __nv_bfloat16* __restrict__ outh,
                                __nv_bfloat16* __restrict__ outl) {
    int w = (blockIdx.x * blockDim.x + threadIdx.x) >> 5;
    int lane = threadIdx.x & 31;
    if (w >= NNODES) return;
    int p0 = rowptr[w], p1 = rowptr[w + 1];
    int headOff = lane >> 3;
    float4 accA = make_float4(0.f, 0.f, 0.f, 0.f);
    float4 accB = make_float4(0.f, 0.f, 0.f, 0.f);
    float dsum = 0.f;

    for (int base = p0; base < p1; base += 32) {
        int2 se = make_int2(0, 0);
        if (base + lane < p1) se = csr[base + lane];
        int cnt = min(32, p1 - base);
        for (int j = 0; j < cnt; j++) {
            int src = __shfl_sync(0xFFFFFFFFu, se.x, j);
            int eid = __shfl_sync(0xFFFFFFFFu, se.y, j);
            float ex = ebuf[(size_t)eid * 4 + headOff];
            const float4* row = (const float4*)(xlr + (size_t)src * NOUT);
            float4 vA = row[lane * 2];
            float4 vB = row[lane * 2 + 1];
            accA.x += ex * vA.x; accA.y += ex * vA.y;
            accA.z += ex * vA.z; accA.w += ex * vA.w;
            accB.x += ex * vB.x; accB.y += ex * vB.y;
            accB.z += ex * vB.z; accB.w += ex * vB.w;
            dsum += ex;
        }
    }
    float inv = 1.f / (dsum + 1e-16f);
    int col = lane * 8;

    float4 bA = *(const float4*)(b + col),  bB = *(const float4*)(b + col + 4);
    float4 gA = *(const float4*)(g + col),  gB = *(const float4*)(g + col + 4);
    float4 eA = *(const float4*)(be + col), eB = *(const float4*)(be + col + 4);
    float4 mA = *(const float4*)(m + col),  mB = *(const float4*)(m + col + 4);
    float4 vA = *(const float4*)(v + col),  vB = *(const float4*)(v + col + 4);

    float o[8];
    o[0] = accA.x * inv + bA.x; o[1] = accA.y * inv + bA.y;
    o[2] = accA.z * inv + bA.z; o[3] = accA.w * inv + bA.w;
    o[4] = accB.x * inv + bB.x; o[5] = accB.y * inv + bB.y;
    o[6] = accB.z * inv + bB.z; o[7] = accB.w * inv + bB.w;
    float gg[8] = {gA.x, gA.y, gA.z, gA.w, gB.x, gB.y, gB.z, gB.w};
    float ee[8] = {eA.x, eA.y, eA.z, eA.w, eB.x, eB.y, eB.z, eB.w};
    float mm[8] = {mA.x, mA.y, mA.z, mA.w, mB.x, mB.y, mB.z, mB.w};
    float vv[8] = {vA.x, vA.y, vA.z, vA.w, vB.x, vB.y, vB.z, vB.w};

    union { uint4 u; __nv_bfloat162 p[4]; } ph, pl;
#pragma unroll
    for (int i = 0; i < 8; i++) {
        float x = (o[i] - mm[i]) * (gg[i] * rsqrtf(vv[i] + EPS_BN)) + ee[i];
        x = x > 0.f ? x : (expf(x) - 1.0f);
        o[i] = x;
    }
    *(float4*)(hout + (size_t)w * HCDIM + col) = make_float4(o[0], o[1], o[2], o[3]);
    *(float4*)(hout + (size_t)w * HCDIM + col + 4) = make_float4(o[4], o[5], o[6], o[7]);
#pragma unroll
    for (int i = 0; i < 4; i++) {
        __nv_bfloat16 h0 = __float2bfloat16(o[2 * i]);
        __nv_bfloat16 h1 = __float2bfloat16(o[2 * i + 1]);
        ph.p[i] = __nv_bfloat162(h0, h1);
        pl.p[i] = __nv_bfloat162(
            __float2bfloat16(o[2 * i] - __bfloat162float(h0)),
            __float2bfloat16(o[2 * i + 1] - __bfloat162float(h1)));
    }
    *(uint4*)(outh + (size_t)w * HCDIM + col) = ph.u;
    *(uint4*)(outl + (size_t)w * HCDIM + col) = pl.u;
}

// ---------------- layer 2 (HC=256 -> 2, single head) -----------------------
__global__ void gemm2_kernel(const float* __restrict__ h,
                             const float* __restrict__ Wl,
                             const float* __restrict__ Wr,
                             float* __restrict__ xl2,
                             float* __restrict__ xr2) {
    int w = (blockIdx.x * blockDim.x + threadIdx.x) >> 5;
    int lane = threadIdx.x & 31;
    if (w >= NNODES) return;
    float al0 = 0.f, al1 = 0.f, ar0 = 0.f, ar1 = 0.f;
    const float* hp = h + (long)w * HCDIM;
#pragma unroll
    for (int k = lane; k < HCDIM; k += 32) {
        float hv = hp[k];
        float2 wl = *(const float2*)(Wl + k * 2);
        float2 wr = *(const float2*)(Wr + k * 2);
        al0 += hv * wl.x; al1 += hv * wl.y;
        ar0 += hv * wr.x; ar1 += hv * wr.y;
    }
#pragma unroll
    for (int off = 16; off; off >>= 1) {
        al0 += __shfl_xor_sync(0xFFFFFFFFu, al0, off);
        al1 += __shfl_xor_sync(0xFFFFFFFFu, al1, off);
        ar0 += __shfl_xor_sync(0xFFFFFFFFu, ar0, off);
        ar1 += __shfl_xor_sync(0xFFFFFFFFu, ar1, off);
    }
    if (lane == 0) {
        xl2[w * 2 + 0] = al0; xl2[w * 2 + 1] = al1;
        xr2[w * 2 + 0] = ar0; xr2[w * 2 + 1] = ar1;
    }
}

// Fused: scores + softmax-agg + bias + log_softmax. Warp per node, lane/edge.
__global__ void node_gat2_kernel(const int* __restrict__ rowptr,
                                 const int2* __restrict__ csr,
                                 const float* __restrict__ xl2,
                                 const float* __restrict__ xr2,
                                 const float* __restrict__ att2,
                                 const float* __restrict__ b2,
                                 float* __restrict__ out) {
    int w = (blockIdx.x * blockDim.x + threadIdx.x) >> 5;
    int lane = threadIdx.x & 31;
    if (w >= NNODES) return;
    int p0 = rowptr[w], p1 = rowptr[w + 1];
    float2 r = *(const float2*)(xr2 + w * 2);
    float a0 = att2[0], a1 = att2[1];
    float s0 = 0.f, s1 = 0.f, ds = 0.f;
    for (int p = p0 + lane; p < p1; p += 32) {
        int src = csr[p].x;
        float2 l = *(const float2*)(xl2 + src * 2);
        float mx = l.x + r.x, my = l.y + r.y;
        mx = mx > 0.f ? mx : 0.2f * mx;
        my = my > 0.f ? my : 0.2f * my;
        float ex = expf(mx * a0 + my * a1);
        s0 += ex * l.x; s1 += ex * l.y; ds += ex;
    }
#pragma unroll
    for (int off = 16; off; off >>= 1) {
        s0 += __shfl_xor_sync(0xFFFFFFFFu, s0, off);
        s1 += __shfl_xor_sync(0xFFFFFFFFu, s1, off);
        ds += __shfl_xor_sync(0xFFFFFFFFu, ds, off);
    }
    if (lane == 0) {
        float inv = 1.f / (ds + 1e-16f);
        float o0 = s0 * inv + b2[0];
        float o1 = s1 * inv + b2[1];
        float mx = fmaxf(o0, o1);
        float lse = mx + logf(expf(o0 - mx) + expf(o1 - mx));
        *(float2*)(out + w * 2) = make_float2(o0 - lse, o1 - lse);
    }
}

// ---------------- launch ---------------------------------------------------
extern "C" void kernel_launch(void* const* d_in, const int* in_sizes, int n_in,
                              void* d_out, int out_size) {
    const float* x   = (const float*)d_in[0];
    const int*   ei  = (const int*)d_in[1];
    const float* Wl0 = (const float*)d_in[2];
    const float* Wr0 = (const float*)d_in[3];
    const float* att0= (const float*)d_in[4];
    const float* b0  = (const float*)d_in[5];
    const float* g0  = (const float*)d_in[6];
    const float* be0 = (const float*)d_in[7];
    const float* m0  = (const float*)d_in[8];
    const float* v0  = (const float*)d_in[9];
    const float* Wl1 = (const float*)d_in[10];
    const float* Wr1 = (const float*)d_in[11];
    const float* att1= (const float*)d_in[12];
    const float* b1  = (const float*)d_in[13];
    const float* g1  = (const float*)d_in[14];
    const float* be1 = (const float*)d_in[15];
    const float* m1  = (const float*)d_in[16];
    const float* v1  = (const float*)d_in[17];
    const float* Wl2 = (const float*)d_in[18];
    const float* Wr2 = (const float*)d_in[19];
    const float* att2= (const float*)d_in[20];
    const float* b2  = (const float*)d_in[21];
    float* out = (float*)d_out;

    float *p_xlr, *p_h, *p_e, *p_xl2, *p_xr2;
    int *p_deg, *p_cursor, *p_rowptr;
    int2* p_csr;
    __nv_bfloat16 *p_xhi, *p_xlo, *p_hhi, *p_hlo;
    __nv_bfloat16 *p_w0h, *p_w0l, *p_w1h, *p_w1l;
    cudaGetSymbolAddress((void**)&p_xlr, g_xlr);
    cudaGetSymbolAddress((void**)&p_h, g_h);
    cudaGetSymbolAddress((void**)&p_e, g_e);
    cudaGetSymbolAddress((void**)&p_xl2, g_xl2);
    cudaGetSymbolAddress((void**)&p_xr2, g_xr2);
    cudaGetSymbolAddress((void**)&p_deg, g_deg);
    cudaGetSymbolAddress((void**)&p_cursor, g_cursor);
    cudaGetSymbolAddress((void**)&p_rowptr, g_rowptr);
    cudaGetSymbolAddress((void**)&p_csr, g_csr);
    cudaGetSymbolAddress((void**)&p_xhi, g_xhi);
    cudaGetSymbolAddress((void**)&p_xlo, g_xlo);
    cudaGetSymbolAddress((void**)&p_hhi, g_hhi);
    cudaGetSymbolAddress((void**)&p_hlo, g_hlo);
    cudaGetSymbolAddress((void**)&p_w0h, g_w0h);
    cudaGetSymbolAddress((void**)&p_w0l, g_w0l);
    cudaGetSymbolAddress((void**)&p_w1h, g_w1h);
    cudaGetSymbolAddress((void**)&p_w1l, g_w1l);

    cudaFuncSetAttribute(hmma_dual_gemm,
                         cudaFuncAttributeMaxDynamicSharedMemorySize, GSMEM);

    int eBlocks = (ETOT + 255) / 256;
    int edgeWarpBlocks = (ETOT * 32 + 255) / 256;
    int nodeWarpBlocks = (NNODES * 32 + 255) / 256;
    dim3 gemmGrid(NOUT / 128, (NNODES + 127) / 128);

    // ===== prep: bf16 splits + CSR build =====
    xsplit_kernel<<<(NNODES * INDIM + 255) / 256, 256>>>(x, NNODES * INDIM, p_xhi, p_xlo);
    wsplit_kernel<<<(HCDIM * INDIM + 255) / 256, 256>>>(Wl0, INDIM, p_w0h, p_w0l);
    wsplit_kernel<<<(HCDIM * INDIM + 255) / 256, 256>>>(Wr0, INDIM,
                                                        p_w0h + 256 * INDIM, p_w0l + 256 * INDIM);
    wsplit_kernel<<<(HCDIM * HCDIM + 255) / 256, 256>>>(Wl1, HCDIM, p_w1h, p_w1l);
    wsplit_kernel<<<(HCDIM * HCDIM + 255) / 256, 256>>>(Wr1, HCDIM,
                                                        p_w1h + 256 * HCDIM, p_w1l + 256 * HCDIM);
    zero_int_kernel<<<(NNODES + 255) / 256, 256>>>(p_deg, NNODES);
    deg_kernel<<<eBlocks, 256>>>(ei, p_deg);
    scan_kernel<<<1, 1024>>>(p_deg, p_rowptr, p_cursor);
    scatter_kernel<<<eBlocks, 256>>>(ei, p_cursor, p_csr);

    // ===== Layer 0 =====
    hmma_dual_gemm<<<gemmGrid, 256, GSMEM>>>(p_xhi, p_xlo, p_w0h, p_w0l,
                                             p_xlr, NNODES, INDIM);
    edge_es_kernel<<<edgeWarpBlocks, 256>>>(ei, p_xlr, att0, p_e);
    node_agg_kernel<<<nodeWarpBlocks, 256>>>(p_rowptr, p_csr, p_e, p_xlr,
                                             b0, g0, be0, m0, v0,
                                             p_h, p_hhi, p_hlo);

    // ===== Layer 1 =====
    hmma_dual_gemm<<<gemmGrid, 256, GSMEM>>>(p_hhi, p_hlo, p_w1h, p_w1l,
                                             p_xlr, NNODES, HCDIM);
    edge_es_kernel<<<edgeWarpBlocks, 256>>>(ei, p_xlr, att1, p_e);
    node_agg_kernel<<<nodeWarpBlocks, 256>>>(p_rowptr, p_csr, p_e, p_xlr,
                                             b1, g1, be1, m1, v1,
                                             p_h, p_hhi, p_hlo);

    // ===== Layer 2 =====
    gemm2_kernel<<<nodeWarpBlocks, 256>>>(p_h, Wl2, Wr2, p_xl2, p_xr2);
    node_gat2_kernel<<<nodeWarpBlocks, 256>>>(p_rowptr, p_csr, p_xl2, p_xr2,
                                              att2, b2, out);
}

// round 7
// speedup vs baseline: 2.9503x; 1.2751x over previous
#include <cuda_runtime.h>
#include <cuda_bf16.h>
#include <math.h>
#include <stdint.h>

// Problem constants (fixed by reference)
#define NNODES 20000
#define NEDGES 320000
#define ETOT   340000   // NEDGES + NNODES self loops
#define INDIM  512
#define NHEAD  4
#define CDIM   64
#define HCDIM  256
#define NOUT   512      // dual-GEMM output width (xl | xr)
#define EPS_BN 1e-5f

// ---------------- scratch (device globals; no allocation allowed) ----------
__device__ float g_xlr[NNODES * NOUT];   // cols 0-255: xl, 256-511: xr
__device__ float g_h[NNODES * HCDIM];
__device__ float g_xl2[NNODES * 2];
__device__ float g_xr2[NNODES * 2];

// CSR by destination (src only)
__device__ int g_deg[NNODES];
__device__ int g_cursor[NNODES];
__device__ int g_rowptr[NNODES + 1];
__device__ int g_csr[ETOT];

// bf16 hi/lo split buffers for tensor-core GEMMs
__device__ __nv_bfloat16 g_xhi[NNODES * INDIM];
__device__ __nv_bfloat16 g_xlo[NNODES * INDIM];
__device__ __nv_bfloat16 g_hhi[NNODES * HCDIM];
__device__ __nv_bfloat16 g_hlo[NNODES * HCDIM];
// concatenated, transposed (N-major, K-contiguous) weight splits: [512, K]
__device__ __nv_bfloat16 g_w0h[NOUT * INDIM];
__device__ __nv_bfloat16 g_w0l[NOUT * INDIM];
__device__ __nv_bfloat16 g_w1h[NOUT * HCDIM];
__device__ __nv_bfloat16 g_w1l[NOUT * HCDIM];

// ---------------- PTX helpers ----------------------------------------------
__device__ __forceinline__ uint32_t smem_to_u32(const void* smem_ptr) {
    uint32_t addr;
    asm("{ .reg .u64 tmp; cvta.to.shared.u64 tmp, %1; cvt.u32.u64 %0, tmp; }"
        : "=r"(addr) : "l"(smem_ptr));
    return addr;
}

__device__ __forceinline__ void cp_async16(uint32_t dst, const void* src) {
    asm volatile("cp.async.cg.shared.global [%0], [%1], 16;" :: "r"(dst), "l"(src));
}
#define CP_COMMIT() asm volatile("cp.async.commit_group;" ::: "memory")
#define CP_WAIT(n)  asm volatile("cp.async.wait_group %0;" :: "n"(n) : "memory")

__device__ __forceinline__ void ldsm_x4(uint32_t (&r)[4], uint32_t addr) {
    asm volatile("ldmatrix.sync.aligned.m8n8.x4.shared.b16 {%0,%1,%2,%3}, [%4];"
                 : "=r"(r[0]), "=r"(r[1]), "=r"(r[2]), "=r"(r[3]) : "r"(addr));
}
__device__ __forceinline__ void ldsm_x2(uint32_t (&r)[2], uint32_t addr) {
    asm volatile("ldmatrix.sync.aligned.m8n8.x2.shared.b16 {%0,%1}, [%2];"
                 : "=r"(r[0]), "=r"(r[1]) : "r"(addr));
}
__device__ __forceinline__ void mma_bf16(float (&d)[4], const uint32_t (&a)[4],
                                         const uint32_t (&b)[2]) {
    asm volatile("mma.sync.aligned.m16n8k16.row.col.f32.bf16.bf16.f32 "
                 "{%0,%1,%2,%3}, {%4,%5,%6,%7}, {%8,%9}, {%0,%1,%2,%3};"
                 : "+f"(d[0]), "+f"(d[1]), "+f"(d[2]), "+f"(d[3])
                 : "r"(a[0]), "r"(a[1]), "r"(a[2]), "r"(a[3]),
                   "r"(b[0]), "r"(b[1]));
}

__device__ __forceinline__ void edge_endpoints(const int* __restrict__ ei, int e,
                                               int& src, int& dst) {
    if (e < NEDGES) { src = ei[e]; dst = ei[NEDGES + e]; }
    else            { src = e - NEDGES; dst = src; }
}

// ---------------- CSR build -------------------------------------------------
__global__ void zero_int_kernel(int* p, int n) {
    int i = blockIdx.x * blockDim.x + threadIdx.x;
    if (i < n) p[i] = 0;
}

__global__ void deg_kernel(const int* __restrict__ ei, int* __restrict__ deg) {
    int t = blockIdx.x * blockDim.x + threadIdx.x;
    if (t >= ETOT) return;
    int dst = (t < NEDGES) ? ei[NEDGES + t] : t - NEDGES;
    atomicAdd(&deg[dst], 1);
}

// single-block exclusive scan over NNODES elements
__global__ void scan_kernel(const int* __restrict__ deg,
                            int* __restrict__ rowptr,
                            int* __restrict__ cursor) {
    __shared__ int sdata[1024];
    __shared__ int soff;
    int tid = threadIdx.x;
    if (tid == 0) soff = 0;
    __syncthreads();
    for (int base = 0; base < NNODES; base += 1024) {
        int i = base + tid;
        int v = (i < NNODES) ? deg[i] : 0;
        sdata[tid] = v;
        __syncthreads();
        for (int d = 1; d < 1024; d <<= 1) {
            int t = (tid >= d) ? sdata[tid - d] : 0;
            __syncthreads();
            sdata[tid] += t;
            __syncthreads();
        }
        int excl = soff + sdata[tid] - v;
        if (i < NNODES) { rowptr[i] = excl; cursor[i] = excl; }
        __syncthreads();
        if (tid == 0) soff += sdata[1023];
        __syncthreads();
    }
    if (tid == 0) rowptr[NNODES] = soff;
}

__global__ void scatter_kernel(const int* __restrict__ ei,
                               int* __restrict__ cursor,
                               int* __restrict__ csr) {
    int t = blockIdx.x * blockDim.x + threadIdx.x;
    if (t >= ETOT) return;
    int src, dst;
    edge_endpoints(ei, t, src, dst);
    int pos = atomicAdd(&cursor[dst], 1);
    csr[pos] = src;
}

// ---------------- bf16 split kernels ---------------------------------------
__global__ void xsplit_kernel(const float* __restrict__ X, int n,
                              __nv_bfloat16* __restrict__ Xh,
                              __nv_bfloat16* __restrict__ Xl) {
    int i = blockIdx.x * blockDim.x + threadIdx.x;
    if (i >= n) return;
    float v = X[i];
    __nv_bfloat16 h = __float2bfloat16(v);
    Xh[i] = h;
    Xl[i] = __float2bfloat16(v - __bfloat162float(h));
}

// Transpose [K, 256] fp32 weight into [256, K] bf16 hi/lo (K contiguous)
__global__ void wsplit_kernel(const float* __restrict__ W, int K,
                              __nv_bfloat16* __restrict__ Wh,
                              __nv_bfloat16* __restrict__ Wl) {
    int i = blockIdx.x * blockDim.x + threadIdx.x;
    if (i >= HCDIM * K) return;
    int n = i / K, k = i - n * K;
    float v = W[(size_t)k * HCDIM + n];
    __nv_bfloat16 h = __float2bfloat16(v);
    Wh[i] = h;
    Wl[i] = __float2bfloat16(v - __bfloat162float(h));
}

// ---------------- HMMA dual GEMM --------------------------------------------
#define GSTAGE 32768
#define GSMEM  (2 * GSTAGE)

__global__ void __launch_bounds__(256, 1)
hmma_dual_gemm(const __nv_bfloat16* __restrict__ Ah,
               const __nv_bfloat16* __restrict__ Al,
               const __nv_bfloat16* __restrict__ Bh,
               const __nv_bfloat16* __restrict__ Bl,
               float* __restrict__ C, int M, int K) {
    extern __shared__ char smem[];
    uint32_t sb = smem_to_u32(smem);
    int tid = threadIdx.x;
    int lane = tid & 31, wid = tid >> 5;
    int wm = wid >> 2, wn = wid & 3;
    int mBase = blockIdx.y * 128;
    int nBase = blockIdx.x * 128;
    int nq = K >> 5;

    float acc[4][4][4];
#pragma unroll
    for (int a = 0; a < 4; a++)
#pragma unroll
        for (int b = 0; b < 4; b++)
#pragma unroll
            for (int c = 0; c < 4; c++) acc[a][b][c] = 0.f;

    auto load_stage = [&](int q, int s) {
        int k0 = q << 5;
        uint32_t base = sb + s * GSTAGE;
        char* sm = smem + s * GSTAGE;
#pragma unroll
        for (int it = 0; it < 2; it++) {
            int idx = tid + it * 256;
            int r = idx >> 2, c = idx & 3;
            uint32_t dsw = r * 64 + ((c ^ (r & 3)) << 4);
            int R = mBase + r;
            if (R < M) {
                const char* sh = (const char*)(Ah + (size_t)R * K + k0) + c * 16;
                const char* sl = (const char*)(Al + (size_t)R * K + k0) + c * 16;
                cp_async16(base + dsw, sh);
                cp_async16(base + 8192 + dsw, sl);
            } else {
                uint4 z = make_uint4(0, 0, 0, 0);
                *(uint4*)(sm + dsw) = z;
                *(uint4*)(sm + 8192 + dsw) = z;
            }
        }
#pragma unroll
        for (int it = 0; it < 2; it++) {
            int idx = tid + it * 256;
            int r = idx >> 2, c = idx & 3;
            uint32_t dsw = r * 64 + ((c ^ (r & 3)) << 4);
            int NR = nBase + r;
            const char* sh = (const char*)(Bh + (size_t)NR * K + k0) + c * 16;
            const char* sl = (const char*)(Bl + (size_t)NR * K + k0) + c * 16;
            cp_async16(base + 16384 + dsw, sh);
            cp_async16(base + 24576 + dsw, sl);
        }
    };

    load_stage(0, 0); CP_COMMIT();

    for (int q = 0; q < nq; q++) {
        if (q + 1 < nq) {
            load_stage(q + 1, (q + 1) & 1); CP_COMMIT();
            CP_WAIT(1);
        } else {
            CP_WAIT(0);
        }
        __syncthreads();
        uint32_t base = sb + (q & 1) * GSTAGE;

#pragma unroll
        for (int step = 0; step < 2; step++) {
            uint32_t ahf[4][4], alf[4][4], bhf[4][2], blf[4][2];
            int arow = wm * 64 + (lane & 15);
            int ac = 2 * step + (lane >> 4);
#pragma unroll
            for (int mi = 0; mi < 4; mi++) {
                int r = arow + mi * 16;
                uint32_t ad = base + r * 64 + ((ac ^ (r & 3)) << 4);
                ldsm_x4(ahf[mi], ad);
                ldsm_x4(alf[mi], ad + 8192);
            }
#pragma unroll
            for (int nj = 0; nj < 4; nj++) {
                int r = wn * 32 + nj * 8 + (lane & 7);
                int bc = 2 * step + ((lane >> 3) & 1);
                uint32_t bd = base + 16384 + r * 64 + ((bc ^ (r & 3)) << 4);
                ldsm_x2(bhf[nj], bd);
                ldsm_x2(blf[nj], bd + 8192);
            }
#pragma unroll
            for (int mi = 0; mi < 4; mi++)
#pragma unroll
                for (int nj = 0; nj < 4; nj++) {
                    mma_bf16(acc[mi][nj], ahf[mi], bhf[nj]);
                    mma_bf16(acc[mi][nj], ahf[mi], blf[nj]);
                    mma_bf16(acc[mi][nj], alf[mi], bhf[nj]);
                }
        }
        __syncthreads();
    }

    int rBase = mBase + wm * 64;
    int cBase = nBase + wn * 32;
#pragma unroll
    for (int mi = 0; mi < 4; mi++) {
        int r0 = rBase + mi * 16 + (lane >> 2);
#pragma unroll
        for (int nj = 0; nj < 4; nj++) {
            int cc = cBase + nj * 8 + 2 * (lane & 3);
            if (r0 < M)
                *(float2*)(C + (size_t)r0 * NOUT + cc) =
                    make_float2(acc[mi][nj][0], acc[mi][nj][1]);
            if (r0 + 8 < M)
                *(float2*)(C + (size_t)(r0 + 8) * NOUT + cc) =
                    make_float2(acc[mi][nj][2], acc[mi][nj][3]);
        }
    }
}

// ---------------- fused GATv2 layer (score + softmax-agg + BN + ELU) --------
// Warp per node; lane owns 8 channels (head = lane/8). Per gathered edge:
// score from in-register xr/att + loaded xl row; 8-lane-group reduce; exp;
// weighted accumulate + denom — single pass, no edge buffers, no atomics.
__global__ void node_gat_kernel(const int* __restrict__ rowptr,
                                const int* __restrict__ csr,
                                const float* __restrict__ xlr,
                                const float* __restrict__ att,
                                const float* __restrict__ b,
                                const float* __restrict__ g,
                                const float* __restrict__ be,
                                const float* __restrict__ m,
                                const float* __restrict__ v,
                                float* __restrict__ hout,
                                __nv_bfloat16* __restrict__ outh,
                                __nv_bfloat16* __restrict__ outl) {
    int w = (blockIdx.x * blockDim.x + threadIdx.x) >> 5;
    int lane = threadIdx.x & 31;
    if (w >= NNODES) return;
    int p0 = rowptr[w], p1 = rowptr[w + 1];
    int col = lane * 8;

    // per-lane channel constants: xr[dst] and att
    float4 rA = *(const float4*)(xlr + (size_t)w * NOUT + 256 + col);
    float4 rB = *(const float4*)(xlr + (size_t)w * NOUT + 256 + col + 4);
    float4 aA = *(const float4*)(att + col);
    float4 aB = *(const float4*)(att + col + 4);

    float4 accA = make_float4(0.f, 0.f, 0.f, 0.f);
    float4 accB = make_float4(0.f, 0.f, 0.f, 0.f);
    float dsum = 0.f;

    for (int base = p0; base < p1; base += 32) {
        int se = 0;
        if (base + lane < p1) se = csr[base + lane];
        int cnt = min(32, p1 - base);
        for (int j = 0; j < cnt; j++) {
            int src = __shfl_sync(0xFFFFFFFFu, se, j);
            const float4* row = (const float4*)(xlr + (size_t)src * NOUT);
            float4 vA = row[lane * 2];
            float4 vB = row[lane * 2 + 1];
            // per-lane partial score over its 8 channels
            float s, mv;
            mv = vA.x + rA.x; mv = mv > 0.f ? mv : 0.2f * mv; s  = mv * aA.x;
            mv = vA.y + rA.y; mv = mv > 0.f ? mv : 0.2f * mv; s += mv * aA.y;
            mv = vA.z + rA.z; mv = mv > 0.f ? mv : 0.2f * mv; s += mv * aA.z;
            mv = vA.w + rA.w; mv = mv > 0.f ? mv : 0.2f * mv; s += mv * aA.w;
            mv = vB.x + rB.x; mv = mv > 0.f ? mv : 0.2f * mv; s += mv * aB.x;
            mv = vB.y + rB.y; mv = mv > 0.f ? mv : 0.2f * mv; s += mv * aB.y;
            mv = vB.z + rB.z; mv = mv > 0.f ? mv : 0.2f * mv; s += mv * aB.z;
            mv = vB.w + rB.w; mv = mv > 0.f ? mv : 0.2f * mv; s += mv * aB.w;
            // reduce within 8-lane head group
            s += __shfl_xor_sync(0xFFFFFFFFu, s, 1);
            s += __shfl_xor_sync(0xFFFFFFFFu, s, 2);
            s += __shfl_xor_sync(0xFFFFFFFFu, s, 4);
            float ex = expf(s);
            accA.x += ex * vA.x; accA.y += ex * vA.y;
            accA.z += ex * vA.z; accA.w += ex * vA.w;
            accB.x += ex * vB.x; accB.y += ex * vB.y;
            accB.z += ex * vB.z; accB.w += ex * vB.w;
            dsum += ex;
        }
    }
    float inv = 1.f / (dsum + 1e-16f);

    float4 bA = *(const float4*)(b + col),  bB = *(const float4*)(b + col + 4);
    float4 gA = *(const float4*)(g + col),  gB = *(const float4*)(g + col + 4);
    float4 eA = *(const float4*)(be + col), eB = *(const float4*)(be + col + 4);
    float4 mA = *(const float4*)(m + col),  mB = *(const float4*)(m + col + 4);
    float4 vA = *(const float4*)(v + col),  vB = *(const float4*)(v + col + 4);

    float o[8];
    o[0] = accA.x * inv + bA.x; o[1] = accA.y * inv + bA.y;
    o[2] = accA.z * inv + bA.z; o[3] = accA.w * inv + bA.w;
    o[4] = accB.x * inv + bB.x; o[5] = accB.y * inv + bB.y;
    o[6] = accB.z * inv + bB.z; o[7] = accB.w * inv + bB.w;
    float gg[8] = {gA.x, gA.y, gA.z, gA.w, gB.x, gB.y, gB.z, gB.w};
    float ee[8] = {eA.x, eA.y, eA.z, eA.w, eB.x, eB.y, eB.z, eB.w};
    float mm[8] = {mA.x, mA.y, mA.z, mA.w, mB.x, mB.y, mB.z, mB.w};
    float vv[8] = {vA.x, vA.y, vA.z, vA.w, vB.x, vB.y, vB.z, vB.w};

    union { uint4 u; __nv_bfloat162 p[4]; } ph, pl;
#pragma unroll
    for (int i = 0; i < 8; i++) {
        float x = (o[i] - mm[i]) * (gg[i] * rsqrtf(vv[i] + EPS_BN)) + ee[i];
        x = x > 0.f ? x : (expf(x) - 1.0f);
        o[i] = x;
    }
    *(float4*)(hout + (size_t)w * HCDIM + col) = make_float4(o[0], o[1], o[2], o[3]);
    *(float4*)(hout + (size_t)w * HCDIM + col + 4) = make_float4(o[4], o[5], o[6], o[7]);
#pragma unroll
    for (int i = 0; i < 4; i++) {
        __nv_bfloat16 h0 = __float2bfloat16(o[2 * i]);
        __nv_bfloat16 h1 = __float2bfloat16(o[2 * i + 1]);
        ph.p[i] = __nv_bfloat162(h0, h1);
        pl.p[i] = __nv_bfloat162(
            __float2bfloat16(o[2 * i] - __bfloat162float(h0)),
            __float2bfloat16(o[2 * i + 1] - __bfloat162float(h1)));
    }
    *(uint4*)(outh + (size_t)w * HCDIM + col) = ph.u;
    *(uint4*)(outl + (size_t)w * HCDIM + col) = pl.u;
}

// ---------------- layer 2 (HC=256 -> 2, single head) -----------------------
__global__ void gemm2_kernel(const float* __restrict__ h,
                             const float* __restrict__ Wl,
                             const float* __restrict__ Wr,
                             float* __restrict__ xl2,
                             float* __restrict__ xr2) {
    int w = (blockIdx.x * blockDim.x + threadIdx.x) >> 5;
    int lane = threadIdx.x & 31;
    if (w >= NNODES) return;
    float al0 = 0.f, al1 = 0.f, ar0 = 0.f, ar1 = 0.f;
    const float* hp = h + (long)w * HCDIM;
#pragma unroll
    for (int k = lane; k < HCDIM; k += 32) {
        float hv = hp[k];
        float2 wl = *(const float2*)(Wl + k * 2);
        float2 wr = *(const float2*)(Wr + k * 2);
        al0 += hv * wl.x; al1 += hv * wl.y;
        ar0 += hv * wr.x; ar1 += hv * wr.y;
    }
#pragma unroll
    for (int off = 16; off; off >>= 1) {
        al0 += __shfl_xor_sync(0xFFFFFFFFu, al0, off);
        al1 += __shfl_xor_sync(0xFFFFFFFFu, al1, off);
        ar0 += __shfl_xor_sync(0xFFFFFFFFu, ar0, off);
        ar1 += __shfl_xor_sync(0xFFFFFFFFu, ar1, off);
    }
    if (lane == 0) {
        xl2[w * 2 + 0] = al0; xl2[w * 2 + 1] = al1;
        xr2[w * 2 + 0] = ar0; xr2[w * 2 + 1] = ar1;
    }
}

// Fused: scores + softmax-agg + bias + log_softmax. Warp per node, lane/edge.
__global__ void node_gat2_kernel(const int* __restrict__ rowptr,
                                 const int* __restrict__ csr,
                                 const float* __restrict__ xl2,
                                 const float* __restrict__ xr2,
                                 const float* __restrict__ att2,
                                 const float* __restrict__ b2,
                                 float* __restrict__ out) {
    int w = (blockIdx.x * blockDim.x + threadIdx.x) >> 5;
    int lane = threadIdx.x & 31;
    if (w >= NNODES) return;
    int p0 = rowptr[w], p1 = rowptr[w + 1];
    float2 r = *(const float2*)(xr2 + w * 2);
    float a0 = att2[0], a1 = att2[1];
    float s0 = 0.f, s1 = 0.f, ds = 0.f;
    for (int p = p0 + lane; p < p1; p += 32) {
        int src = csr[p];
        float2 l = *(const float2*)(xl2 + src * 2);
        float mx = l.x + r.x, my = l.y + r.y;
        mx = mx > 0.f ? mx : 0.2f * mx;
        my = my > 0.f ? my : 0.2f * my;
        float ex = expf(mx * a0 + my * a1);
        s0 += ex * l.x; s1 += ex * l.y; ds += ex;
    }
#pragma unroll
    for (int off = 16; off; off >>= 1) {
        s0 += __shfl_xor_sync(0xFFFFFFFFu, s0, off);
        s1 += __shfl_xor_sync(0xFFFFFFFFu, s1, off);
        ds += __shfl_xor_sync(0xFFFFFFFFu, ds, off);
    }
    if (lane == 0) {
        float inv = 1.f / (ds + 1e-16f);
        float o0 = s0 * inv + b2[0];
        float o1 = s1 * inv + b2[1];
        float mx = fmaxf(o0, o1);
        float lse = mx + logf(expf(o0 - mx) + expf(o1 - mx));
        *(float2*)(out + w * 2) = make_float2(o0 - lse, o1 - lse);
    }
}

// ---------------- launch ---------------------------------------------------
extern "C" void kernel_launch(void* const* d_in, const int* in_sizes, int n_in,
                              void* d_out, int out_size) {
    const float* x   = (const float*)d_in[0];
    const int*   ei  = (const int*)d_in[1];
    const float* Wl0 = (const float*)d_in[2];
    const float* Wr0 = (const float*)d_in[3];
    const float* att0= (const float*)d_in[4];
    const float* b0  = (const float*)d_in[5];
    const float* g0  = (const float*)d_in[6];
    const float* be0 = (const float*)d_in[7];
    const float* m0  = (const float*)d_in[8];
    const float* v0  = (const float*)d_in[9];
    const float* Wl1 = (const float*)d_in[10];
    const float* Wr1 = (const float*)d_in[11];
    const float* att1= (const float*)d_in[12];
    const float* b1  = (const float*)d_in[13];
    const float* g1  = (const float*)d_in[14];
    const float* be1 = (const float*)d_in[15];
    const float* m1  = (const float*)d_in[16];
    const float* v1  = (const float*)d_in[17];
    const float* Wl2 = (const float*)d_in[18];
    const float* Wr2 = (const float*)d_in[19];
    const float* att2= (const float*)d_in[20];
    const float* b2  = (const float*)d_in[21];
    float* out = (float*)d_out;

    float *p_xlr, *p_h, *p_xl2, *p_xr2;
    int *p_deg, *p_cursor, *p_rowptr, *p_csr;
    __nv_bfloat16 *p_xhi, *p_xlo, *p_hhi, *p_hlo;
    __nv_bfloat16 *p_w0h, *p_w0l, *p_w1h, *p_w1l;
    cudaGetSymbolAddress((void**)&p_xlr, g_xlr);
    cudaGetSymbolAddress((void**)&p_h, g_h);
    cudaGetSymbolAddress((void**)&p_xl2, g_xl2);
    cudaGetSymbolAddress((void**)&p_xr2, g_xr2);
    cudaGetSymbolAddress((void**)&p_deg, g_deg);
    cudaGetSymbolAddress((void**)&p_cursor, g_cursor);
    cudaGetSymbolAddress((void**)&p_rowptr, g_rowptr);
    cudaGetSymbolAddress((void**)&p_csr, g_csr);
    cudaGetSymbolAddress((void**)&p_xhi, g_xhi);
    cudaGetSymbolAddress((void**)&p_xlo, g_xlo);
    cudaGetSymbolAddress((void**)&p_hhi, g_hhi);
    cudaGetSymbolAddress((void**)&p_hlo, g_hlo);
    cudaGetSymbolAddress((void**)&p_w0h, g_w0h);
    cudaGetSymbolAddress((void**)&p_w0l, g_w0l);
    cudaGetSymbolAddress((void**)&p_w1h, g_w1h);
    cudaGetSymbolAddress((void**)&p_w1l, g_w1l);

    cudaFuncSetAttribute(hmma_dual_gemm,
                         cudaFuncAttributeMaxDynamicSharedMemorySize, GSMEM);

    int eBlocks = (ETOT + 255) / 256;
    int nodeWarpBlocks = (NNODES * 32 + 255) / 256;
    dim3 gemmGrid(NOUT / 128, (NNODES + 127) / 128);

    // ===== prep: bf16 splits + CSR build =====
    xsplit_kernel<<<(NNODES * INDIM + 255) / 256, 256>>>(x, NNODES * INDIM, p_xhi, p_xlo);
    wsplit_kernel<<<(HCDIM * INDIM + 255) / 256, 256>>>(Wl0, INDIM, p_w0h, p_w0l);
    wsplit_kernel<<<(HCDIM * INDIM + 255) / 256, 256>>>(Wr0, INDIM,
                                                        p_w0h + 256 * INDIM, p_w0l + 256 * INDIM);
    wsplit_kernel<<<(HCDIM * HCDIM + 255) / 256, 256>>>(Wl1, HCDIM, p_w1h, p_w1l);
    wsplit_kernel<<<(HCDIM * HCDIM + 255) / 256, 256>>>(Wr1, HCDIM,
                                                        p_w1h + 256 * HCDIM, p_w1l + 256 * HCDIM);
    zero_int_kernel<<<(NNODES + 255) / 256, 256>>>(p_deg, NNODES);
    deg_kernel<<<eBlocks, 256>>>(ei, p_deg);
    scan_kernel<<<1, 1024>>>(p_deg, p_rowptr, p_cursor);
    scatter_kernel<<<eBlocks, 256>>>(ei, p_cursor, p_csr);

    // ===== Layer 0 =====
    hmma_dual_gemm<<<gemmGrid, 256, GSMEM>>>(p_xhi, p_xlo, p_w0h, p_w0l,
                                             p_xlr, NNODES, INDIM);
    node_gat_kernel<<<nodeWarpBlocks, 256>>>(p_rowptr, p_csr, p_xlr, att0,
                                             b0, g0, be0, m0, v0,
                                             p_h, p_hhi, p_hlo);

    // ===== Layer 1 =====
    hmma_dual_gemm<<<gemmGrid, 256, GSMEM>>>(p_hhi, p_hlo, p_w1h, p_w1l,
                                             p_xlr, NNODES, HCDIM);
    node_gat_kernel<<<nodeWarpBlocks, 256>>>(p_rowptr, p_csr, p_xlr, att1,
                                             b1, g1, be1, m1, v1,
                                             p_h, p_hhi, p_hlo);

    // ===== Layer 2 =====
    gemm2_kernel<<<nodeWarpBlocks, 256>>>(p_h, Wl2, Wr2, p_xl2, p_xr2);
    node_gat2_kernel<<<nodeWarpBlocks, 256>>>(p_rowptr, p_csr, p_xl2, p_xr2,
                                              att2, b2, out);
}

// round 9
// speedup vs baseline: 3.0187x; 1.0232x over previous
#include <cuda_runtime.h>
#include <cuda_bf16.h>
#include <math.h>
#include <stdint.h>

// Problem constants (fixed by reference)
#define NNODES 20000
#define NEDGES 320000
#define ETOT   340000   // NEDGES + NNODES self loops
#define INDIM  512
#define NHEAD  4
#define CDIM   64
#define HCDIM  256
#define NOUT   512      // dual-GEMM output width (xl | xr)
#define EPS_BN 1e-5f

// ---------------- scratch (device globals; no allocation allowed) ----------
__device__ float g_xlr[NNODES * NOUT];   // cols 0-255: xl, 256-511: xr
__device__ float g_h[NNODES * HCDIM];
__device__ float g_xl2[NNODES * 2];
__device__ float g_xr2[NNODES * 2];

// CSR by destination (src only)
__device__ int g_deg[NNODES];
__device__ int g_cursor[NNODES];
__device__ int g_rowptr[NNODES + 1];
__device__ int g_csr[ETOT];

// bf16 hi/lo split buffers for tensor-core GEMMs
__device__ __nv_bfloat16 g_xhi[NNODES * INDIM];
__device__ __nv_bfloat16 g_xlo[NNODES * INDIM];
__device__ __nv_bfloat16 g_hhi[NNODES * HCDIM];
__device__ __nv_bfloat16 g_hlo[NNODES * HCDIM];
// concatenated, transposed (N-major, K-contiguous) weight splits: [512, K]
__device__ __nv_bfloat16 g_w0h[NOUT * INDIM];
__device__ __nv_bfloat16 g_w0l[NOUT * INDIM];
__device__ __nv_bfloat16 g_w1h[NOUT * HCDIM];
__device__ __nv_bfloat16 g_w1l[NOUT * HCDIM];

// ---------------- PTX helpers ----------------------------------------------
__device__ __forceinline__ uint32_t smem_to_u32(const void* smem_ptr) {
    uint32_t addr;
    asm("{ .reg .u64 tmp; cvta.to.shared.u64 tmp, %1; cvt.u32.u64 %0, tmp; }"
        : "=r"(addr) : "l"(smem_ptr));
    return addr;
}

__device__ __forceinline__ void cp_async16(uint32_t dst, const void* src) {
    asm volatile("cp.async.cg.shared.global [%0], [%1], 16;" :: "r"(dst), "l"(src));
}
#define CP_COMMIT() asm volatile("cp.async.commit_group;" ::: "memory")
#define CP_WAIT(n)  asm volatile("cp.async.wait_group %0;" :: "n"(n) : "memory")

__device__ __forceinline__ void ldsm_x4(uint32_t (&r)[4], uint32_t addr) {
    asm volatile("ldmatrix.sync.aligned.m8n8.x4.shared.b16 {%0,%1,%2,%3}, [%4];"
                 : "=r"(r[0]), "=r"(r[1]), "=r"(r[2]), "=r"(r[3]) : "r"(addr));
}
__device__ __forceinline__ void ldsm_x2(uint32_t (&r)[2], uint32_t addr) {
    asm volatile("ldmatrix.sync.aligned.m8n8.x2.shared.b16 {%0,%1}, [%2];"
                 : "=r"(r[0]), "=r"(r[1]) : "r"(addr));
}
__device__ __forceinline__ void mma_bf16(float (&d)[4], const uint32_t (&a)[4],
                                         const uint32_t (&b)[2]) {
    asm volatile("mma.sync.aligned.m16n8k16.row.col.f32.bf16.bf16.f32 "
                 "{%0,%1,%2,%3}, {%4,%5,%6,%7}, {%8,%9}, {%0,%1,%2,%3};"
                 : "+f"(d[0]), "+f"(d[1]), "+f"(d[2]), "+f"(d[3])
                 : "r"(a[0]), "r"(a[1]), "r"(a[2]), "r"(a[3]),
                   "r"(b[0]), "r"(b[1]));
}

__device__ __forceinline__ void edge_endpoints(const int* __restrict__ ei, int e,
                                               int& src, int& dst) {
    if (e < NEDGES) { src = ei[e]; dst = ei[NEDGES + e]; }
    else            { src = e - NEDGES; dst = src; }
}

// ---------------- CSR build -------------------------------------------------
__global__ void zero_int_kernel(int* p, int n) {
    int i = blockIdx.x * blockDim.x + threadIdx.x;
    if (i < n) p[i] = 0;
}

__global__ void deg_kernel(const int* __restrict__ ei, int* __restrict__ deg) {
    int t = blockIdx.x * blockDim.x + threadIdx.x;
    if (t >= ETOT) return;
    int dst = (t < NEDGES) ? ei[NEDGES + t] : t - NEDGES;
    atomicAdd(&deg[dst], 1);
}

// single-block exclusive scan over NNODES elements
__global__ void scan_kernel(const int* __restrict__ deg,
                            int* __restrict__ rowptr,
                            int* __restrict__ cursor) {
    __shared__ int sdata[1024];
    __shared__ int soff;
    int tid = threadIdx.x;
    if (tid == 0) soff = 0;
    __syncthreads();
    for (int base = 0; base < NNODES; base += 1024) {
        int i = base + tid;
        int v = (i < NNODES) ? deg[i] : 0;
        sdata[tid] = v;
        __syncthreads();
        for (int d = 1; d < 1024; d <<= 1) {
            int t = (tid >= d) ? sdata[tid - d] : 0;
            __syncthreads();
            sdata[tid] += t;
            __syncthreads();
        }
        int excl = soff + sdata[tid] - v;
        if (i < NNODES) { rowptr[i] = excl; cursor[i] = excl; }
        __syncthreads();
        if (tid == 0) soff += sdata[1023];
        __syncthreads();
    }
    if (tid == 0) rowptr[NNODES] = soff;
}

__global__ void scatter_kernel(const int* __restrict__ ei,
                               int* __restrict__ cursor,
                               int* __restrict__ csr) {
    int t = blockIdx.x * blockDim.x + threadIdx.x;
    if (t >= ETOT) return;
    int src, dst;
    edge_endpoints(ei, t, src, dst);
    int pos = atomicAdd(&cursor[dst], 1);
    csr[pos] = src;
}

// ---------------- bf16 split kernels ---------------------------------------
__global__ void xsplit_kernel(const float* __restrict__ X, int n,
                              __nv_bfloat16* __restrict__ Xh,
                              __nv_bfloat16* __restrict__ Xl) {
    int i = blockIdx.x * blockDim.x + threadIdx.x;
    if (i >= n) return;
    float v = X[i];
    __nv_bfloat16 h = __float2bfloat16(v);
    Xh[i] = h;
    Xl[i] = __float2bfloat16(v - __bfloat162float(h));
}

// Tiled transpose: [K, 256] fp32 weight -> [256, K] bf16 hi/lo (K contiguous).
// 32x32 tile via padded smem; coalesced reads AND writes.
__global__ void wtrans_kernel(const float* __restrict__ W, int K,
                              __nv_bfloat16* __restrict__ Wh,
                              __nv_bfloat16* __restrict__ Wl) {
    __shared__ float tile[32][33];
    int k0 = blockIdx.x * 32, n0 = blockIdx.y * 32;
    int tx = threadIdx.x, ty = threadIdx.y;   // (32, 8)
#pragma unroll
    for (int i = 0; i < 4; i++) {
        int k = k0 + ty + i * 8;
        tile[ty + i * 8][tx] = W[(size_t)k * HCDIM + n0 + tx];
    }
    __syncthreads();
#pragma unroll
    for (int i = 0; i < 4; i++) {
        int n = n0 + ty + i * 8;
        float v = tile[tx][ty + i * 8];
        __nv_bfloat16 h = __float2bfloat16(v);
        Wh[(size_t)n * K + k0 + tx] = h;
        Wl[(size_t)n * K + k0 + tx] = __float2bfloat16(v - __bfloat162float(h));
    }
}

// ---------------- HMMA dual GEMM --------------------------------------------
#define GSTAGE 32768
#define GSMEM  (2 * GSTAGE)

__global__ void __launch_bounds__(256, 1)
hmma_dual_gemm(const __nv_bfloat16* __restrict__ Ah,
               const __nv_bfloat16* __restrict__ Al,
               const __nv_bfloat16* __restrict__ Bh,
               const __nv_bfloat16* __restrict__ Bl,
               float* __restrict__ C, int M, int K) {
    extern __shared__ char smem[];
    uint32_t sb = smem_to_u32(smem);
    int tid = threadIdx.x;
    int lane = tid & 31, wid = tid >> 5;
    int wm = wid >> 2, wn = wid & 3;
    int mBase = blockIdx.y * 128;
    int nBase = blockIdx.x * 128;
    int nq = K >> 5;

    float acc[4][4][4];
#pragma unroll
    for (int a = 0; a < 4; a++)
#pragma unroll
        for (int b = 0; b < 4; b++)
#pragma unroll
            for (int c = 0; c < 4; c++) acc[a][b][c] = 0.f;

    auto load_stage = [&](int q, int s) {
        int k0 = q << 5;
        uint32_t base = sb + s * GSTAGE;
        char* sm = smem + s * GSTAGE;
#pragma unroll
        for (int it = 0; it < 2; it++) {
            int idx = tid + it * 256;
            int r = idx >> 2, c = idx & 3;
            uint32_t dsw = r * 64 + ((c ^ (r & 3)) << 4);
            int R = mBase + r;
            if (R < M) {
                const char* sh = (const char*)(Ah + (size_t)R * K + k0) + c * 16;
                const char* sl = (const char*)(Al + (size_t)R * K + k0) + c * 16;
                cp_async16(base + dsw, sh);
                cp_async16(base + 8192 + dsw, sl);
            } else {
                uint4 z = make_uint4(0, 0, 0, 0);
                *(uint4*)(sm + dsw) = z;
                *(uint4*)(sm + 8192 + dsw) = z;
            }
        }
#pragma unroll
        for (int it = 0; it < 2; it++) {
            int idx = tid + it * 256;
            int r = idx >> 2, c = idx & 3;
            uint32_t dsw = r * 64 + ((c ^ (r & 3)) << 4);
            int NR = nBase + r;
            const char* sh = (const char*)(Bh + (size_t)NR * K + k0) + c * 16;
            const char* sl = (const char*)(Bl + (size_t)NR * K + k0) + c * 16;
            cp_async16(base + 16384 + dsw, sh);
            cp_async16(base + 24576 + dsw, sl);
        }
    };

    load_stage(0, 0); CP_COMMIT();

    for (int q = 0; q < nq; q++) {
        if (q + 1 < nq) {
            load_stage(q + 1, (q + 1) & 1); CP_COMMIT();
            CP_WAIT(1);
        } else {
            CP_WAIT(0);
        }
        __syncthreads();
        uint32_t base = sb + (q & 1) * GSTAGE;

#pragma unroll
        for (int step = 0; step < 2; step++) {
            uint32_t ahf[4][4], alf[4][4], bhf[4][2], blf[4][2];
            int arow = wm * 64 + (lane & 15);
            int ac = 2 * step + (lane >> 4);
#pragma unroll
            for (int mi = 0; mi < 4; mi++) {
                int r = arow + mi * 16;
                uint32_t ad = base + r * 64 + ((ac ^ (r & 3)) << 4);
                ldsm_x4(ahf[mi], ad);
                ldsm_x4(alf[mi], ad + 8192);
            }
#pragma unroll
            for (int nj = 0; nj < 4; nj++) {
                int r = wn * 32 + nj * 8 + (lane & 7);
                int bc = 2 * step + ((lane >> 3) & 1);
                uint32_t bd = base + 16384 + r * 64 + ((bc ^ (r & 3)) << 4);
                ldsm_x2(bhf[nj], bd);
                ldsm_x2(blf[nj], bd + 8192);
            }
#pragma unroll
            for (int mi = 0; mi < 4; mi++)
#pragma unroll
                for (int nj = 0; nj < 4; nj++) {
                    mma_bf16(acc[mi][nj], ahf[mi], bhf[nj]);
                    mma_bf16(acc[mi][nj], ahf[mi], blf[nj]);
                    mma_bf16(acc[mi][nj], alf[mi], bhf[nj]);
                }
        }
        __syncthreads();
    }

    int rBase = mBase + wm * 64;
    int cBase = nBase + wn * 32;
#pragma unroll
    for (int mi = 0; mi < 4; mi++) {
        int r0 = rBase + mi * 16 + (lane >> 2);
#pragma unroll
        for (int nj = 0; nj < 4; nj++) {
            int cc = cBase + nj * 8 + 2 * (lane & 3);
            if (r0 < M)
                *(float2*)(C + (size_t)r0 * NOUT + cc) =
                    make_float2(acc[mi][nj][0], acc[mi][nj][1]);
            if (r0 + 8 < M)
                *(float2*)(C + (size_t)(r0 + 8) * NOUT + cc) =
                    make_float2(acc[mi][nj][2], acc[mi][nj][3]);
        }
    }
}

// ---------------- fused GATv2 layer (score + softmax-agg + BN + ELU) --------
// TWO warps per node (warp half = 2 heads = 128 channels); lane owns 4 channels.
// 2-edge unrolled gather: both row loads issued before the reduce chains.
__global__ void node_gat_kernel(const int* __restrict__ rowptr,
                                const int* __restrict__ csr,
                                const float* __restrict__ xlr,
                                const float* __restrict__ att,
                                const float* __restrict__ b,
                                const float* __restrict__ g,
                                const float* __restrict__ be,
                                const float* __restrict__ m,
                                const float* __restrict__ v,
                                float* __restrict__ hout,
                                __nv_bfloat16* __restrict__ outh,
                                __nv_bfloat16* __restrict__ outl) {
    int gw = (blockIdx.x * blockDim.x + threadIdx.x) >> 5;
    int w = gw >> 1;
    if (w >= NNODES) return;
    int half = gw & 1;
    int lane = threadIdx.x & 31;
    int col = half * 128 + lane * 4;   // 4 channels per lane; 16-lane head groups
    int p0 = rowptr[w], p1 = rowptr[w + 1];

    float4 r4 = *(const float4*)(xlr + (size_t)w * NOUT + 256 + col);
    float4 a4 = *(const float4*)(att + col);
    float4 acc = make_float4(0.f, 0.f, 0.f, 0.f);
    float dsum = 0.f;

    for (int base = p0; base < p1; base += 32) {
        int se = 0;
        if (base + lane < p1) se = csr[base + lane];
        int cnt = min(32, p1 - base);
        int j = 0;
        for (; j + 2 <= cnt; j += 2) {
            int s0 = __shfl_sync(0xFFFFFFFFu, se, j);
            int s1 = __shfl_sync(0xFFFFFFFFu, se, j + 1);
            float4 v0 = *(const float4*)(xlr + (size_t)s0 * NOUT + col);
            float4 v1 = *(const float4*)(xlr + (size_t)s1 * NOUT + col);
            float sc0, sc1, mv;
            mv = v0.x + r4.x; mv = mv > 0.f ? mv : 0.2f * mv; sc0  = mv * a4.x;
            mv = v0.y + r4.y; mv = mv > 0.f ? mv : 0.2f * mv; sc0 += mv * a4.y;
            mv = v0.z + r4.z; mv = mv > 0.f ? mv : 0.2f * mv; sc0 += mv * a4.z;
            mv = v0.w + r4.w; mv = mv > 0.f ? mv : 0.2f * mv; sc0 += mv * a4.w;
            mv = v1.x + r4.x; mv = mv > 0.f ? mv : 0.2f * mv; sc1  = mv * a4.x;
            mv = v1.y + r4.y; mv = mv > 0.f ? mv : 0.2f * mv; sc1 += mv * a4.y;
            mv = v1.z + r4.z; mv = mv > 0.f ? mv : 0.2f * mv; sc1 += mv * a4.z;
            mv = v1.w + r4.w; mv = mv > 0.f ? mv : 0.2f * mv; sc1 += mv * a4.w;
#pragma unroll
            for (int off = 1; off < 16; off <<= 1) {
                sc0 += __shfl_xor_sync(0xFFFFFFFFu, sc0, off);
                sc1 += __shfl_xor_sync(0xFFFFFFFFu, sc1, off);
            }
            float e0 = __expf(sc0), e1 = __expf(sc1);
            acc.x += e0 * v0.x + e1 * v1.x;
            acc.y += e0 * v0.y + e1 * v1.y;
            acc.z += e0 * v0.z + e1 * v1.z;
            acc.w += e0 * v0.w + e1 * v1.w;
            dsum += e0 + e1;
        }
        if (j < cnt) {
            int s0 = __shfl_sync(0xFFFFFFFFu, se, j);
            float4 v0 = *(const float4*)(xlr + (size_t)s0 * NOUT + col);
            float sc0, mv;
            mv = v0.x + r4.x; mv = mv > 0.f ? mv : 0.2f * mv; sc0  = mv * a4.x;
            mv = v0.y + r4.y; mv = mv > 0.f ? mv : 0.2f * mv; sc0 += mv * a4.y;
            mv = v0.z + r4.z; mv = mv > 0.f ? mv : 0.2f * mv; sc0 += mv * a4.z;
            mv = v0.w + r4.w; mv = mv > 0.f ? mv : 0.2f * mv; sc0 += mv * a4.w;
#pragma unroll
            for (int off = 1; off < 16; off <<= 1)
                sc0 += __shfl_xor_sync(0xFFFFFFFFu, sc0, off);
            float e0 = __expf(sc0);
            acc.x += e0 * v0.x; acc.y += e0 * v0.y;
            acc.z += e0 * v0.z; acc.w += e0 * v0.w;
            dsum += e0;
        }
    }
    float inv = 1.f / (dsum + 1e-16f);

    float4 b4 = *(const float4*)(b + col);
    float4 g4 = *(const float4*)(g + col);
    float4 e4 = *(const float4*)(be + col);
    float4 m4 = *(const float4*)(m + col);
    float4 v4 = *(const float4*)(v + col);

    float o[4];
    o[0] = acc.x * inv + b4.x; o[1] = acc.y * inv + b4.y;
    o[2] = acc.z * inv + b4.z; o[3] = acc.w * inv + b4.w;
    float gg[4] = {g4.x, g4.y, g4.z, g4.w};
    float ee[4] = {e4.x, e4.y, e4.z, e4.w};
    float mm[4] = {m4.x, m4.y, m4.z, m4.w};
    float vv[4] = {v4.x, v4.y, v4.z, v4.w};
#pragma unroll
    for (int i = 0; i < 4; i++) {
        float x = (o[i] - mm[i]) * (gg[i] * rsqrtf(vv[i] + EPS_BN)) + ee[i];
        x = x > 0.f ? x : (expf(x) - 1.0f);
        o[i] = x;
    }
    *(float4*)(hout + (size_t)w * HCDIM + col) = make_float4(o[0], o[1], o[2], o[3]);

    union { uint2 u; __nv_bfloat162 p[2]; } ph, pl;
#pragma unroll
    for (int i = 0; i < 2; i++) {
        __nv_bfloat16 h0 = __float2bfloat16(o[2 * i]);
        __nv_bfloat16 h1 = __float2bfloat16(o[2 * i + 1]);
        ph.p[i] = __nv_bfloat162(h0, h1);
        pl.p[i] = __nv_bfloat162(
            __float2bfloat16(o[2 * i] - __bfloat162float(h0)),
            __float2bfloat16(o[2 * i + 1] - __bfloat162float(h1)));
    }
    *(uint2*)(outh + (size_t)w * HCDIM + col) = ph.u;
    *(uint2*)(outl + (size_t)w * HCDIM + col) = pl.u;
}

// ---------------- layer 2 (HC=256 -> 2, single head) -----------------------
__global__ void gemm2_kernel(const float* __restrict__ h,
                             const float* __restrict__ Wl,
                             const float* __restrict__ Wr,
                             float* __restrict__ xl2,
                             float* __restrict__ xr2) {
    int w = (blockIdx.x * blockDim.x + threadIdx.x) >> 5;
    int lane = threadIdx.x & 31;
    if (w >= NNODES) return;
    float al0 = 0.f, al1 = 0.f, ar0 = 0.f, ar1 = 0.f;
    const float* hp = h + (long)w * HCDIM;
#pragma unroll
    for (int k = lane; k < HCDIM; k += 32) {
        float hv = hp[k];
        float2 wl = *(const float2*)(Wl + k * 2);
        float2 wr = *(const float2*)(Wr + k * 2);
        al0 += hv * wl.x; al1 += hv * wl.y;
        ar0 += hv * wr.x; ar1 += hv * wr.y;
    }
#pragma unroll
    for (int off = 16; off; off >>= 1) {
        al0 += __shfl_xor_sync(0xFFFFFFFFu, al0, off);
        al1 += __shfl_xor_sync(0xFFFFFFFFu, al1, off);
        ar0 += __shfl_xor_sync(0xFFFFFFFFu, ar0, off);
        ar1 += __shfl_xor_sync(0xFFFFFFFFu, ar1, off);
    }
    if (lane == 0) {
        xl2[w * 2 + 0] = al0; xl2[w * 2 + 1] = al1;
        xr2[w * 2 + 0] = ar0; xr2[w * 2 + 1] = ar1;
    }
}

// Fused: scores + softmax-agg + bias + log_softmax. Warp per node, lane/edge.
__global__ void node_gat2_kernel(const int* __restrict__ rowptr,
                                 const int* __restrict__ csr,
                                 const float* __restrict__ xl2,
                                 const float* __restrict__ xr2,
                                 const float* __restrict__ att2,
                                 const float* __restrict__ b2,
                                 float* __restrict__ out) {
    int w = (blockIdx.x * blockDim.x + threadIdx.x) >> 5;
    int lane = threadIdx.x & 31;
    if (w >= NNODES) return;
    int p0 = rowptr[w], p1 = rowptr[w + 1];
    float2 r = *(const float2*)(xr2 + w * 2);
    float a0 = att2[0], a1 = att2[1];
    float s0 = 0.f, s1 = 0.f, ds = 0.f;
    for (int p = p0 + lane; p < p1; p += 32) {
        int src = csr[p];
        float2 l = *(const float2*)(xl2 + src * 2);
        float mx = l.x + r.x, my = l.y + r.y;
        mx = mx > 0.f ? mx : 0.2f * mx;
        my = my > 0.f ? my : 0.2f * my;
        float ex = __expf(mx * a0 + my * a1);
        s0 += ex * l.x; s1 += ex * l.y; ds += ex;
    }
#pragma unroll
    for (int off = 16; off; off >>= 1) {
        s0 += __shfl_xor_sync(0xFFFFFFFFu, s0, off);
        s1 += __shfl_xor_sync(0xFFFFFFFFu, s1, off);
        ds += __shfl_xor_sync(0xFFFFFFFFu, ds, off);
    }
    if (lane == 0) {
        float inv = 1.f / (ds + 1e-16f);
        float o0 = s0 * inv + b2[0];
        float o1 = s1 * inv + b2[1];
        float mx = fmaxf(o0, o1);
        float lse = mx + logf(expf(o0 - mx) + expf(o1 - mx));
        *(float2*)(out + w * 2) = make_float2(o0 - lse, o1 - lse);
    }
}

// ---------------- launch ---------------------------------------------------
extern "C" void kernel_launch(void* const* d_in, const int* in_sizes, int n_in,
                              void* d_out, int out_size) {
    const float* x   = (const float*)d_in[0];
    const int*   ei  = (const int*)d_in[1];
    const float* Wl0 = (const float*)d_in[2];
    const float* Wr0 = (const float*)d_in[3];
    const float* att0= (const float*)d_in[4];
    const float* b0  = (const float*)d_in[5];
    const float* g0  = (const float*)d_in[6];
    const float* be0 = (const float*)d_in[7];
    const float* m0  = (const float*)d_in[8];
    const float* v0  = (const float*)d_in[9];
    const float* Wl1 = (const float*)d_in[10];
    const float* Wr1 = (const float*)d_in[11];
    const float* att1= (const float*)d_in[12];
    const float* b1  = (const float*)d_in[13];
    const float* g1  = (const float*)d_in[14];
    const float* be1 = (const float*)d_in[15];
    const float* m1  = (const float*)d_in[16];
    const float* v1  = (const float*)d_in[17];
    const float* Wl2 = (const float*)d_in[18];
    const float* Wr2 = (const float*)d_in[19];
    const float* att2= (const float*)d_in[20];
    const float* b2  = (const float*)d_in[21];
    float* out = (float*)d_out;

    float *p_xlr, *p_h, *p_xl2, *p_xr2;
    int *p_deg, *p_cursor, *p_rowptr, *p_csr;
    __nv_bfloat16 *p_xhi, *p_xlo, *p_hhi, *p_hlo;
    __nv_bfloat16 *p_w0h, *p_w0l, *p_w1h, *p_w1l;
    cudaGetSymbolAddress((void**)&p_xlr, g_xlr);
    cudaGetSymbolAddress((void**)&p_h, g_h);
    cudaGetSymbolAddress((void**)&p_xl2, g_xl2);
    cudaGetSymbolAddress((void**)&p_xr2, g_xr2);
    cudaGetSymbolAddress((void**)&p_deg, g_deg);
    cudaGetSymbolAddress((void**)&p_cursor, g_cursor);
    cudaGetSymbolAddress((void**)&p_rowptr, g_rowptr);
    cudaGetSymbolAddress((void**)&p_csr, g_csr);
    cudaGetSymbolAddress((void**)&p_xhi, g_xhi);
    cudaGetSymbolAddress((void**)&p_xlo, g_xlo);
    cudaGetSymbolAddress((void**)&p_hhi, g_hhi);
    cudaGetSymbolAddress((void**)&p_hlo, g_hlo);
    cudaGetSymbolAddress((void**)&p_w0h, g_w0h);
    cudaGetSymbolAddress((void**)&p_w0l, g_w0l);
    cudaGetSymbolAddress((void**)&p_w1h, g_w1h);
    cudaGetSymbolAddress((void**)&p_w1l, g_w1l);

    cudaFuncSetAttribute(hmma_dual_gemm,
                         cudaFuncAttributeMaxDynamicSharedMemorySize, GSMEM);

    int eBlocks = (ETOT + 255) / 256;
    int nodeWarpBlocks = (NNODES * 32 + 255) / 256;
    int node2WarpBlocks = (NNODES * 64 + 255) / 256;
    dim3 gemmGrid(NOUT / 128, (NNODES + 127) / 128);
    dim3 wtB(32, 8);

    // ===== prep: bf16 splits + CSR build =====
    xsplit_kernel<<<(NNODES * INDIM + 255) / 256, 256>>>(x, NNODES * INDIM, p_xhi, p_xlo);
    wtrans_kernel<<<dim3(INDIM / 32, 8), wtB>>>(Wl0, INDIM, p_w0h, p_w0l);
    wtrans_kernel<<<dim3(INDIM / 32, 8), wtB>>>(Wr0, INDIM,
                                                p_w0h + 256 * INDIM, p_w0l + 256 * INDIM);
    wtrans_kernel<<<dim3(HCDIM / 32, 8), wtB>>>(Wl1, HCDIM, p_w1h, p_w1l);
    wtrans_kernel<<<dim3(HCDIM / 32, 8), wtB>>>(Wr1, HCDIM,
                                                p_w1h + 256 * HCDIM, p_w1l + 256 * HCDIM);
    zero_int_kernel<<<(NNODES + 255) / 256, 256>>>(p_deg, NNODES);
    deg_kernel<<<eBlocks, 256>>>(ei, p_deg);
    scan_kernel<<<1, 1024>>>(p_deg, p_rowptr, p_cursor);
    scatter_kernel<<<eBlocks, 256>>>(ei, p_cursor, p_csr);

    // ===== Layer 0 =====
    hmma_dual_gemm<<<gemmGrid, 256, GSMEM>>>(p_xhi, p_xlo, p_w0h, p_w0l,
                                             p_xlr, NNODES, INDIM);
    node_gat_kernel<<<node2WarpBlocks, 256>>>(p_rowptr, p_csr, p_xlr, att0,
                                              b0, g0, be0, m0, v0,
                                              p_h, p_hhi, p_hlo);

    // ===== Layer 1 =====
    hmma_dual_gemm<<<gemmGrid, 256, GSMEM>>>(p_hhi, p_hlo, p_w1h, p_w1l,
                                             p_xlr, NNODES, HCDIM);
    node_gat_kernel<<<node2WarpBlocks, 256>>>(p_rowptr, p_csr, p_xlr, att1,
                                              b1, g1, be1, m1, v1,
                                              p_h, p_hhi, p_hlo);

    // ===== Layer 2 =====
    gemm2_kernel<<<nodeWarpBlocks, 256>>>(p_h, Wl2, Wr2, p_xl2, p_xr2);
    node_gat2_kernel<<<nodeWarpBlocks, 256>>>(p_rowptr, p_csr, p_xl2, p_xr2,
                                              att2, b2, out);
}

// round 12
// speedup vs baseline: 3.1422x; 1.0409x over previous
#include <cuda_runtime.h>
#include <cuda_bf16.h>
#include <math.h>
#include <stdint.h>

// Problem constants (fixed by reference)
#define NNODES 20000
#define NEDGES 320000
#define ETOT   340000   // NEDGES + NNODES self loops
#define INDIM  512
#define NHEAD  4
#define CDIM   64
#define HCDIM  256
#define NOUT   512      // dual-GEMM output width (xl | xr)
#define EPS_BN 1e-5f

// ---------------- scratch (device globals; no allocation allowed) ----------
__device__ float g_xlr[NNODES * NOUT];   // cols 0-255: xl, 256-511: xr
__device__ float g_h[NNODES * HCDIM];
__device__ float g_xl2[NNODES * 2];
__device__ float g_xr2[NNODES * 2];

// CSR by destination (src only)
__device__ int g_deg[NNODES];
__device__ int g_cursor[NNODES];
__device__ int g_rowptr[NNODES + 1];
__device__ int g_csr[ETOT];

// bf16 hi/lo split buffers for tensor-core GEMMs
__device__ __nv_bfloat16 g_xhi[NNODES * INDIM];
__device__ __nv_bfloat16 g_xlo[NNODES * INDIM];
__device__ __nv_bfloat16 g_hhi[NNODES * HCDIM];
__device__ __nv_bfloat16 g_hlo[NNODES * HCDIM];
// concatenated, transposed (N-major, K-contiguous) weight splits: [512, K]
__device__ __nv_bfloat16 g_w0h[NOUT * INDIM];
__device__ __nv_bfloat16 g_w0l[NOUT * INDIM];
__device__ __nv_bfloat16 g_w1h[NOUT * HCDIM];
__device__ __nv_bfloat16 g_w1l[NOUT * HCDIM];

// ---------------- PTX helpers ----------------------------------------------
__device__ __forceinline__ uint32_t smem_to_u32(const void* smem_ptr) {
    uint32_t addr;
    asm("{ .reg .u64 tmp; cvta.to.shared.u64 tmp, %1; cvt.u32.u64 %0, tmp; }"
        : "=r"(addr) : "l"(smem_ptr));
    return addr;
}

__device__ __forceinline__ void cp_async16(uint32_t dst, const void* src) {
    asm volatile("cp.async.cg.shared.global [%0], [%1], 16;" :: "r"(dst), "l"(src));
}
#define CP_COMMIT() asm volatile("cp.async.commit_group;" ::: "memory")
#define CP_WAIT(n)  asm volatile("cp.async.wait_group %0;" :: "n"(n) : "memory")

__device__ __forceinline__ void ldsm_x4(uint32_t (&r)[4], uint32_t addr) {
    asm volatile("ldmatrix.sync.aligned.m8n8.x4.shared.b16 {%0,%1,%2,%3}, [%4];"
                 : "=r"(r[0]), "=r"(r[1]), "=r"(r[2]), "=r"(r[3]) : "r"(addr));
}
__device__ __forceinline__ void ldsm_x2(uint32_t (&r)[2], uint32_t addr) {
    asm volatile("ldmatrix.sync.aligned.m8n8.x2.shared.b16 {%0,%1}, [%2];"
                 : "=r"(r[0]), "=r"(r[1]) : "r"(addr));
}
__device__ __forceinline__ void mma_bf16(float (&d)[4], const uint32_t (&a)[4],
                                         const uint32_t (&b)[2]) {
    asm volatile("mma.sync.aligned.m16n8k16.row.col.f32.bf16.bf16.f32 "
                 "{%0,%1,%2,%3}, {%4,%5,%6,%7}, {%8,%9}, {%0,%1,%2,%3};"
                 : "+f"(d[0]), "+f"(d[1]), "+f"(d[2]), "+f"(d[3])
                 : "r"(a[0]), "r"(a[1]), "r"(a[2]), "r"(a[3]),
                   "r"(b[0]), "r"(b[1]));
}

__device__ __forceinline__ void edge_endpoints(const int* __restrict__ ei, int e,
                                               int& src, int& dst) {
    if (e < NEDGES) { src = ei[e]; dst = ei[NEDGES + e]; }
    else            { src = e - NEDGES; dst = src; }
}

// ---------------- CSR build -------------------------------------------------
__global__ void deg_kernel(const int* __restrict__ ei, int* __restrict__ deg) {
    int t = blockIdx.x * blockDim.x + threadIdx.x;
    if (t >= ETOT) return;
    int dst = (t < NEDGES) ? ei[NEDGES + t] : t - NEDGES;
    atomicAdd(&deg[dst], 1);
}

// single-block hierarchical exclusive scan: 20/thread serial -> warp -> block
__global__ void scan_kernel(const int* __restrict__ deg,
                            int* __restrict__ rowptr,
                            int* __restrict__ cursor) {
    const int PER = 20;   // 1024 * 20 >= NNODES
    int tid = threadIdx.x;
    int base = tid * PER;
    int vals[PER];
    int sum = 0;
#pragma unroll
    for (int i = 0; i < PER; i++) {
        int idx = base + i;
        int v = (idx < NNODES) ? deg[idx] : 0;
        vals[i] = sum;
        sum += v;
    }
    int lane = tid & 31, wid = tid >> 5;
    int inc = sum;
#pragma unroll
    for (int off = 1; off < 32; off <<= 1) {
        int n = __shfl_up_sync(0xFFFFFFFFu, inc, off);
        if (lane >= off) inc += n;
    }
    __shared__ int wsum[32];
    if (lane == 31) wsum[wid] = inc;
    __syncthreads();
    if (tid < 32) {
        int wv = wsum[tid];
#pragma unroll
        for (int off = 1; off < 32; off <<= 1) {
            int n = __shfl_up_sync(0xFFFFFFFFu, wv, off);
            if (tid >= off) wv += n;
        }
        wsum[tid] = wv;
    }
    __syncthreads();
    int warpExcl = (wid == 0) ? 0 : wsum[wid - 1];
    int thrExcl = warpExcl + inc - sum;
#pragma unroll
    for (int i = 0; i < PER; i++) {
        int idx = base + i;
        if (idx < NNODES) {
            int e = thrExcl + vals[i];
            rowptr[idx] = e;
            cursor[idx] = e;
        }
    }
    if (tid == 0) rowptr[NNODES] = wsum[31];
}

__global__ void scatter_kernel(const int* __restrict__ ei,
                               int* __restrict__ cursor,
                               int* __restrict__ csr) {
    int t = blockIdx.x * blockDim.x + threadIdx.x;
    if (t >= ETOT) return;
    int src, dst;
    edge_endpoints(ei, t, src, dst);
    int pos = atomicAdd(&cursor[dst], 1);
    csr[pos] = src;
}

// ---------------- bf16 split kernels ---------------------------------------
// also zeroes the degree histogram (first 79 blocks) to save a launch
__global__ void xsplit_kernel(const float* __restrict__ X, int n,
                              __nv_bfloat16* __restrict__ Xh,
                              __nv_bfloat16* __restrict__ Xl,
                              int* __restrict__ deg) {
    int i = blockIdx.x * blockDim.x + threadIdx.x;
    if (i < NNODES) deg[i] = 0;
    if (i >= n) return;
    float v = X[i];
    __nv_bfloat16 h = __float2bfloat16(v);
    Xh[i] = h;
    Xl[i] = __float2bfloat16(v - __bfloat162float(h));
}

// All 4 weight transposes in one launch (blockIdx.z selects matrix).
// [K, 256] fp32 -> [256, K] bf16 hi/lo via 32x33 padded smem tile.
__global__ void wtrans_all_kernel(const float* __restrict__ Wl0,
                                  const float* __restrict__ Wr0,
                                  const float* __restrict__ Wl1,
                                  const float* __restrict__ Wr1,
                                  __nv_bfloat16* __restrict__ w0h,
                                  __nv_bfloat16* __restrict__ w0l,
                                  __nv_bfloat16* __restrict__ w1h,
                                  __nv_bfloat16* __restrict__ w1l) {
    int z = blockIdx.z;
    const float* W;
    __nv_bfloat16 *Wh, *Wl;
    int K;
    if (z == 0)      { W = Wl0; K = INDIM; Wh = w0h;               Wl = w0l; }
    else if (z == 1) { W = Wr0; K = INDIM; Wh = w0h + 256 * INDIM; Wl = w0l + 256 * INDIM; }
    else if (z == 2) { W = Wl1; K = HCDIM; Wh = w1h;               Wl = w1l; }
    else             { W = Wr1; K = HCDIM; Wh = w1h + 256 * HCDIM; Wl = w1l + 256 * HCDIM; }
    int k0 = blockIdx.x * 32;
    if (k0 >= K) return;
    int n0 = blockIdx.y * 32;
    __shared__ float tile[32][33];
    int tx = threadIdx.x, ty = threadIdx.y;   // (32, 8)
#pragma unroll
    for (int i = 0; i < 4; i++) {
        int k = k0 + ty + i * 8;
        tile[ty + i * 8][tx] = W[(size_t)k * HCDIM + n0 + tx];
    }
    __syncthreads();
#pragma unroll
    for (int i = 0; i < 4; i++) {
        int n = n0 + ty + i * 8;
        float v = tile[tx][ty + i * 8];
        __nv_bfloat16 h = __float2bfloat16(v);
        Wh[(size_t)n * K + k0 + tx] = h;
        Wl[(size_t)n * K + k0 + tx] = __float2bfloat16(v - __bfloat162float(h));
    }
}

// ---------------- HMMA dual GEMM (3-stage pipeline) -------------------------
#define GSTAGE 32768
#define GSMEM  (3 * GSTAGE)

__global__ void __launch_bounds__(256, 1)
hmma_dual_gemm(const __nv_bfloat16* __restrict__ Ah,
               const __nv_bfloat16* __restrict__ Al,
               const __nv_bfloat16* __restrict__ Bh,
               const __nv_bfloat16* __restrict__ Bl,
               float* __restrict__ C, int M, int K) {
    extern __shared__ char smem[];
    uint32_t sb = smem_to_u32(smem);
    int tid = threadIdx.x;
    int lane = tid & 31, wid = tid >> 5;
    int wm = wid >> 2, wn = wid & 3;
    int mBase = blockIdx.y * 128;
    int nBase = blockIdx.x * 128;
    int nq = K >> 5;

    float acc[4][4][4];
#pragma unroll
    for (int a = 0; a < 4; a++)
#pragma unroll
        for (int b = 0; b < 4; b++)
#pragma unroll
            for (int c = 0; c < 4; c++) acc[a][b][c] = 0.f;

    auto load_stage = [&](int q, int s) {
        int k0 = q << 5;
        uint32_t base = sb + s * GSTAGE;
        char* sm = smem + s * GSTAGE;
#pragma unroll
        for (int it = 0; it < 2; it++) {
            int idx = tid + it * 256;
            int r = idx >> 2, c = idx & 3;
            uint32_t dsw = r * 64 + ((c ^ (r & 3)) << 4);
            int R = mBase + r;
            if (R < M) {
                const char* sh = (const char*)(Ah + (size_t)R * K + k0) + c * 16;
                const char* sl = (const char*)(Al + (size_t)R * K + k0) + c * 16;
                cp_async16(base + dsw, sh);
                cp_async16(base + 8192 + dsw, sl);
            } else {
                uint4 z = make_uint4(0, 0, 0, 0);
                *(uint4*)(sm + dsw) = z;
                *(uint4*)(sm + 8192 + dsw) = z;
            }
        }
#pragma unroll
        for (int it = 0; it < 2; it++) {
            int idx = tid + it * 256;
            int r = idx >> 2, c = idx & 3;
            uint32_t dsw = r * 64 + ((c ^ (r & 3)) << 4);
            int NR = nBase + r;
            const char* sh = (const char*)(Bh + (size_t)NR * K + k0) + c * 16;
            const char* sl = (const char*)(Bl + (size_t)NR * K + k0) + c * 16;
            cp_async16(base + 16384 + dsw, sh);
            cp_async16(base + 24576 + dsw, sl);
        }
    };

    load_stage(0, 0); CP_COMMIT();
    load_stage(1, 1); CP_COMMIT();

    int stage = 0;
    for (int q = 0; q < nq; q++) {
        if (q + 2 < nq) {
            int s2 = stage + 2; if (s2 >= 3) s2 -= 3;
            load_stage(q + 2, s2); CP_COMMIT();
            CP_WAIT(2);
        } else if (q + 1 < nq) {
            CP_WAIT(1);
        } else {
            CP_WAIT(0);
        }
        __syncthreads();
        uint32_t base = sb + stage * GSTAGE;

#pragma unroll
        for (int step = 0; step < 2; step++) {
            uint32_t ahf[4][4], alf[4][4], bhf[4][2], blf[4][2];
            int arow = wm * 64 + (lane & 15);
            int ac = 2 * step + (lane >> 4);
#pragma unroll
            for (int mi = 0; mi < 4; mi++) {
                int r = arow + mi * 16;
                uint32_t ad = base + r * 64 + ((ac ^ (r & 3)) << 4);
                ldsm_x4(ahf[mi], ad);
                ldsm_x4(alf[mi], ad + 8192);
            }
#pragma unroll
            for (int nj = 0; nj < 4; nj++) {
                int r = wn * 32 + nj * 8 + (lane & 7);
                int bc = 2 * step + ((lane >> 3) & 1);
                uint32_t bd = base + 16384 + r * 64 + ((bc ^ (r & 3)) << 4);
                ldsm_x2(bhf[nj], bd);
                ldsm_x2(blf[nj], bd + 8192);
            }
            // product-major ordering: 16 independent accumulators between revisits
#pragma unroll
            for (int mi = 0; mi < 4; mi++)
#pragma unroll
                for (int nj = 0; nj < 4; nj++)
                    mma_bf16(acc[mi][nj], ahf[mi], bhf[nj]);
#pragma unroll
            for (int mi = 0; mi < 4; mi++)
#pragma unroll
                for (int nj = 0; nj < 4; nj++)
                    mma_bf16(acc[mi][nj], ahf[mi], blf[nj]);
#pragma unroll
            for (int mi = 0; mi < 4; mi++)
#pragma unroll
                for (int nj = 0; nj < 4; nj++)
                    mma_bf16(acc[mi][nj], alf[mi], bhf[nj]);
        }
        __syncthreads();
        if (++stage == 3) stage = 0;
    }

    int rBase = mBase + wm * 64;
    int cBase = nBase + wn * 32;
#pragma unroll
    for (int mi = 0; mi < 4; mi++) {
        int r0 = rBase + mi * 16 + (lane >> 2);
#pragma unroll
        for (int nj = 0; nj < 4; nj++) {
            int cc = cBase + nj * 8 + 2 * (lane & 3);
            if (r0 < M)
                *(float2*)(C + (size_t)r0 * NOUT + cc) =
                    make_float2(acc[mi][nj][0], acc[mi][nj][1]);
            if (r0 + 8 < M)
                *(float2*)(C + (size_t)(r0 + 8) * NOUT + cc) =
                    make_float2(acc[mi][nj][2], acc[mi][nj][3]);
        }
    }
}

// ---------------- fused GATv2 layer (score + softmax-agg + BN + ELU) --------
// TWO warps per node (warp half = 2 heads = 128 channels); lane owns 4 channels.
__global__ void node_gat_kernel(const int* __restrict__ rowptr,
                                const int* __restrict__ csr,
                                const float* __restrict__ xlr,
                                const float* __restrict__ att,
                                const float* __restrict__ b,
                                const float* __restrict__ g,
                                const float* __restrict__ be,
                                const float* __restrict__ m,
                                const float* __restrict__ v,
                                float* __restrict__ hout,
                                __nv_bfloat16* __restrict__ outh,
                                __nv_bfloat16* __restrict__ outl) {
    int gw = (blockIdx.x * blockDim.x + threadIdx.x) >> 5;
    int w = gw >> 1;
    if (w >= NNODES) return;
    int half = gw & 1;
    int lane = threadIdx.x & 31;
    int col = half * 128 + lane * 4;
    int p0 = rowptr[w], p1 = rowptr[w + 1];

    float4 r4 = *(const float4*)(xlr + (size_t)w * NOUT + 256 + col);
    float4 a4 = *(const float4*)(att + col);
    float4 acc = make_float4(0.f, 0.f, 0.f, 0.f);
    float dsum = 0.f;

    for (int base = p0; base < p1; base += 32) {
        int se = 0;
        if (base + lane < p1) se = csr[base + lane];
        int cnt = min(32, p1 - base);
        int j = 0;
        for (; j + 2 <= cnt; j += 2) {
            int s0 = __shfl_sync(0xFFFFFFFFu, se, j);
            int s1 = __shfl_sync(0xFFFFFFFFu, se, j + 1);
            float4 v0 = *(const float4*)(xlr + (size_t)s0 * NOUT + col);
            float4 v1 = *(const float4*)(xlr + (size_t)s1 * NOUT + col);
            float sc0, sc1, mv;
            mv = v0.x + r4.x; mv = mv > 0.f ? mv : 0.2f * mv; sc0  = mv * a4.x;
            mv = v0.y + r4.y; mv = mv > 0.f ? mv : 0.2f * mv; sc0 += mv * a4.y;
            mv = v0.z + r4.z; mv = mv > 0.f ? mv : 0.2f * mv; sc0 += mv * a4.z;
            mv = v0.w + r4.w; mv = mv > 0.f ? mv : 0.2f * mv; sc0 += mv * a4.w;
            mv = v1.x + r4.x; mv = mv > 0.f ? mv : 0.2f * mv; sc1  = mv * a4.x;
            mv = v1.y + r4.y; mv = mv > 0.f ? mv : 0.2f * mv; sc1 += mv * a4.y;
            mv = v1.z + r4.z; mv = mv > 0.f ? mv : 0.2f * mv; sc1 += mv * a4.z;
            mv = v1.w + r4.w; mv = mv > 0.f ? mv : 0.2f * mv; sc1 += mv * a4.w;
#pragma unroll
            for (int off = 1; off < 16; off <<= 1) {
                sc0 += __shfl_xor_sync(0xFFFFFFFFu, sc0, off);
                sc1 += __shfl_xor_sync(0xFFFFFFFFu, sc1, off);
            }
            float e0 = __expf(sc0), e1 = __expf(sc1);
            acc.x += e0 * v0.x + e1 * v1.x;
            acc.y += e0 * v0.y + e1 * v1.y;
            acc.z += e0 * v0.z + e1 * v1.z;
            acc.w += e0 * v0.w + e1 * v1.w;
            dsum += e0 + e1;
        }
        if (j < cnt) {
            int s0 = __shfl_sync(0xFFFFFFFFu, se, j);
            float4 v0 = *(const float4*)(xlr + (size_t)s0 * NOUT + col);
            float sc0, mv;
            mv = v0.x + r4.x; mv = mv > 0.f ? mv : 0.2f * mv; sc0  = mv * a4.x;
            mv = v0.y + r4.y; mv = mv > 0.f ? mv : 0.2f * mv; sc0 += mv * a4.y;
            mv = v0.z + r4.z; mv = mv > 0.f ? mv : 0.2f * mv; sc0 += mv * a4.z;
            mv = v0.w + r4.w; mv = mv > 0.f ? mv : 0.2f * mv; sc0 += mv * a4.w;
#pragma unroll
            for (int off = 1; off < 16; off <<= 1)
                sc0 += __shfl_xor_sync(0xFFFFFFFFu, sc0, off);
            float e0 = __expf(sc0);
            acc.x += e0 * v0.x; acc.y += e0 * v0.y;
            acc.z += e0 * v0.z; acc.w += e0 * v0.w;
            dsum += e0;
        }
    }
    float inv = 1.f / (dsum + 1e-16f);

    float4 b4 = *(const float4*)(b + col);
    float4 g4 = *(const float4*)(g + col);
    float4 e4 = *(const float4*)(be + col);
    float4 m4 = *(const float4*)(m + col);
    float4 v4 = *(const float4*)(v + col);

    float o[4];
    o[0] = acc.x * inv + b4.x; o[1] = acc.y * inv + b4.y;
    o[2] = acc.z * inv + b4.z; o[3] = acc.w * inv + b4.w;
    float gg[4] = {g4.x, g4.y, g4.z, g4.w};
    float ee[4] = {e4.x, e4.y, e4.z, e4.w};
    float mm[4] = {m4.x, m4.y, m4.z, m4.w};
    float vv[4] = {v4.x, v4.y, v4.z, v4.w};
#pragma unroll
    for (int i = 0; i < 4; i++) {
        float x = (o[i] - mm[i]) * (gg[i] * rsqrtf(vv[i] + EPS_BN)) + ee[i];
        x = x > 0.f ? x : (expf(x) - 1.0f);
        o[i] = x;
    }
    *(float4*)(hout + (size_t)w * HCDIM + col) = make_float4(o[0], o[1], o[2], o[3]);

    union { uint2 u; __nv_bfloat162 p[2]; } ph, pl;
#pragma unroll
    for (int i = 0; i < 2; i++) {
        __nv_bfloat16 h0 = __float2bfloat16(o[2 * i]);
        __nv_bfloat16 h1 = __float2bfloat16(o[2 * i + 1]);
        ph.p[i] = __nv_bfloat162(h0, h1);
        pl.p[i] = __nv_bfloat162(
            __float2bfloat16(o[2 * i] - __bfloat162float(h0)),
            __float2bfloat16(o[2 * i + 1] - __bfloat162float(h1)));
    }
    *(uint2*)(outh + (size_t)w * HCDIM + col) = ph.u;
    *(uint2*)(outl + (size_t)w * HCDIM + col) = pl.u;
}

// ---------------- layer 2 (HC=256 -> 2, single head) -----------------------
__global__ void gemm2_kernel(const float* __restrict__ h,
                             const float* __restrict__ Wl,
                             const float* __restrict__ Wr,
                             float* __restrict__ xl2,
                             float* __restrict__ xr2) {
    int w = (blockIdx.x * blockDim.x + threadIdx.x) >> 5;
    int lane = threadIdx.x & 31;
    if (w >= NNODES) return;
    float al0 = 0.f, al1 = 0.f, ar0 = 0.f, ar1 = 0.f;
    const float* hp = h + (long)w * HCDIM;
#pragma unroll
    for (int k = lane; k < HCDIM; k += 32) {
        float hv = hp[k];
        float2 wl = *(const float2*)(Wl + k * 2);
        float2 wr = *(const float2*)(Wr + k * 2);
        al0 += hv * wl.x; al1 += hv * wl.y;
        ar0 += hv * wr.x; ar1 += hv * wr.y;
    }
#pragma unroll
    for (int off = 16; off; off >>= 1) {
        al0 += __shfl_xor_sync(0xFFFFFFFFu, al0, off);
        al1 += __shfl_xor_sync(0xFFFFFFFFu, al1, off);
        ar0 += __shfl_xor_sync(0xFFFFFFFFu, ar0, off);
        ar1 += __shfl_xor_sync(0xFFFFFFFFu, ar1, off);
    }
    if (lane == 0) {
        xl2[w * 2 + 0] = al0; xl2[w * 2 + 1] = al1;
        xr2[w * 2 + 0] = ar0; xr2[w * 2 + 1] = ar1;
    }
}

__global__ void node_gat2_kernel(const int* __restrict__ rowptr,
                                 const int* __restrict__ csr,
                                 const float* __restrict__ xl2,
                                 const float* __restrict__ xr2,
                                 const float* __restrict__ att2,
                                 const float* __restrict__ b2,
                                 float* __restrict__ out) {
    int w = (blockIdx.x * blockDim.x + threadIdx.x) >> 5;
    int lane = threadIdx.x & 31;
    if (w >= NNODES) return;
    int p0 = rowptr[w], p1 = rowptr[w + 1];
    float2 r = *(const float2*)(xr2 + w * 2);
    float a0 = att2[0], a1 = att2[1];
    float s0 = 0.f, s1 = 0.f, ds = 0.f;
    for (int p = p0 + lane; p < p1; p += 32) {
        int src = csr[p];
        float2 l = *(const float2*)(xl2 + src * 2);
        float mx = l.x + r.x, my = l.y + r.y;
        mx = mx > 0.f ? mx : 0.2f * mx;
        my = my > 0.f ? my : 0.2f * my;
        float ex = __expf(mx * a0 + my * a1);
        s0 += ex * l.x; s1 += ex * l.y; ds += ex;
    }
#pragma unroll
    for (int off = 16; off; off >>= 1) {
        s0 += __shfl_xor_sync(0xFFFFFFFFu, s0, off);
        s1 += __shfl_xor_sync(0xFFFFFFFFu, s1, off);
        ds += __shfl_xor_sync(0xFFFFFFFFu, ds, off);
    }
    if (lane == 0) {
        float inv = 1.f / (ds + 1e-16f);
        float o0 = s0 * inv + b2[0];
        float o1 = s1 * inv + b2[1];
        float mx = fmaxf(o0, o1);
        float lse = mx + logf(expf(o0 - mx) + expf(o1 - mx));
        *(float2*)(out + w * 2) = make_float2(o0 - lse, o1 - lse);
    }
}

// ---------------- launch ---------------------------------------------------
extern "C" void kernel_launch(void* const* d_in, const int* in_sizes, int n_in,
                              void* d_out, int out_size) {
    const float* x   = (const float*)d_in[0];
    const int*   ei  = (const int*)d_in[1];
    const float* Wl0 = (const float*)d_in[2];
    const float* Wr0 = (const float*)d_in[3];
    const float* att0= (const float*)d_in[4];
    const float* b0  = (const float*)d_in[5];
    const float* g0  = (const float*)d_in[6];
    const float* be0 = (const float*)d_in[7];
    const float* m0  = (const float*)d_in[8];
    const float* v0  = (const float*)d_in[9];
    const float* Wl1 = (const float*)d_in[10];
    const float* Wr1 = (const float*)d_in[11];
    const float* att1= (const float*)d_in[12];
    const float* b1  = (const float*)d_in[13];
    const float* g1  = (const float*)d_in[14];
    const float* be1 = (const float*)d_in[15];
    const float* m1  = (const float*)d_in[16];
    const float* v1  = (const float*)d_in[17];
    const float* Wl2 = (const float*)d_in[18];
    const float* Wr2 = (const float*)d_in[19];
    const float* att2= (const float*)d_in[20];
    const float* b2  = (const float*)d_in[21];
    float* out = (float*)d_out;

    float *p_xlr, *p_h, *p_xl2, *p_xr2;
    int *p_deg, *p_cursor, *p_rowptr, *p_csr;
    __nv_bfloat16 *p_xhi, *p_xlo, *p_hhi, *p_hlo;
    __nv_bfloat16 *p_w0h, *p_w0l, *p_w1h, *p_w1l;
    cudaGetSymbolAddress((void**)&p_xlr, g_xlr);
    cudaGetSymbolAddress((void**)&p_h, g_h);
    cudaGetSymbolAddress((void**)&p_xl2, g_xl2);
    cudaGetSymbolAddress((void**)&p_xr2, g_xr2);
    cudaGetSymbolAddress((void**)&p_deg, g_deg);
    cudaGetSymbolAddress((void**)&p_cursor, g_cursor);
    cudaGetSymbolAddress((void**)&p_rowptr, g_rowptr);
    cudaGetSymbolAddress((void**)&p_csr, g_csr);
    cudaGetSymbolAddress((void**)&p_xhi, g_xhi);
    cudaGetSymbolAddress((void**)&p_xlo, g_xlo);
    cudaGetSymbolAddress((void**)&p_hhi, g_hhi);
    cudaGetSymbolAddress((void**)&p_hlo, g_hlo);
    cudaGetSymbolAddress((void**)&p_w0h, g_w0h);
    cudaGetSymbolAddress((void**)&p_w0l, g_w0l);
    cudaGetSymbolAddress((void**)&p_w1h, g_w1h);
    cudaGetSymbolAddress((void**)&p_w1l, g_w1l);

    cudaFuncSetAttribute(hmma_dual_gemm,
                         cudaFuncAttributeMaxDynamicSharedMemorySize, GSMEM);

    int eBlocks = (ETOT + 255) / 256;
    int nodeWarpBlocks = (NNODES * 32 + 255) / 256;
    int node2WarpBlocks = (NNODES * 64 + 255) / 256;
    dim3 gemmGrid(NOUT / 128, (NNODES + 127) / 128);
    dim3 wtB(32, 8);

    // ===== prep: bf16 splits (+deg zero) + merged wtrans + CSR build =====
    xsplit_kernel<<<(NNODES * INDIM + 255) / 256, 256>>>(x, NNODES * INDIM,
                                                         p_xhi, p_xlo, p_deg);
    wtrans_all_kernel<<<dim3(INDIM / 32, 8, 4), wtB>>>(Wl0, Wr0, Wl1, Wr1,
                                                       p_w0h, p_w0l, p_w1h, p_w1l);
    deg_kernel<<<eBlocks, 256>>>(ei, p_deg);
    scan_kernel<<<1, 1024>>>(p_deg, p_rowptr, p_cursor);
    scatter_kernel<<<eBlocks, 256>>>(ei, p_cursor, p_csr);

    // ===== Layer 0 =====
    hmma_dual_gemm<<<gemmGrid, 256, GSMEM>>>(p_xhi, p_xlo, p_w0h, p_w0l,
                                             p_xlr, NNODES, INDIM);
    node_gat_kernel<<<node2WarpBlocks, 256>>>(p_rowptr, p_csr, p_xlr, att0,
                                              b0, g0, be0, m0, v0,
                                              p_h, p_hhi, p_hlo);

    // ===== Layer 1 =====
    hmma_dual_gemm<<<gemmGrid, 256, GSMEM>>>(p_hhi, p_hlo, p_w1h, p_w1l,
                                             p_xlr, NNODES, HCDIM);
    node_gat_kernel<<<node2WarpBlocks, 256>>>(p_rowptr, p_csr, p_xlr, att1,
                                              b1, g1, be1, m1, v1,
                                              p_h, p_hhi, p_hlo);

    // ===== Layer 2 =====
    gemm2_kernel<<<nodeWarpBlocks, 256>>>(p_h, Wl2, Wr2, p_xl2, p_xr2);
    node_gat2_kernel<<<nodeWarpBlocks, 256>>>(p_rowptr, p_csr, p_xl2, p_xr2,
                                              att2, b2, out);
}

// round 13
// speedup vs baseline: 3.2407x; 1.0313x over previous
#include <cuda_runtime.h>
#include <cuda_bf16.h>
#include <math.h>
#include <stdint.h>

// Problem constants (fixed by reference)
#define NNODES 20000
#define NEDGES 320000
#define ETOT   340000   // NEDGES + NNODES self loops
#define INDIM  512
#define NHEAD  4
#define CDIM   64
#define HCDIM  256
#define NOUT   512      // dual-GEMM output width (xl | xr)
#define EPS_BN 1e-5f

// ---------------- scratch (device globals; no allocation allowed) ----------
__device__ float g_xlr[NNODES * NOUT];   // cols 0-255: xl, 256-511: xr
__device__ float g_h[NNODES * HCDIM];
__device__ float g_xl2[NNODES * 2];
__device__ float g_xr2[NNODES * 2];

// CSR by destination (src only)
__device__ int g_deg[NNODES];
__device__ int g_cursor[NNODES];
__device__ int g_rowptr[NNODES + 1];
__device__ int g_csr[ETOT];

// bf16 hi/lo split buffers for tensor-core GEMMs
__device__ __nv_bfloat16 g_xhi[NNODES * INDIM];
__device__ __nv_bfloat16 g_xlo[NNODES * INDIM];
__device__ __nv_bfloat16 g_hhi[NNODES * HCDIM];
__device__ __nv_bfloat16 g_hlo[NNODES * HCDIM];
// concatenated, transposed (N-major, K-contiguous) weight splits: [512, K]
__device__ __nv_bfloat16 g_w0h[NOUT * INDIM];
__device__ __nv_bfloat16 g_w0l[NOUT * INDIM];
__device__ __nv_bfloat16 g_w1h[NOUT * HCDIM];
__device__ __nv_bfloat16 g_w1l[NOUT * HCDIM];

// ---------------- PTX helpers ----------------------------------------------
__device__ __forceinline__ uint32_t smem_to_u32(const void* smem_ptr) {
    uint32_t addr;
    asm("{ .reg .u64 tmp; cvta.to.shared.u64 tmp, %1; cvt.u32.u64 %0, tmp; }"
        : "=r"(addr) : "l"(smem_ptr));
    return addr;
}

__device__ __forceinline__ void cp_async16(uint32_t dst, const void* src) {
    asm volatile("cp.async.cg.shared.global [%0], [%1], 16;" :: "r"(dst), "l"(src));
}
#define CP_COMMIT() asm volatile("cp.async.commit_group;" ::: "memory")
#define CP_WAIT(n)  asm volatile("cp.async.wait_group %0;" :: "n"(n) : "memory")

__device__ __forceinline__ void ldsm_x4(uint32_t (&r)[4], uint32_t addr) {
    asm volatile("ldmatrix.sync.aligned.m8n8.x4.shared.b16 {%0,%1,%2,%3}, [%4];"
                 : "=r"(r[0]), "=r"(r[1]), "=r"(r[2]), "=r"(r[3]) : "r"(addr));
}
__device__ __forceinline__ void ldsm_x2(uint32_t (&r)[2], uint32_t addr) {
    asm volatile("ldmatrix.sync.aligned.m8n8.x2.shared.b16 {%0,%1}, [%2];"
                 : "=r"(r[0]), "=r"(r[1]) : "r"(addr));
}
__device__ __forceinline__ void mma_bf16(float (&d)[4], const uint32_t (&a)[4],
                                         const uint32_t (&b)[2]) {
    asm volatile("mma.sync.aligned.m16n8k16.row.col.f32.bf16.bf16.f32 "
                 "{%0,%1,%2,%3}, {%4,%5,%6,%7}, {%8,%9}, {%0,%1,%2,%3};"
                 : "+f"(d[0]), "+f"(d[1]), "+f"(d[2]), "+f"(d[3])
                 : "r"(a[0]), "r"(a[1]), "r"(a[2]), "r"(a[3]),
                   "r"(b[0]), "r"(b[1]));
}

__device__ __forceinline__ void red_add_v2(float* ptr, float x, float y) {
    asm volatile("red.global.add.v2.f32 [%0], {%1, %2};"
                 :: "l"(ptr), "f"(x), "f"(y) : "memory");
}

__device__ __forceinline__ void edge_endpoints(const int* __restrict__ ei, int e,
                                               int& src, int& dst) {
    if (e < NEDGES) { src = ei[e]; dst = ei[NEDGES + e]; }
    else            { src = e - NEDGES; dst = src; }
}

// ---------------- CSR build -------------------------------------------------
__global__ void deg_kernel(const int* __restrict__ ei, int* __restrict__ deg) {
    int t = blockIdx.x * blockDim.x + threadIdx.x;
    if (t >= ETOT) return;
    int dst = (t < NEDGES) ? ei[NEDGES + t] : t - NEDGES;
    atomicAdd(&deg[dst], 1);
}

// single-block exclusive scan; smem-staged for coalesced global traffic
#define SCAN_SMEM (NNODES * 4)
__global__ void scan_kernel(const int* __restrict__ deg,
                            int* __restrict__ rowptr,
                            int* __restrict__ cursor) {
    extern __shared__ int sdeg[];
    const int PER = 20;   // 1024 * 20 >= NNODES
    int tid = threadIdx.x;
    // coalesced stage-in
    for (int i = tid; i < NNODES; i += 1024) sdeg[i] = deg[i];
    __syncthreads();

    int base = tid * PER;
    int vals[PER];
    int sum = 0;
#pragma unroll
    for (int i = 0; i < PER; i++) {
        int idx = base + i;
        int v = (idx < NNODES) ? sdeg[idx] : 0;
        vals[i] = sum;
        sum += v;
    }
    int lane = tid & 31, wid = tid >> 5;
    int inc = sum;
#pragma unroll
    for (int off = 1; off < 32; off <<= 1) {
        int n = __shfl_up_sync(0xFFFFFFFFu, inc, off);
        if (lane >= off) inc += n;
    }
    __shared__ int wsum[32];
    if (lane == 31) wsum[wid] = inc;
    __syncthreads();
    if (tid < 32) {
        int wv = wsum[tid];
#pragma unroll
        for (int off = 1; off < 32; off <<= 1) {
            int n = __shfl_up_sync(0xFFFFFFFFu, wv, off);
            if (tid >= off) wv += n;
        }
        wsum[tid] = wv;
    }
    __syncthreads();
    int warpExcl = (wid == 0) ? 0 : wsum[wid - 1];
    int thrExcl = warpExcl + inc - sum;
#pragma unroll
    for (int i = 0; i < PER; i++) {
        int idx = base + i;
        if (idx < NNODES) sdeg[idx] = thrExcl + vals[i];
    }
    __syncthreads();
    // coalesced stage-out
    for (int i = tid; i < NNODES; i += 1024) {
        int e = sdeg[i];
        rowptr[i] = e;
        cursor[i] = e;
    }
    if (tid == 0) rowptr[NNODES] = wsum[31];
}

__global__ void scatter_kernel(const int* __restrict__ ei,
                               int* __restrict__ cursor,
                               int* __restrict__ csr) {
    int t = blockIdx.x * blockDim.x + threadIdx.x;
    if (t >= ETOT) return;
    int src, dst;
    edge_endpoints(ei, t, src, dst);
    int pos = atomicAdd(&cursor[dst], 1);
    csr[pos] = src;
}

// ---------------- bf16 split kernels ---------------------------------------
// also zeroes deg histogram and xl2/xr2 accumulators (fits in early blocks)
__global__ void xsplit_kernel(const float* __restrict__ X, int n,
                              __nv_bfloat16* __restrict__ Xh,
                              __nv_bfloat16* __restrict__ Xl,
                              int* __restrict__ deg,
                              float* __restrict__ xl2,
                              float* __restrict__ xr2) {
    int i = blockIdx.x * blockDim.x + threadIdx.x;
    if (i < NNODES) deg[i] = 0;
    if (i < NNODES * 2) { xl2[i] = 0.f; xr2[i] = 0.f; }
    if (i >= n) return;
    float v = X[i];
    __nv_bfloat16 h = __float2bfloat16(v);
    Xh[i] = h;
    Xl[i] = __float2bfloat16(v - __bfloat162float(h));
}

// All 4 weight transposes in one launch (blockIdx.z selects matrix).
// [K, 256] fp32 -> [256, K] bf16 hi/lo via 32x33 padded smem tile.
__global__ void wtrans_all_kernel(const float* __restrict__ Wl0,
                                  const float* __restrict__ Wr0,
                                  const float* __restrict__ Wl1,
                                  const float* __restrict__ Wr1,
                                  __nv_bfloat16* __restrict__ w0h,
                                  __nv_bfloat16* __restrict__ w0l,
                                  __nv_bfloat16* __restrict__ w1h,
                                  __nv_bfloat16* __restrict__ w1l) {
    int z = blockIdx.z;
    const float* W;
    __nv_bfloat16 *Wh, *Wl;
    int K;
    if (z == 0)      { W = Wl0; K = INDIM; Wh = w0h;               Wl = w0l; }
    else if (z == 1) { W = Wr0; K = INDIM; Wh = w0h + 256 * INDIM; Wl = w0l + 256 * INDIM; }
    else if (z == 2) { W = Wl1; K = HCDIM; Wh = w1h;               Wl = w1l; }
    else             { W = Wr1; K = HCDIM; Wh = w1h + 256 * HCDIM; Wl = w1l + 256 * HCDIM; }
    int k0 = blockIdx.x * 32;
    if (k0 >= K) return;
    int n0 = blockIdx.y * 32;
    __shared__ float tile[32][33];
    int tx = threadIdx.x, ty = threadIdx.y;   // (32, 8)
#pragma unroll
    for (int i = 0; i < 4; i++) {
        int k = k0 + ty + i * 8;
        tile[ty + i * 8][tx] = W[(size_t)k * HCDIM + n0 + tx];
    }
    __syncthreads();
#pragma unroll
    for (int i = 0; i < 4; i++) {
        int n = n0 + ty + i * 8;
        float v = tile[tx][ty + i * 8];
        __nv_bfloat16 h = __float2bfloat16(v);
        Wh[(size_t)n * K + k0 + tx] = h;
        Wl[(size_t)n * K + k0 + tx] = __float2bfloat16(v - __bfloat162float(h));
    }
}

// ---------------- HMMA dual GEMM (3-stage pipeline) -------------------------
#define GSTAGE 32768
#define GSMEM  (3 * GSTAGE)

__global__ void __launch_bounds__(256, 1)
hmma_dual_gemm(const __nv_bfloat16* __restrict__ Ah,
               const __nv_bfloat16* __restrict__ Al,
               const __nv_bfloat16* __restrict__ Bh,
               const __nv_bfloat16* __restrict__ Bl,
               float* __restrict__ C, int M, int K) {
    extern __shared__ char smem[];
    uint32_t sb = smem_to_u32(smem);
    int tid = threadIdx.x;
    int lane = tid & 31, wid = tid >> 5;
    int wm = wid >> 2, wn = wid & 3;
    int mBase = blockIdx.y * 128;
    int nBase = blockIdx.x * 128;
    int nq = K >> 5;

    float acc[4][4][4];
#pragma unroll
    for (int a = 0; a < 4; a++)
#pragma unroll
        for (int b = 0; b < 4; b++)
#pragma unroll
            for (int c = 0; c < 4; c++) acc[a][b][c] = 0.f;

    auto load_stage = [&](int q, int s) {
        int k0 = q << 5;
        uint32_t base = sb + s * GSTAGE;
        char* sm = smem + s * GSTAGE;
#pragma unroll
        for (int it = 0; it < 2; it++) {
            int idx = tid + it * 256;
            int r = idx >> 2, c = idx & 3;
            uint32_t dsw = r * 64 + ((c ^ (r & 3)) << 4);
            int R = mBase + r;
            if (R < M) {
                const char* sh = (const char*)(Ah + (size_t)R * K + k0) + c * 16;
                const char* sl = (const char*)(Al + (size_t)R * K + k0) + c * 16;
                cp_async16(base + dsw, sh);
                cp_async16(base + 8192 + dsw, sl);
            } else {
                uint4 z = make_uint4(0, 0, 0, 0);
                *(uint4*)(sm + dsw) = z;
                *(uint4*)(sm + 8192 + dsw) = z;
            }
        }
#pragma unroll
        for (int it = 0; it < 2; it++) {
            int idx = tid + it * 256;
            int r = idx >> 2, c = idx & 3;
            uint32_t dsw = r * 64 + ((c ^ (r & 3)) << 4);
            int NR = nBase + r;
            const char* sh = (const char*)(Bh + (size_t)NR * K + k0) + c * 16;
            const char* sl = (const char*)(Bl + (size_t)NR * K + k0) + c * 16;
            cp_async16(base + 16384 + dsw, sh);
            cp_async16(base + 24576 + dsw, sl);
        }
    };

    load_stage(0, 0); CP_COMMIT();
    load_stage(1, 1); CP_COMMIT();

    int stage = 0;
    for (int q = 0; q < nq; q++) {
        if (q + 2 < nq) {
            int s2 = stage + 2; if (s2 >= 3) s2 -= 3;
            load_stage(q + 2, s2); CP_COMMIT();
            CP_WAIT(2);
        } else if (q + 1 < nq) {
            CP_WAIT(1);
        } else {
            CP_WAIT(0);
        }
        __syncthreads();
        uint32_t base = sb + stage * GSTAGE;

#pragma unroll
        for (int step = 0; step < 2; step++) {
            uint32_t ahf[4][4], alf[4][4], bhf[4][2], blf[4][2];
            int arow = wm * 64 + (lane & 15);
            int ac = 2 * step + (lane >> 4);
#pragma unroll
            for (int mi = 0; mi < 4; mi++) {
                int r = arow + mi * 16;
                uint32_t ad = base + r * 64 + ((ac ^ (r & 3)) << 4);
                ldsm_x4(ahf[mi], ad);
                ldsm_x4(alf[mi], ad + 8192);
            }
#pragma unroll
            for (int nj = 0; nj < 4; nj++) {
                int r = wn * 32 + nj * 8 + (lane & 7);
                int bc = 2 * step + ((lane >> 3) & 1);
                uint32_t bd = base + 16384 + r * 64 + ((bc ^ (r & 3)) << 4);
                ldsm_x2(bhf[nj], bd);
                ldsm_x2(blf[nj], bd + 8192);
            }
            // product-major ordering: 16 independent accumulators between revisits
#pragma unroll
            for (int mi = 0; mi < 4; mi++)
#pragma unroll
                for (int nj = 0; nj < 4; nj++)
                    mma_bf16(acc[mi][nj], ahf[mi], bhf[nj]);
#pragma unroll
            for (int mi = 0; mi < 4; mi++)
#pragma unroll
                for (int nj = 0; nj < 4; nj++)
                    mma_bf16(acc[mi][nj], ahf[mi], blf[nj]);
#pragma unroll
            for (int mi = 0; mi < 4; mi++)
#pragma unroll
                for (int nj = 0; nj < 4; nj++)
                    mma_bf16(acc[mi][nj], alf[mi], bhf[nj]);
        }
        __syncthreads();
        if (++stage == 3) stage = 0;
    }

    int rBase = mBase + wm * 64;
    int cBase = nBase + wn * 32;
#pragma unroll
    for (int mi = 0; mi < 4; mi++) {
        int r0 = rBase + mi * 16 + (lane >> 2);
#pragma unroll
        for (int nj = 0; nj < 4; nj++) {
            int cc = cBase + nj * 8 + 2 * (lane & 3);
            if (r0 < M)
                *(float2*)(C + (size_t)r0 * NOUT + cc) =
                    make_float2(acc[mi][nj][0], acc[mi][nj][1]);
            if (r0 + 8 < M)
                *(float2*)(C + (size_t)(r0 + 8) * NOUT + cc) =
                    make_float2(acc[mi][nj][2], acc[mi][nj][3]);
        }
    }
}

// ---------------- fused GATv2 layer (score + softmax-agg + BN + ELU) --------
// TWO warps per node (warp half = 2 heads = 128 channels); lane owns 4 channels.
// Optionally fuses the layer-2 projection (h @ Wl2 / Wr2, 256->2) into the
// epilogue via per-lane dot + warp reduce + one red.add.v2 per warp.
__global__ void node_gat_kernel(const int* __restrict__ rowptr,
                                const int* __restrict__ csr,
                                const float* __restrict__ xlr,
                                const float* __restrict__ att,
                                const float* __restrict__ b,
                                const float* __restrict__ g,
                                const float* __restrict__ be,
                                const float* __restrict__ m,
                                const float* __restrict__ v,
                                float* __restrict__ hout,
                                __nv_bfloat16* __restrict__ outh,
                                __nv_bfloat16* __restrict__ outl,
                                const float* __restrict__ Wl2,
                                const float* __restrict__ Wr2,
                                float* __restrict__ xl2,
                                float* __restrict__ xr2,
                                int doProj) {
    int gw = (blockIdx.x * blockDim.x + threadIdx.x) >> 5;
    int w = gw >> 1;
    if (w >= NNODES) return;
    int half = gw & 1;
    int lane = threadIdx.x & 31;
    int col = half * 128 + lane * 4;
    int p0 = rowptr[w], p1 = rowptr[w + 1];

    float4 r4 = *(const float4*)(xlr + (size_t)w * NOUT + 256 + col);
    float4 a4 = *(const float4*)(att + col);
    float4 acc = make_float4(0.f, 0.f, 0.f, 0.f);
    float dsum = 0.f;

    for (int base = p0; base < p1; base += 32) {
        int se = 0;
        if (base + lane < p1) se = csr[base + lane];
        int cnt = min(32, p1 - base);
        int j = 0;
        for (; j + 2 <= cnt; j += 2) {
            int s0 = __shfl_sync(0xFFFFFFFFu, se, j);
            int s1 = __shfl_sync(0xFFFFFFFFu, se, j + 1);
            float4 v0 = *(const float4*)(xlr + (size_t)s0 * NOUT + col);
            float4 v1 = *(const float4*)(xlr + (size_t)s1 * NOUT + col);
            float sc0, sc1, mv;
            mv = v0.x + r4.x; mv = mv > 0.f ? mv : 0.2f * mv; sc0  = mv * a4.x;
            mv = v0.y + r4.y; mv = mv > 0.f ? mv : 0.2f * mv; sc0 += mv * a4.y;
            mv = v0.z + r4.z; mv = mv > 0.f ? mv : 0.2f * mv; sc0 += mv * a4.z;
            mv = v0.w + r4.w; mv = mv > 0.f ? mv : 0.2f * mv; sc0 += mv * a4.w;
            mv = v1.x + r4.x; mv = mv > 0.f ? mv : 0.2f * mv; sc1  = mv * a4.x;
            mv = v1.y + r4.y; mv = mv > 0.f ? mv : 0.2f * mv; sc1 += mv * a4.y;
            mv = v1.z + r4.z; mv = mv > 0.f ? mv : 0.2f * mv; sc1 += mv * a4.z;
            mv = v1.w + r4.w; mv = mv > 0.f ? mv : 0.2f * mv; sc1 += mv * a4.w;
#pragma unroll
            for (int off = 1; off < 16; off <<= 1) {
                sc0 += __shfl_xor_sync(0xFFFFFFFFu, sc0, off);
                sc1 += __shfl_xor_sync(0xFFFFFFFFu, sc1, off);
            }
            float e0 = __expf(sc0), e1 = __expf(sc1);
            acc.x += e0 * v0.x + e1 * v1.x;
            acc.y += e0 * v0.y + e1 * v1.y;
            acc.z += e0 * v0.z + e1 * v1.z;
            acc.w += e0 * v0.w + e1 * v1.w;
            dsum += e0 + e1;
        }
        if (j < cnt) {
            int s0 = __shfl_sync(0xFFFFFFFFu, se, j);
            float4 v0 = *(const float4*)(xlr + (size_t)s0 * NOUT + col);
            float sc0, mv;
            mv = v0.x + r4.x; mv = mv > 0.f ? mv : 0.2f * mv; sc0  = mv * a4.x;
            mv = v0.y + r4.y; mv = mv > 0.f ? mv : 0.2f * mv; sc0 += mv * a4.y;
            mv = v0.z + r4.z; mv = mv > 0.f ? mv : 0.2f * mv; sc0 += mv * a4.z;
            mv = v0.w + r4.w; mv = mv > 0.f ? mv : 0.2f * mv; sc0 += mv * a4.w;
#pragma unroll
            for (int off = 1; off < 16; off <<= 1)
                sc0 += __shfl_xor_sync(0xFFFFFFFFu, sc0, off);
            float e0 = __expf(sc0);
            acc.x += e0 * v0.x; acc.y += e0 * v0.y;
            acc.z += e0 * v0.z; acc.w += e0 * v0.w;
            dsum += e0;
        }
    }
    float inv = 1.f / (dsum + 1e-16f);

    float4 b4 = *(const float4*)(b + col);
    float4 g4 = *(const float4*)(g + col);
    float4 e4 = *(const float4*)(be + col);
    float4 m4 = *(const float4*)(m + col);
    float4 v4 = *(const float4*)(v + col);

    float o[4];
    o[0] = acc.x * inv + b4.x; o[1] = acc.y * inv + b4.y;
    o[2] = acc.z * inv + b4.z; o[3] = acc.w * inv + b4.w;
    float gg[4] = {g4.x, g4.y, g4.z, g4.w};
    float ee[4] = {e4.x, e4.y, e4.z, e4.w};
    float mm[4] = {m4.x, m4.y, m4.z, m4.w};
    float vv[4] = {v4.x, v4.y, v4.z, v4.w};
#pragma unroll
    for (int i = 0; i < 4; i++) {
        float x = (o[i] - mm[i]) * (gg[i] * rsqrtf(vv[i] + EPS_BN)) + ee[i];
        x = x > 0.f ? x : (expf(x) - 1.0f);
        o[i] = x;
    }
    *(float4*)(hout + (size_t)w * HCDIM + col) = make_float4(o[0], o[1], o[2], o[3]);

    union { uint2 u; __nv_bfloat162 p[2]; } ph, pl;
#pragma unroll
    for (int i = 0; i < 2; i++) {
        __nv_bfloat16 h0 = __float2bfloat16(o[2 * i]);
        __nv_bfloat16 h1 = __float2bfloat16(o[2 * i + 1]);
        ph.p[i] = __nv_bfloat162(h0, h1);
        pl.p[i] = __nv_bfloat162(
            __float2bfloat16(o[2 * i] - __bfloat162float(h0)),
            __float2bfloat16(o[2 * i + 1] - __bfloat162float(h1)));
    }
    *(uint2*)(outh + (size_t)w * HCDIM + col) = ph.u;
    *(uint2*)(outl + (size_t)w * HCDIM + col) = pl.u;

    // fused layer-2 projection: partial dot over this lane's 4 channels
    if (doProj) {
        float l0 = 0.f, l1 = 0.f, q0 = 0.f, q1 = 0.f;
#pragma unroll
        for (int i = 0; i < 4; i++) {
            float2 wl = *(const float2*)(Wl2 + (col + i) * 2);
            float2 wr = *(const float2*)(Wr2 + (col + i) * 2);
            l0 += o[i] * wl.x; l1 += o[i] * wl.y;
            q0 += o[i] * wr.x; q1 += o[i] * wr.y;
        }
#pragma unroll
        for (int off = 16; off; off >>= 1) {
            l0 += __shfl_xor_sync(0xFFFFFFFFu, l0, off);
            l1 += __shfl_xor_sync(0xFFFFFFFFu, l1, off);
            q0 += __shfl_xor_sync(0xFFFFFFFFu, q0, off);
            q1 += __shfl_xor_sync(0xFFFFFFFFu, q1, off);
        }
        if (lane == 0) {
            red_add_v2(xl2 + w * 2, l0, l1);
            red_add_v2(xr2 + w * 2, q0, q1);
        }
    }
}

// Fused: scores + softmax-agg + bias + log_softmax. Warp per node, lane/edge.
__global__ void node_gat2_kernel(const int* __restrict__ rowptr,
                                 const int* __restrict__ csr,
                                 const float* __restrict__ xl2,
                                 const float* __restrict__ xr2,
                                 const float* __restrict__ att2,
                                 const float* __restrict__ b2,
                                 float* __restrict__ out) {
    int w = (blockIdx.x * blockDim.x + threadIdx.x) >> 5;
    int lane = threadIdx.x & 31;
    if (w >= NNODES) return;
    int p0 = rowptr[w], p1 = rowptr[w + 1];
    float2 r = *(const float2*)(xr2 + w * 2);
    float a0 = att2[0], a1 = att2[1];
    float s0 = 0.f, s1 = 0.f, ds = 0.f;
    for (int p = p0 + lane; p < p1; p += 32) {
        int src = csr[p];
        float2 l = *(const float2*)(xl2 + src * 2);
        float mx = l.x + r.x, my = l.y + r.y;
        mx = mx > 0.f ? mx : 0.2f * mx;
        my = my > 0.f ? my : 0.2f * my;
        float ex = __expf(mx * a0 + my * a1);
        s0 += ex * l.x; s1 += ex * l.y; ds += ex;
    }
#pragma unroll
    for (int off = 16; off; off >>= 1) {
        s0 += __shfl_xor_sync(0xFFFFFFFFu, s0, off);
        s1 += __shfl_xor_sync(0xFFFFFFFFu, s1, off);
        ds += __shfl_xor_sync(0xFFFFFFFFu, ds, off);
    }
    if (lane == 0) {
        float inv = 1.f / (ds + 1e-16f);
        float o0 = s0 * inv + b2[0];
        float o1 = s1 * inv + b2[1];
        float mx = fmaxf(o0, o1);
        float lse = mx + logf(expf(o0 - mx) + expf(o1 - mx));
        *(float2*)(out + w * 2) = make_float2(o0 - lse, o1 - lse);
    }
}

// ---------------- launch ---------------------------------------------------
extern "C" void kernel_launch(void* const* d_in, const int* in_sizes, int n_in,
                              void* d_out, int out_size) {
    const float* x   = (const float*)d_in[0];
    const int*   ei  = (const int*)d_in[1];
    const float* Wl0 = (const float*)d_in[2];
    const float* Wr0 = (const float*)d_in[3];
    const float* att0= (const float*)d_in[4];
    const float* b0  = (const float*)d_in[5];
    const float* g0  = (const float*)d_in[6];
    const float* be0 = (const float*)d_in[7];
    const float* m0  = (const float*)d_in[8];
    const float* v0  = (const float*)d_in[9];
    const float* Wl1 = (const float*)d_in[10];
    const float* Wr1 = (const float*)d_in[11];
    const float* att1= (const float*)d_in[12];
    const float* b1  = (const float*)d_in[13];
    const float* g1  = (const float*)d_in[14];
    const float* be1 = (const float*)d_in[15];
    const float* m1  = (const float*)d_in[16];
    const float* v1  = (const float*)d_in[17];
    const float* Wl2 = (const float*)d_in[18];
    const float* Wr2 = (const float*)d_in[19];
    const float* att2= (const float*)d_in[20];
    const float* b2  = (const float*)d_in[21];
    float* out = (float*)d_out;

    float *p_xlr, *p_h, *p_xl2, *p_xr2;
    int *p_deg, *p_cursor, *p_rowptr, *p_csr;
    __nv_bfloat16 *p_xhi, *p_xlo, *p_hhi, *p_hlo;
    __nv_bfloat16 *p_w0h, *p_w0l, *p_w1h, *p_w1l;
    cudaGetSymbolAddress((void**)&p_xlr, g_xlr);
    cudaGetSymbolAddress((void**)&p_h, g_h);
    cudaGetSymbolAddress((void**)&p_xl2, g_xl2);
    cudaGetSymbolAddress((void**)&p_xr2, g_xr2);
    cudaGetSymbolAddress((void**)&p_deg, g_deg);
    cudaGetSymbolAddress((void**)&p_cursor, g_cursor);
    cudaGetSymbolAddress((void**)&p_rowptr, g_rowptr);
    cudaGetSymbolAddress((void**)&p_csr, g_csr);
    cudaGetSymbolAddress((void**)&p_xhi, g_xhi);
    cudaGetSymbolAddress((void**)&p_xlo, g_xlo);
    cudaGetSymbolAddress((void**)&p_hhi, g_hhi);
    cudaGetSymbolAddress((void**)&p_hlo, g_hlo);
    cudaGetSymbolAddress((void**)&p_w0h, g_w0h);
    cudaGetSymbolAddress((void**)&p_w0l, g_w0l);
    cudaGetSymbolAddress((void**)&p_w1h, g_w1h);
    cudaGetSymbolAddress((void**)&p_w1l, g_w1l);

    cudaFuncSetAttribute(hmma_dual_gemm,
                         cudaFuncAttributeMaxDynamicSharedMemorySize, GSMEM);
    cudaFuncSetAttribute(scan_kernel,
                         cudaFuncAttributeMaxDynamicSharedMemorySize, SCAN_SMEM);

    int eBlocks = (ETOT + 255) / 256;
    int nodeWarpBlocks = (NNODES * 32 + 255) / 256;
    int node2WarpBlocks = (NNODES * 64 + 255) / 256;
    dim3 gemmGrid(NOUT / 128, (NNODES + 127) / 128);
    dim3 wtB(32, 8);

    // ===== prep: bf16 splits (+zeroing) + merged wtrans + CSR build =====
    xsplit_kernel<<<(NNODES * INDIM + 255) / 256, 256>>>(x, NNODES * INDIM,
                                                         p_xhi, p_xlo, p_deg,
                                                         p_xl2, p_xr2);
    wtrans_all_kernel<<<dim3(INDIM / 32, 8, 4), wtB>>>(Wl0, Wr0, Wl1, Wr1,
                                                       p_w0h, p_w0l, p_w1h, p_w1l);
    deg_kernel<<<eBlocks, 256>>>(ei, p_deg);
    scan_kernel<<<1, 1024, SCAN_SMEM>>>(p_deg, p_rowptr, p_cursor);
    scatter_kernel<<<eBlocks, 256>>>(ei, p_cursor, p_csr);

    // ===== Layer 0 =====
    hmma_dual_gemm<<<gemmGrid, 256, GSMEM>>>(p_xhi, p_xlo, p_w0h, p_w0l,
                                             p_xlr, NNODES, INDIM);
    node_gat_kernel<<<node2WarpBlocks, 256>>>(p_rowptr, p_csr, p_xlr, att0,
                                              b0, g0, be0, m0, v0,
                                              p_h, p_hhi, p_hlo,
                                              nullptr, nullptr, nullptr, nullptr, 0);

    // ===== Layer 1 (+ fused layer-2 projection) =====
    hmma_dual_gemm<<<gemmGrid, 256, GSMEM>>>(p_hhi, p_hlo, p_w1h, p_w1l,
                                             p_xlr, NNODES, HCDIM);
    node_gat_kernel<<<node2WarpBlocks, 256>>>(p_rowptr, p_csr, p_xlr, att1,
                                              b1, g1, be1, m1, v1,
                                              p_h, p_hhi, p_hlo,
                                              Wl2, Wr2, p_xl2, p_xr2, 1);

    // ===== Layer 2 =====
    node_gat2_kernel<<<nodeWarpBlocks, 256>>>(p_rowptr, p_csr, p_xl2, p_xr2,
                                              att2, b2, out);
}

// round 16
// speedup vs baseline: 3.4221x; 1.0560x over previous
#include <cuda_runtime.h>
#include <cuda_bf16.h>
#include <math.h>
#include <stdint.h>

// Problem constants (fixed by reference)
#define NNODES 20000
#define NEDGES 320000
#define ETOT   340000   // NEDGES + NNODES self loops
#define INDIM  512
#define NHEAD  4
#define CDIM   64
#define HCDIM  256
#define NOUT   512      // dual-GEMM output width (xl | xr)
#define EPS_BN 1e-5f

// ---------------- scratch (device globals; no allocation allowed) ----------
__device__ float g_xlr[NNODES * NOUT];   // cols 0-255: xl, 256-511: xr
__device__ float g_h[NNODES * HCDIM];
__device__ float g_xl2[NNODES * 2];
__device__ float g_xr2[NNODES * 2];

// CSR by destination (src only)
__device__ int g_deg[NNODES];
__device__ int g_cursor[NNODES];
__device__ int g_rowptr[NNODES + 1];
__device__ int g_csr[ETOT];

// bf16 hi/lo split buffers for tensor-core GEMMs
__device__ __nv_bfloat16 g_xhi[NNODES * INDIM];
__device__ __nv_bfloat16 g_xlo[NNODES * INDIM];
__device__ __nv_bfloat16 g_hhi[NNODES * HCDIM];
__device__ __nv_bfloat16 g_hlo[NNODES * HCDIM];
// concatenated, transposed (N-major, K-contiguous) weight splits: [512, K]
__device__ __nv_bfloat16 g_w0h[NOUT * INDIM];
__device__ __nv_bfloat16 g_w0l[NOUT * INDIM];
__device__ __nv_bfloat16 g_w1h[NOUT * HCDIM];
__device__ __nv_bfloat16 g_w1l[NOUT * HCDIM];

// ---------------- PTX helpers ----------------------------------------------
__device__ __forceinline__ uint32_t smem_to_u32(const void* smem_ptr) {
    uint32_t addr;
    asm("{ .reg .u64 tmp; cvta.to.shared.u64 tmp, %1; cvt.u32.u64 %0, tmp; }"
        : "=r"(addr) : "l"(smem_ptr));
    return addr;
}

__device__ __forceinline__ void cp_async16(uint32_t dst, const void* src) {
    asm volatile("cp.async.cg.shared.global [%0], [%1], 16;" :: "r"(dst), "l"(src));
}
#define CP_COMMIT() asm volatile("cp.async.commit_group;" ::: "memory")
#define CP_WAIT(n)  asm volatile("cp.async.wait_group %0;" :: "n"(n) : "memory")

__device__ __forceinline__ void ldsm_x4(uint32_t (&r)[4], uint32_t addr) {
    asm volatile("ldmatrix.sync.aligned.m8n8.x4.shared.b16 {%0,%1,%2,%3}, [%4];"
                 : "=r"(r[0]), "=r"(r[1]), "=r"(r[2]), "=r"(r[3]) : "r"(addr));
}
__device__ __forceinline__ void ldsm_x2(uint32_t (&r)[2], uint32_t addr) {
    asm volatile("ldmatrix.sync.aligned.m8n8.x2.shared.b16 {%0,%1}, [%2];"
                 : "=r"(r[0]), "=r"(r[1]) : "r"(addr));
}
__device__ __forceinline__ void mma_bf16(float (&d)[4], const uint32_t (&a)[4],
                                         const uint32_t (&b)[2]) {
    asm volatile("mma.sync.aligned.m16n8k16.row.col.f32.bf16.bf16.f32 "
                 "{%0,%1,%2,%3}, {%4,%5,%6,%7}, {%8,%9}, {%0,%1,%2,%3};"
                 : "+f"(d[0]), "+f"(d[1]), "+f"(d[2]), "+f"(d[3])
                 : "r"(a[0]), "r"(a[1]), "r"(a[2]), "r"(a[3]),
                   "r"(b[0]), "r"(b[1]));
}

__device__ __forceinline__ void red_add_v2(float* ptr, float x, float y) {
    asm volatile("red.global.add.v2.f32 [%0], {%1, %2};"
                 :: "l"(ptr), "f"(x), "f"(y) : "memory");
}

__device__ __forceinline__ void edge_endpoints(const int* __restrict__ ei, int e,
                                               int& src, int& dst) {
    if (e < NEDGES) { src = ei[e]; dst = ei[NEDGES + e]; }
    else            { src = e - NEDGES; dst = src; }
}

// ---------------- CSR build -------------------------------------------------
__global__ void deg_kernel(const int* __restrict__ ei, int* __restrict__ deg) {
    int t = blockIdx.x * blockDim.x + threadIdx.x;
    if (t >= ETOT) return;
    int dst = (t < NEDGES) ? ei[NEDGES + t] : t - NEDGES;
    atomicAdd(&deg[dst], 1);
}

// single-block exclusive scan; smem-staged, two-pass (no local-array spill)
#define SCAN_SMEM (NNODES * 4)
__global__ void scan_kernel(const int* __restrict__ deg,
                            int* __restrict__ rowptr,
                            int* __restrict__ cursor) {
    extern __shared__ int sdeg[];
    const int PER = 20;   // 1024 * 20 >= NNODES
    int tid = threadIdx.x;
    for (int i = tid; i < NNODES; i += 1024) sdeg[i] = deg[i];
    __syncthreads();

    int base = tid * PER;
    int lim = min(base + PER, NNODES);
    // pass 1: per-thread sum
    int sum = 0;
    for (int idx = base; idx < lim; idx++) sum += sdeg[idx];

    int lane = tid & 31, wid = tid >> 5;
    int inc = sum;
#pragma unroll
    for (int off = 1; off < 32; off <<= 1) {
        int n = __shfl_up_sync(0xFFFFFFFFu, inc, off);
        if (lane >= off) inc += n;
    }
    __shared__ int wsum[32];
    if (lane == 31) wsum[wid] = inc;
    __syncthreads();
    if (tid < 32) {
        int wv = wsum[tid];
#pragma unroll
        for (int off = 1; off < 32; off <<= 1) {
            int n = __shfl_up_sync(0xFFFFFFFFu, wv, off);
            if (tid >= off) wv += n;
        }
        wsum[tid] = wv;
    }
    __syncthreads();
    int warpExcl = (wid == 0) ? 0 : wsum[wid - 1];
    int run = warpExcl + inc - sum;
    int total = wsum[31];
    // pass 2: rewrite smem in place with exclusive positions
    for (int idx = base; idx < lim; idx++) {
        int v = sdeg[idx];
        sdeg[idx] = run;
        run += v;
    }
    __syncthreads();
    for (int i = tid; i < NNODES; i += 1024) {
        int e = sdeg[i];
        rowptr[i] = e;
        cursor[i] = e;
    }
    if (tid == 0) rowptr[NNODES] = total;
}

__global__ void scatter_kernel(const int* __restrict__ ei,
                               int* __restrict__ cursor,
                               int* __restrict__ csr) {
    int t = blockIdx.x * blockDim.x + threadIdx.x;
    if (t >= ETOT) return;
    int src, dst;
    edge_endpoints(ei, t, src, dst);
    int pos = atomicAdd(&cursor[dst], 1);
    csr[pos] = src;
}

// ---------------- bf16 split kernels ---------------------------------------
// also zeroes deg histogram and xl2/xr2 accumulators (fits in early blocks)
__global__ void xsplit_kernel(const float* __restrict__ X, int n,
                              __nv_bfloat16* __restrict__ Xh,
                              __nv_bfloat16* __restrict__ Xl,
                              int* __restrict__ deg,
                              float* __restrict__ xl2,
                              float* __restrict__ xr2) {
    int i = blockIdx.x * blockDim.x + threadIdx.x;
    if (i < NNODES) deg[i] = 0;
    if (i < NNODES * 2) { xl2[i] = 0.f; xr2[i] = 0.f; }
    if (i >= n) return;
    float v = X[i];
    __nv_bfloat16 h = __float2bfloat16(v);
    Xh[i] = h;
    Xl[i] = __float2bfloat16(v - __bfloat162float(h));
}

// All 4 weight transposes in one launch (blockIdx.z selects matrix).
// [K, 256] fp32 -> [256, K] bf16 hi/lo via 32x33 padded smem tile.
__global__ void wtrans_all_kernel(const float* __restrict__ Wl0,
                                  const float* __restrict__ Wr0,
                                  const float* __restrict__ Wl1,
                                  const float* __restrict__ Wr1,
                                  __nv_bfloat16* __restrict__ w0h,
                                  __nv_bfloat16* __restrict__ w0l,
                                  __nv_bfloat16* __restrict__ w1h,
                                  __nv_bfloat16* __restrict__ w1l) {
    int z = blockIdx.z;
    const float* W;
    __nv_bfloat16 *Wh, *Wl;
    int K;
    if (z == 0)      { W = Wl0; K = INDIM; Wh = w0h;               Wl = w0l; }
    else if (z == 1) { W = Wr0; K = INDIM; Wh = w0h + 256 * INDIM; Wl = w0l + 256 * INDIM; }
    else if (z == 2) { W = Wl1; K = HCDIM; Wh = w1h;               Wl = w1l; }
    else             { W = Wr1; K = HCDIM; Wh = w1h + 256 * HCDIM; Wl = w1l + 256 * HCDIM; }
    int k0 = blockIdx.x * 32;
    if (k0 >= K) return;
    int n0 = blockIdx.y * 32;
    __shared__ float tile[32][33];
    int tx = threadIdx.x, ty = threadIdx.y;   // (32, 8)
#pragma unroll
    for (int i = 0; i < 4; i++) {
        int k = k0 + ty + i * 8;
        tile[ty + i * 8][tx] = W[(size_t)k * HCDIM + n0 + tx];
    }
    __syncthreads();
#pragma unroll
    for (int i = 0; i < 4; i++) {
        int n = n0 + ty + i * 8;
        float v = tile[tx][ty + i * 8];
        __nv_bfloat16 h = __float2bfloat16(v);
        Wh[(size_t)n * K + k0 + tx] = h;
        Wl[(size_t)n * K + k0 + tx] = __float2bfloat16(v - __bfloat162float(h));
    }
}

// ---------------- HMMA dual GEMM (3-stage pipeline, 2 CTAs/SM) --------------
#define GSTAGE 32768
#define GSMEM  (3 * GSTAGE)

__global__ void __launch_bounds__(256, 2)
hmma_dual_gemm(const __nv_bfloat16* __restrict__ Ah,
               const __nv_bfloat16* __restrict__ Al,
               const __nv_bfloat16* __restrict__ Bh,
               const __nv_bfloat16* __restrict__ Bl,
               float* __restrict__ C, int M, int K) {
    extern __shared__ char smem[];
    uint32_t sb = smem_to_u32(smem);
    int tid = threadIdx.x;
    int lane = tid & 31, wid = tid >> 5;
    int wm = wid >> 2, wn = wid & 3;
    int mBase = blockIdx.y * 128;
    int nBase = blockIdx.x * 128;
    int nq = K >> 5;

    float acc[4][4][4];
#pragma unroll
    for (int a = 0; a < 4; a++)
#pragma unroll
        for (int b = 0; b < 4; b++)
#pragma unroll
            for (int c = 0; c < 4; c++) acc[a][b][c] = 0.f;

    auto load_stage = [&](int q, int s) {
        int k0 = q << 5;
        uint32_t base = sb + s * GSTAGE;
        char* sm = smem + s * GSTAGE;
#pragma unroll
        for (int it = 0; it < 2; it++) {
            int idx = tid + it * 256;
            int r = idx >> 2, c = idx & 3;
            uint32_t dsw = r * 64 + ((c ^ (r & 3)) << 4);
            int R = mBase + r;
            if (R < M) {
                const char* sh = (const char*)(Ah + (size_t)R * K + k0) + c * 16;
                const char* sl = (const char*)(Al + (size_t)R * K + k0) + c * 16;
                cp_async16(base + dsw, sh);
                cp_async16(base + 8192 + dsw, sl);
            } else {
                uint4 z = make_uint4(0, 0, 0, 0);
                *(uint4*)(sm + dsw) = z;
                *(uint4*)(sm + 8192 + dsw) = z;
            }
        }
#pragma unroll
        for (int it = 0; it < 2; it++) {
            int idx = tid + it * 256;
            int r = idx >> 2, c = idx & 3;
            uint32_t dsw = r * 64 + ((c ^ (r & 3)) << 4);
            int NR = nBase + r;
            const char* sh = (const char*)(Bh + (size_t)NR * K + k0) + c * 16;
            const char* sl = (const char*)(Bl + (size_t)NR * K + k0) + c * 16;
            cp_async16(base + 16384 + dsw, sh);
            cp_async16(base + 24576 + dsw, sl);
        }
    };

    load_stage(0, 0); CP_COMMIT();
    load_stage(1, 1); CP_COMMIT();

    int stage = 0;
    for (int q = 0; q < nq; q++) {
        if (q + 2 < nq) {
            int s2 = stage + 2; if (s2 >= 3) s2 -= 3;
            load_stage(q + 2, s2); CP_COMMIT();
            CP_WAIT(2);
        } else if (q + 1 < nq) {
            CP_WAIT(1);
        } else {
            CP_WAIT(0);
        }
        __syncthreads();
        uint32_t base = sb + stage * GSTAGE;

#pragma unroll
        for (int step = 0; step < 2; step++) {
            uint32_t ahf[4][4], alf[4][4], bhf[4][2], blf[4][2];
            int arow = wm * 64 + (lane & 15);
            int ac = 2 * step + (lane >> 4);
#pragma unroll
            for (int mi = 0; mi < 4; mi++) {
                int r = arow + mi * 16;
                uint32_t ad = base + r * 64 + ((ac ^ (r & 3)) << 4);
                ldsm_x4(ahf[mi], ad);
                ldsm_x4(alf[mi], ad + 8192);
            }
#pragma unroll
            for (int nj = 0; nj < 4; nj++) {
                int r = wn * 32 + nj * 8 + (lane & 7);
                int bc = 2 * step + ((lane >> 3) & 1);
                uint32_t bd = base + 16384 + r * 64 + ((bc ^ (r & 3)) << 4);
                ldsm_x2(bhf[nj], bd);
                ldsm_x2(blf[nj], bd + 8192);
            }
            // product-major ordering: 16 independent accumulators between revisits
#pragma unroll
            for (int mi = 0; mi < 4; mi++)
#pragma unroll
                for (int nj = 0; nj < 4; nj++)
                    mma_bf16(acc[mi][nj], ahf[mi], bhf[nj]);
#pragma unroll
            for (int mi = 0; mi < 4; mi++)
#pragma unroll
                for (int nj = 0; nj < 4; nj++)
                    mma_bf16(acc[mi][nj], ahf[mi], blf[nj]);
#pragma unroll
            for (int mi = 0; mi < 4; mi++)
#pragma unroll
                for (int nj = 0; nj < 4; nj++)
                    mma_bf16(acc[mi][nj], alf[mi], bhf[nj]);
        }
        __syncthreads();
        if (++stage == 3) stage = 0;
    }

    int rBase = mBase + wm * 64;
    int cBase = nBase + wn * 32;
#pragma unroll
    for (int mi = 0; mi < 4; mi++) {
        int r0 = rBase + mi * 16 + (lane >> 2);
#pragma unroll
        for (int nj = 0; nj < 4; nj++) {
            int cc = cBase + nj * 8 + 2 * (lane & 3);
            if (r0 < M)
                *(float2*)(C + (size_t)r0 * NOUT + cc) =
                    make_float2(acc[mi][nj][0], acc[mi][nj][1]);
            if (r0 + 8 < M)
                *(float2*)(C + (size_t)(r0 + 8) * NOUT + cc) =
                    make_float2(acc[mi][nj][2], acc[mi][nj][3]);
        }
    }
}

// ---------------- fused GATv2 layer (score + softmax-agg + BN + ELU) --------
// TWO warps per node (warp half = 2 heads = 128 channels); lane owns 4 channels.
// Optionally fuses the layer-2 projection (h @ Wl2 / Wr2, 256->2) into the
// epilogue via per-lane dot + warp reduce + one red.add.v2 per warp.
__global__ void node_gat_kernel(const int* __restrict__ rowptr,
                                const int* __restrict__ csr,
                                const float* __restrict__ xlr,
                                const float* __restrict__ att,
                                const float* __restrict__ b,
                                const float* __restrict__ g,
                                const float* __restrict__ be,
                                const float* __restrict__ m,
                                const float* __restrict__ v,
                                float* __restrict__ hout,
                                __nv_bfloat16* __restrict__ outh,
                                __nv_bfloat16* __restrict__ outl,
                                const float* __restrict__ Wl2,
                                const float* __restrict__ Wr2,
                                float* __restrict__ xl2,
                                float* __restrict__ xr2,
                                int doProj) {
    int gw = (blockIdx.x * blockDim.x + threadIdx.x) >> 5;
    int w = gw >> 1;
    if (w >= NNODES) return;
    int half = gw & 1;
    int lane = threadIdx.x & 31;
    int col = half * 128 + lane * 4;
    int p0 = rowptr[w], p1 = rowptr[w + 1];

    float4 r4 = *(const float4*)(xlr + (size_t)w * NOUT + 256 + col);
    float4 a4 = *(const float4*)(att + col);
    float4 acc = make_float4(0.f, 0.f, 0.f, 0.f);
    float dsum = 0.f;

    for (int base = p0; base < p1; base += 32) {
        int se = 0;
        if (base + lane < p1) se = csr[base + lane];
        int cnt = min(32, p1 - base);
        int j = 0;
        for (; j + 2 <= cnt; j += 2) {
            int s0 = __shfl_sync(0xFFFFFFFFu, se, j);
            int s1 = __shfl_sync(0xFFFFFFFFu, se, j + 1);
            float4 v0 = *(const float4*)(xlr + (size_t)s0 * NOUT + col);
            float4 v1 = *(const float4*)(xlr + (size_t)s1 * NOUT + col);
            float sc0, sc1, mv;
            mv = v0.x + r4.x; mv = mv > 0.f ? mv : 0.2f * mv; sc0  = mv * a4.x;
            mv = v0.y + r4.y; mv = mv > 0.f ? mv : 0.2f * mv; sc0 += mv * a4.y;
            mv = v0.z + r4.z; mv = mv > 0.f ? mv : 0.2f * mv; sc0 += mv * a4.z;
            mv = v0.w + r4.w; mv = mv > 0.f ? mv : 0.2f * mv; sc0 += mv * a4.w;
            mv = v1.x + r4.x; mv = mv > 0.f ? mv : 0.2f * mv; sc1  = mv * a4.x;
            mv = v1.y + r4.y; mv = mv > 0.f ? mv : 0.2f * mv; sc1 += mv * a4.y;
            mv = v1.z + r4.z; mv = mv > 0.f ? mv : 0.2f * mv; sc1 += mv * a4.z;
            mv = v1.w + r4.w; mv = mv > 0.f ? mv : 0.2f * mv; sc1 += mv * a4.w;
#pragma unroll
            for (int off = 1; off < 16; off <<= 1) {
                sc0 += __shfl_xor_sync(0xFFFFFFFFu, sc0, off);
                sc1 += __shfl_xor_sync(0xFFFFFFFFu, sc1, off);
            }
            float e0 = __expf(sc0), e1 = __expf(sc1);
            acc.x += e0 * v0.x + e1 * v1.x;
            acc.y += e0 * v0.y + e1 * v1.y;
            acc.z += e0 * v0.z + e1 * v1.z;
            acc.w += e0 * v0.w + e1 * v1.w;
            dsum += e0 + e1;
        }
        if (j < cnt) {
            int s0 = __shfl_sync(0xFFFFFFFFu, se, j);
            float4 v0 = *(const float4*)(xlr + (size_t)s0 * NOUT + col);
            float sc0, mv;
            mv = v0.x + r4.x; mv = mv > 0.f ? mv : 0.2f * mv; sc0  = mv * a4.x;
            mv = v0.y + r4.y; mv = mv > 0.f ? mv : 0.2f * mv; sc0 += mv * a4.y;
            mv = v0.z + r4.z; mv = mv > 0.f ? mv : 0.2f * mv; sc0 += mv * a4.z;
            mv = v0.w + r4.w; mv = mv > 0.f ? mv : 0.2f * mv; sc0 += mv * a4.w;
#pragma unroll
            for (int off = 1; off < 16; off <<= 1)
                sc0 += __shfl_xor_sync(0xFFFFFFFFu, sc0, off);
            float e0 = __expf(sc0);
            acc.x += e0 * v0.x; acc.y += e0 * v0.y;
            acc.z += e0 * v0.z; acc.w += e0 * v0.w;
            dsum += e0;
        }
    }
    float inv = 1.f / (dsum + 1e-16f);

    float4 b4 = *(const float4*)(b + col);
    float4 g4 = *(const float4*)(g + col);
    float4 e4 = *(const float4*)(be + col);
    float4 m4 = *(const float4*)(m + col);
    float4 v4 = *(const float4*)(v + col);

    float o[4];
    o[0] = acc.x * inv + b4.x; o[1] = acc.y * inv + b4.y;
    o[2] = acc.z * inv + b4.z; o[3] = acc.w * inv + b4.w;
    float gg[4] = {g4.x, g4.y, g4.z, g4.w};
    float ee[4] = {e4.x, e4.y, e4.z, e4.w};
    float mm[4] = {m4.x, m4.y, m4.z, m4.w};
    float vv[4] = {v4.x, v4.y, v4.z, v4.w};
#pragma unroll
    for (int i = 0; i < 4; i++) {
        float x = (o[i] - mm[i]) * (gg[i] * rsqrtf(vv[i] + EPS_BN)) + ee[i];
        x = x > 0.f ? x : (expf(x) - 1.0f);
        o[i] = x;
    }
    *(float4*)(hout + (size_t)w * HCDIM + col) = make_float4(o[0], o[1], o[2], o[3]);

    union { uint2 u; __nv_bfloat162 p[2]; } ph, pl;
#pragma unroll
    for (int i = 0; i < 2; i++) {
        __nv_bfloat16 h0 = __float2bfloat16(o[2 * i]);
        __nv_bfloat16 h1 = __float2bfloat16(o[2 * i + 1]);
        ph.p[i] = __nv_bfloat162(h0, h1);
        pl.p[i] = __nv_bfloat162(
            __float2bfloat16(o[2 * i] - __bfloat162float(h0)),
            __float2bfloat16(o[2 * i + 1] - __bfloat162float(h1)));
    }
    *(uint2*)(outh + (size_t)w * HCDIM + col) = ph.u;
    *(uint2*)(outl + (size_t)w * HCDIM + col) = pl.u;

    // fused layer-2 projection: partial dot over this lane's 4 channels
    if (doProj) {
        float l0 = 0.f, l1 = 0.f, q0 = 0.f, q1 = 0.f;
#pragma unroll
        for (int i = 0; i < 4; i++) {
            float2 wl = *(const float2*)(Wl2 + (col + i) * 2);
            float2 wr = *(const float2*)(Wr2 + (col + i) * 2);
            l0 += o[i] * wl.x; l1 += o[i] * wl.y;
            q0 += o[i] * wr.x; q1 += o[i] * wr.y;
        }
#pragma unroll
        for (int off = 16; off; off >>= 1) {
            l0 += __shfl_xor_sync(0xFFFFFFFFu, l0, off);
            l1 += __shfl_xor_sync(0xFFFFFFFFu, l1, off);
            q0 += __shfl_xor_sync(0xFFFFFFFFu, q0, off);
            q1 += __shfl_xor_sync(0xFFFFFFFFu, q1, off);
        }
        if (lane == 0) {
            red_add_v2(xl2 + w * 2, l0, l1);
            red_add_v2(xr2 + w * 2, q0, q1);
        }
    }
}

// Fused: scores + softmax-agg + bias + log_softmax. Warp per node, lane/edge.
__global__ void node_gat2_kernel(const int* __restrict__ rowptr,
                                 const int* __restrict__ csr,
                                 const float* __restrict__ xl2,
                                 const float* __restrict__ xr2,
                                 const float* __restrict__ att2,
                                 const float* __restrict__ b2,
                                 float* __restrict__ out) {
    int w = (blockIdx.x * blockDim.x + threadIdx.x) >> 5;
    int lane = threadIdx.x & 31;
    if (w >= NNODES) return;
    int p0 = rowptr[w], p1 = rowptr[w + 1];
    float2 r = *(const float2*)(xr2 + w * 2);
    float a0 = att2[0], a1 = att2[1];
    float s0 = 0.f, s1 = 0.f, ds = 0.f;
    for (int p = p0 + lane; p < p1; p += 32) {
        int src = csr[p];
        float2 l = *(const float2*)(xl2 + src * 2);
        float mx = l.x + r.x, my = l.y + r.y;
        mx = mx > 0.f ? mx : 0.2f * mx;
        my = my > 0.f ? my : 0.2f * my;
        float ex = __expf(mx * a0 + my * a1);
        s0 += ex * l.x; s1 += ex * l.y; ds += ex;
    }
#pragma unroll
    for (int off = 16; off; off >>= 1) {
        s0 += __shfl_xor_sync(0xFFFFFFFFu, s0, off);
        s1 += __shfl_xor_sync(0xFFFFFFFFu, s1, off);
        ds += __shfl_xor_sync(0xFFFFFFFFu, ds, off);
    }
    if (lane == 0) {
        float inv = 1.f / (ds + 1e-16f);
        float o0 = s0 * inv + b2[0];
        float o1 = s1 * inv + b2[1];
        float mx = fmaxf(o0, o1);
        float lse = mx + logf(expf(o0 - mx) + expf(o1 - mx));
        *(float2*)(out + w * 2) = make_float2(o0 - lse, o1 - lse);
    }
}

// ---------------- launch ---------------------------------------------------
extern "C" void kernel_launch(void* const* d_in, const int* in_sizes, int n_in,
                              void* d_out, int out_size) {
    const float* x   = (const float*)d_in[0];
    const int*   ei  = (const int*)d_in[1];
    const float* Wl0 = (const float*)d_in[2];
    const float* Wr0 = (const float*)d_in[3];
    const float* att0= (const float*)d_in[4];
    const float* b0  = (const float*)d_in[5];
    const float* g0  = (const float*)d_in[6];
    const float* be0 = (const float*)d_in[7];
    const float* m0  = (const float*)d_in[8];
    const float* v0  = (const float*)d_in[9];
    const float* Wl1 = (const float*)d_in[10];
    const float* Wr1 = (const float*)d_in[11];
    const float* att1= (const float*)d_in[12];
    const float* b1  = (const float*)d_in[13];
    const float* g1  = (const float*)d_in[14];
    const float* be1 = (const float*)d_in[15];
    const float* m1  = (const float*)d_in[16];
    const float* v1  = (const float*)d_in[17];
    const float* Wl2 = (const float*)d_in[18];
    const float* Wr2 = (const float*)d_in[19];
    const float* att2= (const float*)d_in[20];
    const float* b2  = (const float*)d_in[21];
    float* out = (float*)d_out;

    float *p_xlr, *p_h, *p_xl2, *p_xr2;
    int *p_deg, *p_cursor, *p_rowptr, *p_csr;
    __nv_bfloat16 *p_xhi, *p_xlo, *p_hhi, *p_hlo;
    __nv_bfloat16 *p_w0h, *p_w0l, *p_w1h, *p_w1l;
    cudaGetSymbolAddress((void**)&p_xlr, g_xlr);
    cudaGetSymbolAddress((void**)&p_h, g_h);
    cudaGetSymbolAddress((void**)&p_xl2, g_xl2);
    cudaGetSymbolAddress((void**)&p_xr2, g_xr2);
    cudaGetSymbolAddress((void**)&p_deg, g_deg);
    cudaGetSymbolAddress((void**)&p_cursor, g_cursor);
    cudaGetSymbolAddress((void**)&p_rowptr, g_rowptr);
    cudaGetSymbolAddress((void**)&p_csr, g_csr);
    cudaGetSymbolAddress((void**)&p_xhi, g_xhi);
    cudaGetSymbolAddress((void**)&p_xlo, g_xlo);
    cudaGetSymbolAddress((void**)&p_hhi, g_hhi);
    cudaGetSymbolAddress((void**)&p_hlo, g_hlo);
    cudaGetSymbolAddress((void**)&p_w0h, g_w0h);
    cudaGetSymbolAddress((void**)&p_w0l, g_w0l);
    cudaGetSymbolAddress((void**)&p_w1h, g_w1h);
    cudaGetSymbolAddress((void**)&p_w1l, g_w1l);

    cudaFuncSetAttribute(hmma_dual_gemm,
                         cudaFuncAttributeMaxDynamicSharedMemorySize, GSMEM);
    cudaFuncSetAttribute(scan_kernel,
                         cudaFuncAttributeMaxDynamicSharedMemorySize, SCAN_SMEM);

    int eBlocks = (ETOT + 255) / 256;
    int nodeWarpBlocks = (NNODES * 32 + 255) / 256;
    int node2WarpBlocks = (NNODES * 64 + 255) / 256;
    dim3 gemmGrid(NOUT / 128, (NNODES + 127) / 128);
    dim3 wtB(32, 8);

    // ===== prep: bf16 splits (+zeroing) + merged wtrans + CSR build =====
    xsplit_kernel<<<(NNODES * INDIM + 255) / 256, 256>>>(x, NNODES * INDIM,
                                                         p_xhi, p_xlo, p_deg,
                                                         p_xl2, p_xr2);
    wtrans_all_kernel<<<dim3(INDIM / 32, 8, 4), wtB>>>(Wl0, Wr0, Wl1, Wr1,
                                                       p_w0h, p_w0l, p_w1h, p_w1l);
    deg_kernel<<<eBlocks, 256>>>(ei, p_deg);
    scan_kernel<<<1, 1024, SCAN_SMEM>>>(p_deg, p_rowptr, p_cursor);
    scatter_kernel<<<eBlocks, 256>>>(ei, p_cursor, p_csr);

    // ===== Layer 0 =====
    hmma_dual_gemm<<<gemmGrid, 256, GSMEM>>>(p_xhi, p_xlo, p_w0h, p_w0l,
                                             p_xlr, NNODES, INDIM);
    node_gat_kernel<<<node2WarpBlocks, 256>>>(p_rowptr, p_csr, p_xlr, att0,
                                              b0, g0, be0, m0, v0,
                                              p_h, p_hhi, p_hlo,
                                              nullptr, nullptr, nullptr, nullptr, 0);

    // ===== Layer 1 (+ fused layer-2 projection) =====
    hmma_dual_gemm<<<gemmGrid, 256, GSMEM>>>(p_hhi, p_hlo, p_w1h, p_w1l,
                                             p_xlr, NNODES, HCDIM);
    node_gat_kernel<<<node2WarpBlocks, 256>>>(p_rowptr, p_csr, p_xlr, att1,
                                              b1, g1, be1, m1, v1,
                                              p_h, p_hhi, p_hlo,
                                              Wl2, Wr2, p_xl2, p_xr2, 1);

    // ===== Layer 2 =====
    node_gat2_kernel<<<nodeWarpBlocks, 256>>>(p_rowptr, p_csr, p_xl2, p_xr2,
                                              att2, b2, out);
}